// round 5
// baseline (speedup 1.0000x reference)
#include <cuda_runtime.h>
#include <cuda_bf16.h>
#include <math.h>
#include <stdint.h>

// Problem constants
#define BATCH 2
#define SEQ   2048
#define CDIM  1024
#define NHEAD 16
#define HDIM  64
#define ROWS  (BATCH * SEQ)          // 4096
#define HID   (4 * CDIM)             // 4096

typedef unsigned short u16;
typedef unsigned int   u32;

// ---------------- scratch (static device globals; no allocation) ----------------
__device__ float g_t  [(size_t)ROWS * CDIM];
__device__ float g_x1 [(size_t)ROWS * CDIM];
__device__ u16 g_xh [(size_t)ROWS * CDIM],  g_xl [(size_t)ROWS * CDIM];
__device__ u16 g_qkvh[(size_t)ROWS * 3 * CDIM], g_qkvl[(size_t)ROWS * 3 * CDIM];
__device__ u16 g_yh [(size_t)ROWS * CDIM],  g_yl [(size_t)ROWS * CDIM];
__device__ u16 g_x1h[(size_t)ROWS * CDIM],  g_x1l[(size_t)ROWS * CDIM];
__device__ u16 g_hh [(size_t)ROWS * HID],   g_hl [(size_t)ROWS * HID];
__device__ u16 g_wah[(size_t)3*CDIM*CDIM], g_wal[(size_t)3*CDIM*CDIM];
__device__ u16 g_w1h[(size_t)HID*CDIM],    g_w1l[(size_t)HID*CDIM];
__device__ u16 g_w2h[(size_t)CDIM*HID],    g_w2l[(size_t)CDIM*HID];
__device__ u16 g_w3h[(size_t)HID*CDIM],    g_w3l[(size_t)HID*CDIM];
__device__ u16 g_w4h[(size_t)CDIM*HID],    g_w4l[(size_t)CDIM*HID];

// ---------------- helpers ----------------
__device__ __forceinline__ uint32_t smem_u32(const void* p) {
    uint32_t a;
    asm("{ .reg .u64 t; cvta.to.shared.u64 t, %1; cvt.u32.u64 %0, t; }" : "=r"(a) : "l"(p));
    return a;
}
__device__ __forceinline__ void cp16(uint32_t dst, const void* src) {
    asm volatile("cp.async.cg.shared.global [%0], [%1], 16;" :: "r"(dst), "l"(src) : "memory");
}
#define CP_COMMIT() asm volatile("cp.async.commit_group;" ::: "memory")
#define CP_WAIT(n)  asm volatile("cp.async.wait_group %0;" :: "n"(n) : "memory")

__device__ __forceinline__ void ldsm4(u32* r, u32 addr) {
    asm volatile("ldmatrix.sync.aligned.m8n8.x4.shared.b16 {%0,%1,%2,%3}, [%4];"
        : "=r"(r[0]), "=r"(r[1]), "=r"(r[2]), "=r"(r[3]) : "r"(addr));
}
__device__ __forceinline__ void ldsm4t(u32* r, u32 addr) {
    asm volatile("ldmatrix.sync.aligned.m8n8.x4.trans.shared.b16 {%0,%1,%2,%3}, [%4];"
        : "=r"(r[0]), "=r"(r[1]), "=r"(r[2]), "=r"(r[3]) : "r"(addr));
}
__device__ __forceinline__ void mma_bf16(float* d, const u32* a, const u32* b) {
    asm volatile("mma.sync.aligned.m16n8k16.row.col.f32.bf16.bf16.f32 "
        "{%0,%1,%2,%3}, {%4,%5,%6,%7}, {%8,%9}, {%0,%1,%2,%3};"
        : "+f"(d[0]), "+f"(d[1]), "+f"(d[2]), "+f"(d[3])
        : "r"(a[0]), "r"(a[1]), "r"(a[2]), "r"(a[3]), "r"(b[0]), "r"(b[1]));
}
__device__ __forceinline__ uint32_t swz(uint32_t off) { return off ^ ((off >> 3) & 0x70); }

__device__ __forceinline__ u16 bf_hi(float v) { return __bfloat16_as_ushort(__float2bfloat16(v)); }
__device__ __forceinline__ u16 bf_lo(float v, u16 hb) {
    return __bfloat16_as_ushort(__float2bfloat16(v - __bfloat162float(__ushort_as_bfloat16(hb))));
}

// ---------------- decompose (elementwise) ----------------
__global__ __launch_bounds__(256) void decomp_k(const float* __restrict__ x,
                                                u16* __restrict__ h, u16* __restrict__ l, int n4) {
    int i = blockIdx.x * 256 + threadIdx.x;
    if (i >= n4) return;
    float4 v = ((const float4*)x)[i];
    u16 h0 = bf_hi(v.x), h1 = bf_hi(v.y), h2 = bf_hi(v.z), h3 = bf_hi(v.w);
    u16 l0 = bf_lo(v.x, h0), l1 = bf_lo(v.y, h1), l2 = bf_lo(v.z, h2), l3 = bf_lo(v.w, h3);
    ((uint2*)h)[i] = make_uint2((u32)h0 | ((u32)h1 << 16), (u32)h2 | ((u32)h3 << 16));
    ((uint2*)l)[i] = make_uint2((u32)l0 | ((u32)l1 << 16), (u32)l2 | ((u32)l3 << 16));
}

// ---------------- transpose + decompose weights: W[K][N] fp32 -> T[N][K] bf16 hi/lo ----------------
__global__ __launch_bounds__(256) void tdecomp_k(const float* __restrict__ W,
                                                 u16* __restrict__ Th, u16* __restrict__ Tl,
                                                 int K, int N) {
    __shared__ float t[32][33];
    const int n0 = blockIdx.x * 32, k0 = blockIdx.y * 32;
    const int tx = threadIdx.x, ty = threadIdx.y;  // 32x8
    #pragma unroll
    for (int i = 0; i < 32; i += 8)
        t[ty + i][tx] = W[(size_t)(k0 + ty + i) * N + n0 + tx];
    __syncthreads();
    #pragma unroll
    for (int i = 0; i < 32; i += 8) {
        float v = t[tx][ty + i];
        size_t o = (size_t)(n0 + ty + i) * K + k0 + tx;
        u16 hb = bf_hi(v);
        Th[o] = hb;
        Tl[o] = bf_lo(v, hb);
    }
}

// ---------------- tensor-core GEMM via mma.sync ----------------
// OUT=0: fp32 C. OUT=1: gelu -> bf16 hi/lo. OUT=2: bf16 hi/lo (no gelu).
// 3-stage cp.async ring, single __syncthreads per k-chunk.
#define BK 64
#define STAGE_B 65536
#define MG_SMEM (3 * STAGE_B)    // 192 KB

template<int OUT>
__global__ __launch_bounds__(256, 1) void mma_gemm(
    const u16* __restrict__ Ahi, const u16* __restrict__ Alo,
    const u16* __restrict__ Bhi, const u16* __restrict__ Blo,
    const float* __restrict__ bias,
    float* __restrict__ C, u16* __restrict__ Chi, u16* __restrict__ Clo,
    int N, int K)
{
    extern __shared__ char smem_raw[];
    const uint32_t sbase = smem_u32(smem_raw);

    const int tid = threadIdx.x, lane = tid & 31, wid = tid >> 5;
    const int warp_m = wid & 3, warp_n = wid >> 2;
    const int bm = blockIdx.y * 128, bn = blockIdx.x * 128;

    const u16* aH = Ahi + (size_t)bm * K;
    const u16* aL = Alo + (size_t)bm * K;
    const u16* bH = Bhi + (size_t)bn * K;
    const u16* bL = Blo + (size_t)bn * K;

    const int nk = K / BK;

    auto load_stage = [&](int t) {
        const uint32_t st = sbase + (uint32_t)(t % 3) * STAGE_B;
        const int k0 = t * BK;
        #pragma unroll
        for (int i = 0; i < 4; ++i) {
            const int idx = i * 256 + tid;
            const int row = idx >> 3, seg = idx & 7;
            const uint32_t soff = swz((uint32_t)(row * 128 + seg * 16));
            const size_t goff = (size_t)row * K + k0 + seg * 8;
            cp16(st + soff,         aH + goff);
            cp16(st + 16384 + soff, aL + goff);
            cp16(st + 32768 + soff, bH + goff);
            cp16(st + 49152 + soff, bL + goff);
        }
        CP_COMMIT();
    };

    float acc[2][8][4];
    #pragma unroll
    for (int mi = 0; mi < 2; ++mi)
        #pragma unroll
        for (int ni = 0; ni < 8; ++ni)
            #pragma unroll
            for (int j = 0; j < 4; ++j) acc[mi][ni][j] = 0.f;

    load_stage(0);
    load_stage(1);

    for (int t = 0; t < nk; ++t) {
        if (t == nk - 1) CP_WAIT(0); else CP_WAIT(1);
        __syncthreads();
        if (t + 2 < nk) load_stage(t + 2);

        const uint32_t st = sbase + (uint32_t)(t % 3) * STAGE_B;
        const int lrow = lane & 15;
        const int kblk = lane >> 4;

        #pragma unroll
        for (int s = 0; s < BK / 16; ++s) {
            const int c16 = s * 2 + kblk;
            u32 a_hi[2][4], a_lo[2][4];
            #pragma unroll
            for (int mi = 0; mi < 2; ++mi) {
                const int row = warp_m * 32 + mi * 16 + lrow;
                const uint32_t off = swz((uint32_t)(row * 128 + c16 * 16));
                ldsm4(a_hi[mi], st + off);
                ldsm4(a_lo[mi], st + 16384 + off);
            }
            u32 b_hi[8][2], b_lo[8][2];
            #pragma unroll
            for (int nb = 0; nb < 4; ++nb) {
                const int row = warp_n * 64 + nb * 16 + lrow;
                const uint32_t off = swz((uint32_t)(row * 128 + c16 * 16));
                u32 r[4];
                ldsm4(r, st + 32768 + off);
                b_hi[nb * 2][0] = r[0]; b_hi[nb * 2 + 1][0] = r[1];
                b_hi[nb * 2][1] = r[2]; b_hi[nb * 2 + 1][1] = r[3];
                ldsm4(r, st + 49152 + off);
                b_lo[nb * 2][0] = r[0]; b_lo[nb * 2 + 1][0] = r[1];
                b_lo[nb * 2][1] = r[2]; b_lo[nb * 2 + 1][1] = r[3];
            }
            #pragma unroll
            for (int mi = 0; mi < 2; ++mi)
                #pragma unroll
                for (int ni = 0; ni < 8; ++ni) {
                    mma_bf16(acc[mi][ni], a_hi[mi], b_hi[ni]);
                    mma_bf16(acc[mi][ni], a_hi[mi], b_lo[ni]);
                    mma_bf16(acc[mi][ni], a_lo[mi], b_hi[ni]);
                }
        }
    }

    #pragma unroll
    for (int ni = 0; ni < 8; ++ni) {
        const int col = bn + warp_n * 64 + ni * 8 + (lane & 3) * 2;
        const float b0 = bias[col], b1 = bias[col + 1];
        #pragma unroll
        for (int mi = 0; mi < 2; ++mi) {
            const int r0 = bm + warp_m * 32 + mi * 16 + (lane >> 2);
            #pragma unroll
            for (int half = 0; half < 2; ++half) {
                const int r = r0 + half * 8;
                float v0 = acc[mi][ni][half * 2 + 0] + b0;
                float v1 = acc[mi][ni][half * 2 + 1] + b1;
                if (OUT == 0) {
                    *(float2*)(C + (size_t)r * N + col) = make_float2(v0, v1);
                } else {
                    if (OUT == 1) {
                        v0 *= normcdff(v0);
                        v1 *= normcdff(v1);
                    }
                    u16 h0 = bf_hi(v0), h1 = bf_hi(v1);
                    u16 l0 = bf_lo(v0, h0), l1 = bf_lo(v1, h1);
                    *(u32*)(Chi + (size_t)r * N + col) = (u32)h0 | ((u32)h1 << 16);
                    *(u32*)(Clo + (size_t)r * N + col) = (u32)l0 | ((u32)l1 << 16);
                }
            }
        }
    }
}

// ---------------- tensor-core flash attention (causal), qkv split K|Q|V ----------------
// 128 threads (4 warps), 64 queries; 3-stage K/V ring, single sync per tile.
// smem: Qh(8K) Ql(8K) | 3 stages x { Kh Kl Vh Vl } (8K each)
#define ATT_STAGE 32768
#define ATT_SMEM (16384 + 3 * ATT_STAGE)   // 112 KB

__global__ __launch_bounds__(128) void attn_mma(
    const u16* __restrict__ qkvh, const u16* __restrict__ qkvl,
    u16* __restrict__ yh, u16* __restrict__ yl)
{
    extern __shared__ char smem_raw[];
    const uint32_t sb = smem_u32(smem_raw);
    const int tid = threadIdx.x, lane = tid & 31, wid = tid >> 5;
    const int qt = blockIdx.x, h = blockIdx.y, b = blockIdx.z;
    const int q0 = qt * 64;
    const int gid = lane >> 2, qp = lane & 3;
    const size_t tokbase = (size_t)b * SEQ;
    const int rs = 3 * CDIM;

    // Q hi/lo load (channel CDIM + h*64) — rides in stage-0's commit group
    #pragma unroll
    for (int i = 0; i < 4; ++i) {
        const int idx = i * 128 + tid;
        const int row = idx >> 3, seg = idx & 7;
        const uint32_t off = swz((uint32_t)(row * 128 + seg * 16));
        const size_t g = (tokbase + q0 + row) * rs + CDIM + h * HDIM + seg * 8;
        cp16(sb + off,        qkvh + g);
        cp16(sb + 8192 + off, qkvl + g);
    }

    auto load_stage = [&](int t) {
        const uint32_t st = sb + 16384 + (uint32_t)(t % 3) * ATT_STAGE;
        const int k0 = t * 64;
        #pragma unroll
        for (int i = 0; i < 4; ++i) {
            const int idx = i * 128 + tid;
            const int row = idx >> 3, seg = idx & 7;
            const uint32_t off = swz((uint32_t)(row * 128 + seg * 16));
            const size_t gk = (tokbase + k0 + row) * rs + h * HDIM + seg * 8;  // K at ch 0
            const size_t gv = gk + 2 * CDIM;                                   // V at ch 2C
            cp16(st + off,         qkvh + gk);
            cp16(st + 8192 + off,  qkvl + gk);
            cp16(st + 16384 + off, qkvh + gv);
            cp16(st + 24576 + off, qkvl + gv);
        }
        CP_COMMIT();
    };

    const int ntiles = qt + 1;
    load_stage(0);
    if (ntiles > 1) load_stage(1);

    float m0 = -INFINITY, m1 = -INFINITY, l0 = 0.f, l1 = 0.f;
    float oacc[8][4];
    #pragma unroll
    for (int ni = 0; ni < 8; ++ni)
        #pragma unroll
        for (int j = 0; j < 4; ++j) oacc[ni][j] = 0.f;

    const int lr = lane & 15, ck = lane >> 4;

    for (int t = 0; t < ntiles; ++t) {
        if (t == ntiles - 1) CP_WAIT(0); else CP_WAIT(1);
        __syncthreads();
        if (t + 2 < ntiles) load_stage(t + 2);
        const uint32_t st = sb + 16384 + (uint32_t)(t % 3) * ATT_STAGE;

        // ---- S = Q K^T (bf16x3) ----
        float sacc[8][4];
        #pragma unroll
        for (int ni = 0; ni < 8; ++ni)
            #pragma unroll
            for (int j = 0; j < 4; ++j) sacc[ni][j] = 0.f;

        #pragma unroll
        for (int s = 0; s < 4; ++s) {
            const int c16 = s * 2 + ck;
            u32 aH[4], aL[4];
            {
                const uint32_t off = swz((uint32_t)((wid * 16 + lr) * 128 + c16 * 16));
                ldsm4(aH, sb + off);
                ldsm4(aL, sb + 8192 + off);
            }
            u32 bH[8][2], bL[8][2];
            #pragma unroll
            for (int ng = 0; ng < 4; ++ng) {
                const uint32_t off = swz((uint32_t)((ng * 16 + lr) * 128 + c16 * 16));
                u32 r[4];
                ldsm4(r, st + off);
                bH[2 * ng][0] = r[0]; bH[2 * ng + 1][0] = r[1];
                bH[2 * ng][1] = r[2]; bH[2 * ng + 1][1] = r[3];
                ldsm4(r, st + 8192 + off);
                bL[2 * ng][0] = r[0]; bL[2 * ng + 1][0] = r[1];
                bL[2 * ng][1] = r[2]; bL[2 * ng + 1][1] = r[3];
            }
            #pragma unroll
            for (int ni = 0; ni < 8; ++ni) {
                mma_bf16(sacc[ni], aH, bH[ni]);
                mma_bf16(sacc[ni], aH, bL[ni]);
                mma_bf16(sacc[ni], aL, bH[ni]);
            }
        }
        #pragma unroll
        for (int ni = 0; ni < 8; ++ni)
            #pragma unroll
            for (int j = 0; j < 4; ++j) sacc[ni][j] *= 0.125f;

        // causal mask on the diagonal tile
        if (t == qt) {
            const int qr0 = q0 + wid * 16 + gid;
            #pragma unroll
            for (int ni = 0; ni < 8; ++ni) {
                const int kbase = t * 64 + ni * 8 + qp * 2;
                #pragma unroll
                for (int j = 0; j < 4; ++j) {
                    if (kbase + (j & 1) > qr0 + (j >> 1) * 8) sacc[ni][j] = -INFINITY;
                }
            }
        }

        // ---- online softmax ----
        float mt0 = -INFINITY, mt1 = -INFINITY;
        #pragma unroll
        for (int ni = 0; ni < 8; ++ni) {
            mt0 = fmaxf(mt0, fmaxf(sacc[ni][0], sacc[ni][1]));
            mt1 = fmaxf(mt1, fmaxf(sacc[ni][2], sacc[ni][3]));
        }
        mt0 = fmaxf(mt0, __shfl_xor_sync(0xffffffffu, mt0, 1));
        mt0 = fmaxf(mt0, __shfl_xor_sync(0xffffffffu, mt0, 2));
        mt1 = fmaxf(mt1, __shfl_xor_sync(0xffffffffu, mt1, 1));
        mt1 = fmaxf(mt1, __shfl_xor_sync(0xffffffffu, mt1, 2));
        const float mn0 = fmaxf(m0, mt0), mn1 = fmaxf(m1, mt1);
        const float sc0 = __expf(m0 - mn0), sc1 = __expf(m1 - mn1);
        m0 = mn0; m1 = mn1;
        float ls0 = 0.f, ls1 = 0.f;
        #pragma unroll
        for (int ni = 0; ni < 8; ++ni) {
            sacc[ni][0] = __expf(sacc[ni][0] - mn0);
            sacc[ni][1] = __expf(sacc[ni][1] - mn0);
            sacc[ni][2] = __expf(sacc[ni][2] - mn1);
            sacc[ni][3] = __expf(sacc[ni][3] - mn1);
            ls0 += sacc[ni][0] + sacc[ni][1];
            ls1 += sacc[ni][2] + sacc[ni][3];
        }
        ls0 += __shfl_xor_sync(0xffffffffu, ls0, 1);
        ls0 += __shfl_xor_sync(0xffffffffu, ls0, 2);
        ls1 += __shfl_xor_sync(0xffffffffu, ls1, 1);
        ls1 += __shfl_xor_sync(0xffffffffu, ls1, 2);
        l0 = l0 * sc0 + ls0;
        l1 = l1 * sc1 + ls1;
        #pragma unroll
        for (int ni = 0; ni < 8; ++ni) {
            oacc[ni][0] *= sc0; oacc[ni][1] *= sc0;
            oacc[ni][2] *= sc1; oacc[ni][3] *= sc1;
        }

        // ---- pack P into A-frags (hi/lo) ----
        u32 aPh[4][4], aPl[4][4];
        #pragma unroll
        for (int s = 0; s < 4; ++s) {
            #pragma unroll
            for (int half = 0; half < 2; ++half) {
                const float p0 = sacc[2 * s + half][0], p1 = sacc[2 * s + half][1];
                const float p2 = sacc[2 * s + half][2], p3 = sacc[2 * s + half][3];
                const u16 h0 = bf_hi(p0), h1 = bf_hi(p1), h2 = bf_hi(p2), h3 = bf_hi(p3);
                aPh[s][half * 2 + 0] = (u32)h0 | ((u32)h1 << 16);
                aPh[s][half * 2 + 1] = (u32)h2 | ((u32)h3 << 16);
                const u16 q0b = bf_lo(p0, h0), q1b = bf_lo(p1, h1);
                const u16 q2b = bf_lo(p2, h2), q3b = bf_lo(p3, h3);
                aPl[s][half * 2 + 0] = (u32)q0b | ((u32)q1b << 16);
                aPl[s][half * 2 + 1] = (u32)q2b | ((u32)q3b << 16);
            }
        }

        // ---- O += P V (bf16x3), V via ldmatrix.trans ----
        #pragma unroll
        for (int s = 0; s < 4; ++s) {
            u32 bVh[8][2], bVl[8][2];
            #pragma unroll
            for (int nd = 0; nd < 4; ++nd) {
                const uint32_t off = swz((uint32_t)((s * 16 + lr) * 128 + nd * 32 + ck * 16));
                u32 r[4];
                ldsm4t(r, st + 16384 + off);
                bVh[2 * nd][0] = r[0]; bVh[2 * nd][1] = r[1];
                bVh[2 * nd + 1][0] = r[2]; bVh[2 * nd + 1][1] = r[3];
                ldsm4t(r, st + 24576 + off);
                bVl[2 * nd][0] = r[0]; bVl[2 * nd][1] = r[1];
                bVl[2 * nd + 1][0] = r[2]; bVl[2 * nd + 1][1] = r[3];
            }
            #pragma unroll
            for (int ni = 0; ni < 8; ++ni) {
                mma_bf16(oacc[ni], aPh[s], bVh[ni]);
                mma_bf16(oacc[ni], aPh[s], bVl[ni]);
                mma_bf16(oacc[ni], aPl[s], bVh[ni]);
            }
        }
    }

    // ---- writeout ----
    const float rl0 = 1.f / l0, rl1 = 1.f / l1;
    const int r0 = q0 + wid * 16 + gid, r1 = r0 + 8;
    #pragma unroll
    for (int ni = 0; ni < 8; ++ni) {
        const int col = h * HDIM + ni * 8 + qp * 2;
        {
            const float v0 = oacc[ni][0] * rl0, v1 = oacc[ni][1] * rl0;
            const u16 h0 = bf_hi(v0), h1 = bf_hi(v1);
            const u16 l0b = bf_lo(v0, h0), l1b = bf_lo(v1, h1);
            const size_t o = (tokbase + r0) * CDIM + col;
            *(u32*)(yh + o) = (u32)h0 | ((u32)h1 << 16);
            *(u32*)(yl + o) = (u32)l0b | ((u32)l1b << 16);
        }
        {
            const float v0 = oacc[ni][2] * rl1, v1 = oacc[ni][3] * rl1;
            const u16 h0 = bf_hi(v0), h1 = bf_hi(v1);
            const u16 l0b = bf_lo(v0, h0), l1b = bf_lo(v1, h1);
            const size_t o = (tokbase + r1) * CDIM + col;
            *(u32*)(yh + o) = (u32)h0 | ((u32)h1 << 16);
            *(u32*)(yl + o) = (u32)l0b | ((u32)l1b << 16);
        }
    }
}

// ---------------- residual + LayerNorm ----------------
__device__ __forceinline__ float block_sum256(float v, float* red) {
    const int lane = threadIdx.x & 31;
    const int w = threadIdx.x >> 5;
    #pragma unroll
    for (int off = 16; off; off >>= 1) v += __shfl_xor_sync(0xffffffffu, v, off);
    if (lane == 0) red[w] = v;
    __syncthreads();
    float t = (threadIdx.x < 8) ? red[threadIdx.x] : 0.f;
    if (w == 0) {
        t += __shfl_xor_sync(0xffffffffu, t, 4);
        t += __shfl_xor_sync(0xffffffffu, t, 2);
        t += __shfl_xor_sync(0xffffffffu, t, 1);
        if (lane == 0) red[0] = t;
    }
    __syncthreads();
    const float r = red[0];
    __syncthreads();
    return r;
}

template<bool PAIR>
__global__ __launch_bounds__(256) void add_ln_kernel(
    const float* __restrict__ xres, const float* __restrict__ v,
    const float* __restrict__ g, const float* __restrict__ be,
    float* __restrict__ out, u16* __restrict__ oh, u16* __restrict__ ol)
{
    __shared__ float red[8];
    const size_t row = blockIdx.x;
    const int c0 = threadIdx.x * 4;
    const float* vr = v + row * CDIM;

    float vals[4];
    *(float4*)vals = *(const float4*)(vr + c0);
    float s = vals[0] + vals[1] + vals[2] + vals[3];
    const float mean = block_sum256(s, red) * (1.f / CDIM);

    float d2 = 0.f;
    #pragma unroll
    for (int i = 0; i < 4; ++i) {
        const float d = vals[i] - mean;
        d2 = fmaf(d, d, d2);
    }
    const float var = block_sum256(d2, red) * (1.f / CDIM);
    const float rstd = rsqrtf(var + 1e-5f);

    float4 xr = *(const float4*)(xres + row * CDIM + c0);
    float4 gg = *(const float4*)(g + c0);
    float4 bb = *(const float4*)(be + c0);
    float4 res;
    res.x = xr.x + (vals[0] - mean) * rstd * gg.x + bb.x;
    res.y = xr.y + (vals[1] - mean) * rstd * gg.y + bb.y;
    res.z = xr.z + (vals[2] - mean) * rstd * gg.z + bb.z;
    res.w = xr.w + (vals[3] - mean) * rstd * gg.w + bb.w;
    *(float4*)(out + row * CDIM + c0) = res;
    if (PAIR) {
        u16 h0 = bf_hi(res.x), h1 = bf_hi(res.y), h2 = bf_hi(res.z), h3 = bf_hi(res.w);
        u16 l0 = bf_lo(res.x, h0), l1 = bf_lo(res.y, h1), l2 = bf_lo(res.z, h2), l3 = bf_lo(res.w, h3);
        *(uint2*)(oh + row * CDIM + c0) = make_uint2((u32)h0 | ((u32)h1 << 16), (u32)h2 | ((u32)h3 << 16));
        *(uint2*)(ol + row * CDIM + c0) = make_uint2((u32)l0 | ((u32)l1 << 16), (u32)l2 | ((u32)l3 << 16));
    }
}

// ---------------- launch ----------------
extern "C" void kernel_launch(void* const* d_in, const int* in_sizes, int n_in,
                              void* d_out, int out_size)
{
    const float* x      = (const float*)d_in[0];
    const float* w_attn = (const float*)d_in[1];
    const float* b_attn = (const float*)d_in[2];
    const float* wa1    = (const float*)d_in[3];
    const float* ba1    = (const float*)d_in[4];
    const float* wa2    = (const float*)d_in[5];
    const float* ba2    = (const float*)d_in[6];
    const float* g1     = (const float*)d_in[7];
    const float* be1    = (const float*)d_in[8];
    const float* wf1    = (const float*)d_in[9];
    const float* bf1    = (const float*)d_in[10];
    const float* wf2    = (const float*)d_in[11];
    const float* bf2    = (const float*)d_in[12];
    const float* g2     = (const float*)d_in[13];
    const float* be2    = (const float*)d_in[14];
    float* out = (float*)d_out;

    float *tbuf, *x1;
    u16 *xh, *xl, *qkvh, *qkvl, *yh, *yl, *x1h, *x1l, *hh, *hl;
    u16 *wah, *wal, *w1h, *w1l, *w2h, *w2l, *w3h, *w3l, *w4h, *w4l;
    cudaGetSymbolAddress((void**)&tbuf, g_t);
    cudaGetSymbolAddress((void**)&x1, g_x1);
    cudaGetSymbolAddress((void**)&xh, g_xh);     cudaGetSymbolAddress((void**)&xl, g_xl);
    cudaGetSymbolAddress((void**)&qkvh, g_qkvh); cudaGetSymbolAddress((void**)&qkvl, g_qkvl);
    cudaGetSymbolAddress((void**)&yh, g_yh);     cudaGetSymbolAddress((void**)&yl, g_yl);
    cudaGetSymbolAddress((void**)&x1h, g_x1h);   cudaGetSymbolAddress((void**)&x1l, g_x1l);
    cudaGetSymbolAddress((void**)&hh, g_hh);     cudaGetSymbolAddress((void**)&hl, g_hl);
    cudaGetSymbolAddress((void**)&wah, g_wah);   cudaGetSymbolAddress((void**)&wal, g_wal);
    cudaGetSymbolAddress((void**)&w1h, g_w1h);   cudaGetSymbolAddress((void**)&w1l, g_w1l);
    cudaGetSymbolAddress((void**)&w2h, g_w2h);   cudaGetSymbolAddress((void**)&w2l, g_w2l);
    cudaGetSymbolAddress((void**)&w3h, g_w3h);   cudaGetSymbolAddress((void**)&w3l, g_w3l);
    cudaGetSymbolAddress((void**)&w4h, g_w4h);   cudaGetSymbolAddress((void**)&w4l, g_w4l);

    cudaFuncSetAttribute(mma_gemm<0>, cudaFuncAttributeMaxDynamicSharedMemorySize, MG_SMEM);
    cudaFuncSetAttribute(mma_gemm<1>, cudaFuncAttributeMaxDynamicSharedMemorySize, MG_SMEM);
    cudaFuncSetAttribute(mma_gemm<2>, cudaFuncAttributeMaxDynamicSharedMemorySize, MG_SMEM);
    cudaFuncSetAttribute(attn_mma, cudaFuncAttributeMaxDynamicSharedMemorySize, ATT_SMEM);

    const dim3 tb(32, 8);
    tdecomp_k<<<dim3(3 * CDIM / 32, CDIM / 32), tb>>>(w_attn, wah, wal, CDIM, 3 * CDIM);
    tdecomp_k<<<dim3(HID / 32, CDIM / 32), tb>>>(wa1, w1h, w1l, CDIM, HID);
    tdecomp_k<<<dim3(CDIM / 32, HID / 32), tb>>>(wa2, w2h, w2l, HID, CDIM);
    tdecomp_k<<<dim3(HID / 32, CDIM / 32), tb>>>(wf1, w3h, w3l, CDIM, HID);
    tdecomp_k<<<dim3(CDIM / 32, HID / 32), tb>>>(wf2, w4h, w4l, HID, CDIM);
    decomp_k<<<(ROWS * CDIM / 4 + 255) / 256, 256>>>(x, xh, xl, ROWS * CDIM / 4);

    // 1) qkv = x @ w_attn + b_attn -> bf16 hi/lo directly
    mma_gemm<2><<<dim3(3 * CDIM / 128, ROWS / 128), 256, MG_SMEM>>>(
        xh, xl, wah, wal, b_attn, nullptr, qkvh, qkvl, 3 * CDIM, CDIM);

    // 2) causal MHA (tensor cores) -> y hi/lo
    attn_mma<<<dim3(SEQ / 64, NHEAD, BATCH), 128, ATT_SMEM>>>(qkvh, qkvl, yh, yl);

    // 3) h = gelu(y @ wa1 + ba1) -> bf16 hi/lo
    mma_gemm<1><<<dim3(HID / 128, ROWS / 128), 256, MG_SMEM>>>(
        yh, yl, w1h, w1l, ba1, nullptr, hh, hl, HID, CDIM);

    // 4) t = h @ wa2 + ba2 (fp32)
    mma_gemm<0><<<dim3(CDIM / 128, ROWS / 128), 256, MG_SMEM>>>(
        hh, hl, w2h, w2l, ba2, tbuf, nullptr, nullptr, CDIM, HID);

    // 5) x1 = x + LN(t)
    add_ln_kernel<true><<<ROWS, 256>>>(x, tbuf, g1, be1, x1, x1h, x1l);

    // 6) h = gelu(x1 @ wf1 + bf1) -> bf16 hi/lo
    mma_gemm<1><<<dim3(HID / 128, ROWS / 128), 256, MG_SMEM>>>(
        x1h, x1l, w3h, w3l, bf1, nullptr, hh, hl, HID, CDIM);

    // 7) t = h @ wf2 + bf2 (fp32)
    mma_gemm<0><<<dim3(CDIM / 128, ROWS / 128), 256, MG_SMEM>>>(
        hh, hl, w4h, w4l, bf2, tbuf, nullptr, nullptr, CDIM, HID);

    // 8) out = x1 + LN(t)
    add_ln_kernel<false><<<ROWS, 256>>>(x1, tbuf, g2, be2, out, nullptr, nullptr);
}

// round 6
// speedup vs baseline: 1.0365x; 1.0365x over previous
#include <cuda_runtime.h>
#include <cuda_bf16.h>
#include <math.h>
#include <stdint.h>

// Problem constants
#define BATCH 2
#define SEQ   2048
#define CDIM  1024
#define NHEAD 16
#define HDIM  64
#define ROWS  (BATCH * SEQ)          // 4096
#define HID   (4 * CDIM)             // 4096

typedef unsigned short u16;
typedef unsigned int   u32;

// ---------------- scratch (static device globals; no allocation) ----------------
__device__ float g_t  [(size_t)ROWS * CDIM];
__device__ float g_x1 [(size_t)ROWS * CDIM];
__device__ u16 g_xh [(size_t)ROWS * CDIM],  g_xl [(size_t)ROWS * CDIM];
__device__ u16 g_qkvh[(size_t)ROWS * 3 * CDIM], g_qkvl[(size_t)ROWS * 3 * CDIM];
__device__ u16 g_yh [(size_t)ROWS * CDIM],  g_yl [(size_t)ROWS * CDIM];
__device__ u16 g_x1h[(size_t)ROWS * CDIM],  g_x1l[(size_t)ROWS * CDIM];
__device__ u16 g_hh [(size_t)ROWS * HID],   g_hl [(size_t)ROWS * HID];
__device__ u16 g_wah[(size_t)3*CDIM*CDIM], g_wal[(size_t)3*CDIM*CDIM];
__device__ u16 g_w1h[(size_t)HID*CDIM],    g_w1l[(size_t)HID*CDIM];
__device__ u16 g_w2h[(size_t)CDIM*HID],    g_w2l[(size_t)CDIM*HID];
__device__ u16 g_w3h[(size_t)HID*CDIM],    g_w3l[(size_t)HID*CDIM];
__device__ u16 g_w4h[(size_t)CDIM*HID],    g_w4l[(size_t)CDIM*HID];

// ---------------- helpers ----------------
__device__ __forceinline__ uint32_t smem_u32(const void* p) {
    uint32_t a;
    asm("{ .reg .u64 t; cvta.to.shared.u64 t, %1; cvt.u32.u64 %0, t; }" : "=r"(a) : "l"(p));
    return a;
}
__device__ __forceinline__ void cp16(uint32_t dst, const void* src) {
    asm volatile("cp.async.cg.shared.global [%0], [%1], 16;" :: "r"(dst), "l"(src) : "memory");
}
#define CP_COMMIT() asm volatile("cp.async.commit_group;" ::: "memory")
#define CP_WAIT(n)  asm volatile("cp.async.wait_group %0;" :: "n"(n) : "memory")

__device__ __forceinline__ void ldsm4(u32* r, u32 addr) {
    asm volatile("ldmatrix.sync.aligned.m8n8.x4.shared.b16 {%0,%1,%2,%3}, [%4];"
        : "=r"(r[0]), "=r"(r[1]), "=r"(r[2]), "=r"(r[3]) : "r"(addr));
}
__device__ __forceinline__ void ldsm4t(u32* r, u32 addr) {
    asm volatile("ldmatrix.sync.aligned.m8n8.x4.trans.shared.b16 {%0,%1,%2,%3}, [%4];"
        : "=r"(r[0]), "=r"(r[1]), "=r"(r[2]), "=r"(r[3]) : "r"(addr));
}
__device__ __forceinline__ void mma_bf16(float* d, const u32* a, const u32* b) {
    asm volatile("mma.sync.aligned.m16n8k16.row.col.f32.bf16.bf16.f32 "
        "{%0,%1,%2,%3}, {%4,%5,%6,%7}, {%8,%9}, {%0,%1,%2,%3};"
        : "+f"(d[0]), "+f"(d[1]), "+f"(d[2]), "+f"(d[3])
        : "r"(a[0]), "r"(a[1]), "r"(a[2]), "r"(a[3]), "r"(b[0]), "r"(b[1]));
}
__device__ __forceinline__ uint32_t swz(uint32_t off) { return off ^ ((off >> 3) & 0x70); }

__device__ __forceinline__ u16 bf_hi(float v) { return __bfloat16_as_ushort(__float2bfloat16(v)); }
__device__ __forceinline__ u16 bf_lo(float v, u16 hb) {
    return __bfloat16_as_ushort(__float2bfloat16(v - __bfloat162float(__ushort_as_bfloat16(hb))));
}

// ---------------- decompose (elementwise) ----------------
__global__ __launch_bounds__(256) void decomp_k(const float* __restrict__ x,
                                                u16* __restrict__ h, u16* __restrict__ l, int n4) {
    int i = blockIdx.x * 256 + threadIdx.x;
    if (i >= n4) return;
    float4 v = ((const float4*)x)[i];
    u16 h0 = bf_hi(v.x), h1 = bf_hi(v.y), h2 = bf_hi(v.z), h3 = bf_hi(v.w);
    u16 l0 = bf_lo(v.x, h0), l1 = bf_lo(v.y, h1), l2 = bf_lo(v.z, h2), l3 = bf_lo(v.w, h3);
    ((uint2*)h)[i] = make_uint2((u32)h0 | ((u32)h1 << 16), (u32)h2 | ((u32)h3 << 16));
    ((uint2*)l)[i] = make_uint2((u32)l0 | ((u32)l1 << 16), (u32)l2 | ((u32)l3 << 16));
}

// ---------------- transpose + decompose weights: W[K][N] fp32 -> T[N][K] bf16 hi/lo ----------------
__global__ __launch_bounds__(256) void tdecomp_k(const float* __restrict__ W,
                                                 u16* __restrict__ Th, u16* __restrict__ Tl,
                                                 int K, int N) {
    __shared__ float t[32][33];
    const int n0 = blockIdx.x * 32, k0 = blockIdx.y * 32;
    const int tx = threadIdx.x, ty = threadIdx.y;  // 32x8
    #pragma unroll
    for (int i = 0; i < 32; i += 8)
        t[ty + i][tx] = W[(size_t)(k0 + ty + i) * N + n0 + tx];
    __syncthreads();
    #pragma unroll
    for (int i = 0; i < 32; i += 8) {
        float v = t[tx][ty + i];
        size_t o = (size_t)(n0 + ty + i) * K + k0 + tx;
        u16 hb = bf_hi(v);
        Th[o] = hb;
        Tl[o] = bf_lo(v, hb);
    }
}

// ---------------- tensor-core GEMM via mma.sync ----------------
// OUT=0: fp32 C. OUT=1: gelu -> bf16 hi/lo. OUT=2: bf16 hi/lo (no gelu).
// 2-stage cp.async (proven), fragment double-buffering inside the k-chunk.
#define BK 64
#define STAGE_B 65536
#define MG_SMEM (2 * STAGE_B)    // 128 KB

template<int OUT>
__global__ __launch_bounds__(256, 1) void mma_gemm(
    const u16* __restrict__ Ahi, const u16* __restrict__ Alo,
    const u16* __restrict__ Bhi, const u16* __restrict__ Blo,
    const float* __restrict__ bias,
    float* __restrict__ C, u16* __restrict__ Chi, u16* __restrict__ Clo,
    int N, int K)
{
    extern __shared__ char smem_raw[];
    const uint32_t sbase = smem_u32(smem_raw);

    const int tid = threadIdx.x, lane = tid & 31, wid = tid >> 5;
    const int warp_m = wid & 3, warp_n = wid >> 2;
    const int bm = blockIdx.y * 128, bn = blockIdx.x * 128;

    const u16* aH = Ahi + (size_t)bm * K;
    const u16* aL = Alo + (size_t)bm * K;
    const u16* bH = Bhi + (size_t)bn * K;
    const u16* bL = Blo + (size_t)bn * K;

    const int nk = K / BK;

    auto load_stage = [&](int t) {
        const uint32_t st = sbase + (uint32_t)(t & 1) * STAGE_B;
        const int k0 = t * BK;
        #pragma unroll
        for (int i = 0; i < 4; ++i) {
            const int idx = i * 256 + tid;
            const int row = idx >> 3, seg = idx & 7;
            const uint32_t soff = swz((uint32_t)(row * 128 + seg * 16));
            const size_t goff = (size_t)row * K + k0 + seg * 8;
            cp16(st + soff,         aH + goff);
            cp16(st + 16384 + soff, aL + goff);
            cp16(st + 32768 + soff, bH + goff);
            cp16(st + 49152 + soff, bL + goff);
        }
        CP_COMMIT();
    };

    float acc[2][8][4];
    #pragma unroll
    for (int mi = 0; mi < 2; ++mi)
        #pragma unroll
        for (int ni = 0; ni < 8; ++ni)
            #pragma unroll
            for (int j = 0; j < 4; ++j) acc[mi][ni][j] = 0.f;

    load_stage(0);

    const int lrow = lane & 15;
    const int kblk = lane >> 4;

    // double-buffered fragments
    u32 a_hi[2][2][4], a_lo[2][2][4], b_hi[2][8][2], b_lo[2][8][2];

    for (int t = 0; t < nk; ++t) {
        if (t + 1 < nk) {
            load_stage(t + 1);
            CP_WAIT(1);
        } else {
            CP_WAIT(0);
        }
        __syncthreads();

        const uint32_t st = sbase + (uint32_t)(t & 1) * STAGE_B;

        auto ld_frags = [&](int s, int buf) {
            const int c16 = s * 2 + kblk;
            #pragma unroll
            for (int mi = 0; mi < 2; ++mi) {
                const int row = warp_m * 32 + mi * 16 + lrow;
                const uint32_t off = swz((uint32_t)(row * 128 + c16 * 16));
                ldsm4(a_hi[buf][mi], st + off);
                ldsm4(a_lo[buf][mi], st + 16384 + off);
            }
            #pragma unroll
            for (int nb = 0; nb < 4; ++nb) {
                const int row = warp_n * 64 + nb * 16 + lrow;
                const uint32_t off = swz((uint32_t)(row * 128 + c16 * 16));
                u32 r[4];
                ldsm4(r, st + 32768 + off);
                b_hi[buf][nb * 2][0] = r[0]; b_hi[buf][nb * 2 + 1][0] = r[1];
                b_hi[buf][nb * 2][1] = r[2]; b_hi[buf][nb * 2 + 1][1] = r[3];
                ldsm4(r, st + 49152 + off);
                b_lo[buf][nb * 2][0] = r[0]; b_lo[buf][nb * 2 + 1][0] = r[1];
                b_lo[buf][nb * 2][1] = r[2]; b_lo[buf][nb * 2 + 1][1] = r[3];
            }
        };

        ld_frags(0, 0);
        #pragma unroll
        for (int s = 0; s < BK / 16; ++s) {
            if (s + 1 < BK / 16) ld_frags(s + 1, (s + 1) & 1);
            const int bf = s & 1;
            #pragma unroll
            for (int mi = 0; mi < 2; ++mi)
                #pragma unroll
                for (int ni = 0; ni < 8; ++ni) {
                    mma_bf16(acc[mi][ni], a_hi[bf][mi], b_hi[bf][ni]);
                    mma_bf16(acc[mi][ni], a_hi[bf][mi], b_lo[bf][ni]);
                    mma_bf16(acc[mi][ni], a_lo[bf][mi], b_hi[bf][ni]);
                }
        }
        __syncthreads();
    }

    #pragma unroll
    for (int ni = 0; ni < 8; ++ni) {
        const int col = bn + warp_n * 64 + ni * 8 + (lane & 3) * 2;
        const float b0 = bias[col], b1 = bias[col + 1];
        #pragma unroll
        for (int mi = 0; mi < 2; ++mi) {
            const int r0 = bm + warp_m * 32 + mi * 16 + (lane >> 2);
            #pragma unroll
            for (int half = 0; half < 2; ++half) {
                const int r = r0 + half * 8;
                float v0 = acc[mi][ni][half * 2 + 0] + b0;
                float v1 = acc[mi][ni][half * 2 + 1] + b1;
                if (OUT == 0) {
                    *(float2*)(C + (size_t)r * N + col) = make_float2(v0, v1);
                } else {
                    if (OUT == 1) {
                        v0 *= normcdff(v0);
                        v1 *= normcdff(v1);
                    }
                    u16 h0 = bf_hi(v0), h1 = bf_hi(v1);
                    u16 l0 = bf_lo(v0, h0), l1 = bf_lo(v1, h1);
                    *(u32*)(Chi + (size_t)r * N + col) = (u32)h0 | ((u32)h1 << 16);
                    *(u32*)(Clo + (size_t)r * N + col) = (u32)l0 | ((u32)l1 << 16);
                }
            }
        }
    }
}

// ---------------- tensor-core flash attention (causal), qkv split K|Q|V ----------------
// 256 threads (8 warps), 128 queries per CTA; warp w owns rows w*16..w*16+15.
// 2-stage K/V ring (64 keys/stage). smem: Qh(16K) Ql(16K) | 2 x { Kh Kl Vh Vl } (8K each)
#define ATT_STAGE 32768
#define ATT_SMEM (32768 + 2 * ATT_STAGE)   // 96 KB

__global__ __launch_bounds__(256) void attn_mma(
    const u16* __restrict__ qkvh, const u16* __restrict__ qkvl,
    u16* __restrict__ yh, u16* __restrict__ yl)
{
    extern __shared__ char smem_raw[];
    const uint32_t sb = smem_u32(smem_raw);
    const int tid = threadIdx.x, lane = tid & 31, wid = tid >> 5;
    const int qt = blockIdx.x, h = blockIdx.y, b = blockIdx.z;
    const int q0 = qt * 128;
    const int gid = lane >> 2, qp = lane & 3;
    const size_t tokbase = (size_t)b * SEQ;
    const int rs = 3 * CDIM;

    // Q hi/lo load (128 rows; channel CDIM + h*64) — rides in stage-0 commit group
    #pragma unroll
    for (int i = 0; i < 4; ++i) {
        const int idx = i * 256 + tid;
        const int row = idx >> 3, seg = idx & 7;
        const uint32_t off = swz((uint32_t)(row * 128 + seg * 16));
        const size_t g = (tokbase + q0 + row) * rs + CDIM + h * HDIM + seg * 8;
        cp16(sb + off,         qkvh + g);
        cp16(sb + 16384 + off, qkvl + g);
    }

    auto load_stage = [&](int t) {
        const uint32_t st = sb + 32768 + (uint32_t)(t & 1) * ATT_STAGE;
        const int k0 = t * 64;
        #pragma unroll
        for (int i = 0; i < 2; ++i) {
            const int idx = i * 256 + tid;
            const int row = idx >> 3, seg = idx & 7;
            const uint32_t off = swz((uint32_t)(row * 128 + seg * 16));
            const size_t gk = (tokbase + k0 + row) * rs + h * HDIM + seg * 8;  // K at ch 0
            const size_t gv = gk + 2 * CDIM;                                   // V at ch 2C
            cp16(st + off,         qkvh + gk);
            cp16(st + 8192 + off,  qkvl + gk);
            cp16(st + 16384 + off, qkvh + gv);
            cp16(st + 24576 + off, qkvl + gv);
        }
        CP_COMMIT();
    };

    const int ntiles = 2 * qt + 2;
    load_stage(0);

    float m0 = -INFINITY, m1 = -INFINITY, l0 = 0.f, l1 = 0.f;
    float oacc[8][4];
    #pragma unroll
    for (int ni = 0; ni < 8; ++ni)
        #pragma unroll
        for (int j = 0; j < 4; ++j) oacc[ni][j] = 0.f;

    const int lr = lane & 15, ck = lane >> 4;
    const int wrow0 = q0 + wid * 16;   // warp's first query row

    for (int t = 0; t < ntiles; ++t) {
        if (t + 1 < ntiles) {
            load_stage(t + 1);
            CP_WAIT(1);
        } else {
            CP_WAIT(0);
        }
        __syncthreads();
        const uint32_t st = sb + 32768 + (uint32_t)(t & 1) * ATT_STAGE;
        const int k0 = t * 64;
        const bool active = (k0 <= wrow0 + 15);

        if (active) {
            // ---- S = Q K^T (bf16x3) ----
            float sacc[8][4];
            #pragma unroll
            for (int ni = 0; ni < 8; ++ni)
                #pragma unroll
                for (int j = 0; j < 4; ++j) sacc[ni][j] = 0.f;

            #pragma unroll
            for (int s = 0; s < 4; ++s) {
                const int c16 = s * 2 + ck;
                u32 aH[4], aL[4];
                {
                    const uint32_t off = swz((uint32_t)((wid * 16 + lr) * 128 + c16 * 16));
                    ldsm4(aH, sb + off);
                    ldsm4(aL, sb + 16384 + off);
                }
                u32 bH[8][2], bL[8][2];
                #pragma unroll
                for (int ng = 0; ng < 4; ++ng) {
                    const uint32_t off = swz((uint32_t)((ng * 16 + lr) * 128 + c16 * 16));
                    u32 r[4];
                    ldsm4(r, st + off);
                    bH[2 * ng][0] = r[0]; bH[2 * ng + 1][0] = r[1];
                    bH[2 * ng][1] = r[2]; bH[2 * ng + 1][1] = r[3];
                    ldsm4(r, st + 8192 + off);
                    bL[2 * ng][0] = r[0]; bL[2 * ng + 1][0] = r[1];
                    bL[2 * ng][1] = r[2]; bL[2 * ng + 1][1] = r[3];
                }
                #pragma unroll
                for (int ni = 0; ni < 8; ++ni) {
                    mma_bf16(sacc[ni], aH, bH[ni]);
                    mma_bf16(sacc[ni], aH, bL[ni]);
                    mma_bf16(sacc[ni], aL, bH[ni]);
                }
            }
            #pragma unroll
            for (int ni = 0; ni < 8; ++ni)
                #pragma unroll
                for (int j = 0; j < 4; ++j) sacc[ni][j] *= 0.125f;

            // causal mask (only when this k-tile can cross the diagonal for this warp)
            if (k0 + 63 > wrow0) {
                #pragma unroll
                for (int ni = 0; ni < 8; ++ni) {
                    const int kbase = k0 + ni * 8 + qp * 2;
                    #pragma unroll
                    for (int j = 0; j < 4; ++j) {
                        if (kbase + (j & 1) > wrow0 + gid + (j >> 1) * 8) sacc[ni][j] = -INFINITY;
                    }
                }
            }

            // ---- online softmax ----
            float mt0 = -INFINITY, mt1 = -INFINITY;
            #pragma unroll
            for (int ni = 0; ni < 8; ++ni) {
                mt0 = fmaxf(mt0, fmaxf(sacc[ni][0], sacc[ni][1]));
                mt1 = fmaxf(mt1, fmaxf(sacc[ni][2], sacc[ni][3]));
            }
            mt0 = fmaxf(mt0, __shfl_xor_sync(0xffffffffu, mt0, 1));
            mt0 = fmaxf(mt0, __shfl_xor_sync(0xffffffffu, mt0, 2));
            mt1 = fmaxf(mt1, __shfl_xor_sync(0xffffffffu, mt1, 1));
            mt1 = fmaxf(mt1, __shfl_xor_sync(0xffffffffu, mt1, 2));
            const float mn0 = fmaxf(m0, mt0), mn1 = fmaxf(m1, mt1);
            const float sc0 = __expf(m0 - mn0), sc1 = __expf(m1 - mn1);
            m0 = mn0; m1 = mn1;
            float ls0 = 0.f, ls1 = 0.f;
            #pragma unroll
            for (int ni = 0; ni < 8; ++ni) {
                sacc[ni][0] = __expf(sacc[ni][0] - mn0);
                sacc[ni][1] = __expf(sacc[ni][1] - mn0);
                sacc[ni][2] = __expf(sacc[ni][2] - mn1);
                sacc[ni][3] = __expf(sacc[ni][3] - mn1);
                ls0 += sacc[ni][0] + sacc[ni][1];
                ls1 += sacc[ni][2] + sacc[ni][3];
            }
            ls0 += __shfl_xor_sync(0xffffffffu, ls0, 1);
            ls0 += __shfl_xor_sync(0xffffffffu, ls0, 2);
            ls1 += __shfl_xor_sync(0xffffffffu, ls1, 1);
            ls1 += __shfl_xor_sync(0xffffffffu, ls1, 2);
            l0 = l0 * sc0 + ls0;
            l1 = l1 * sc1 + ls1;
            #pragma unroll
            for (int ni = 0; ni < 8; ++ni) {
                oacc[ni][0] *= sc0; oacc[ni][1] *= sc0;
                oacc[ni][2] *= sc1; oacc[ni][3] *= sc1;
            }

            // ---- pack P into A-frags (hi/lo) ----
            u32 aPh[4][4], aPl[4][4];
            #pragma unroll
            for (int s = 0; s < 4; ++s) {
                #pragma unroll
                for (int half = 0; half < 2; ++half) {
                    const float p0 = sacc[2 * s + half][0], p1 = sacc[2 * s + half][1];
                    const float p2 = sacc[2 * s + half][2], p3 = sacc[2 * s + half][3];
                    const u16 h0 = bf_hi(p0), h1 = bf_hi(p1), h2 = bf_hi(p2), h3 = bf_hi(p3);
                    aPh[s][half * 2 + 0] = (u32)h0 | ((u32)h1 << 16);
                    aPh[s][half * 2 + 1] = (u32)h2 | ((u32)h3 << 16);
                    const u16 q0b = bf_lo(p0, h0), q1b = bf_lo(p1, h1);
                    const u16 q2b = bf_lo(p2, h2), q3b = bf_lo(p3, h3);
                    aPl[s][half * 2 + 0] = (u32)q0b | ((u32)q1b << 16);
                    aPl[s][half * 2 + 1] = (u32)q2b | ((u32)q3b << 16);
                }
            }

            // ---- O += P V (bf16x3), V via ldmatrix.trans ----
            #pragma unroll
            for (int s = 0; s < 4; ++s) {
                u32 bVh[8][2], bVl[8][2];
                #pragma unroll
                for (int nd = 0; nd < 4; ++nd) {
                    const uint32_t off = swz((uint32_t)((s * 16 + lr) * 128 + nd * 32 + ck * 16));
                    u32 r[4];
                    ldsm4t(r, st + 16384 + off);
                    bVh[2 * nd][0] = r[0]; bVh[2 * nd][1] = r[1];
                    bVh[2 * nd + 1][0] = r[2]; bVh[2 * nd + 1][1] = r[3];
                    ldsm4t(r, st + 24576 + off);
                    bVl[2 * nd][0] = r[0]; bVl[2 * nd][1] = r[1];
                    bVl[2 * nd + 1][0] = r[2]; bVl[2 * nd + 1][1] = r[3];
                }
                #pragma unroll
                for (int ni = 0; ni < 8; ++ni) {
                    mma_bf16(oacc[ni], aPh[s], bVh[ni]);
                    mma_bf16(oacc[ni], aPh[s], bVl[ni]);
                    mma_bf16(oacc[ni], aPl[s], bVh[ni]);
                }
            }
        }
        __syncthreads();
    }

    // ---- writeout ----
    const float rl0 = 1.f / l0, rl1 = 1.f / l1;
    const int r0 = wrow0 + gid, r1 = r0 + 8;
    #pragma unroll
    for (int ni = 0; ni < 8; ++ni) {
        const int col = h * HDIM + ni * 8 + qp * 2;
        {
            const float v0 = oacc[ni][0] * rl0, v1 = oacc[ni][1] * rl0;
            const u16 h0 = bf_hi(v0), h1 = bf_hi(v1);
            const u16 l0b = bf_lo(v0, h0), l1b = bf_lo(v1, h1);
            const size_t o = (tokbase + r0) * CDIM + col;
            *(u32*)(yh + o) = (u32)h0 | ((u32)h1 << 16);
            *(u32*)(yl + o) = (u32)l0b | ((u32)l1b << 16);
        }
        {
            const float v0 = oacc[ni][2] * rl1, v1 = oacc[ni][3] * rl1;
            const u16 h0 = bf_hi(v0), h1 = bf_hi(v1);
            const u16 l0b = bf_lo(v0, h0), l1b = bf_lo(v1, h1);
            const size_t o = (tokbase + r1) * CDIM + col;
            *(u32*)(yh + o) = (u32)h0 | ((u32)h1 << 16);
            *(u32*)(yl + o) = (u32)l0b | ((u32)l1b << 16);
        }
    }
}

// ---------------- residual + LayerNorm ----------------
__device__ __forceinline__ float block_sum256(float v, float* red) {
    const int lane = threadIdx.x & 31;
    const int w = threadIdx.x >> 5;
    #pragma unroll
    for (int off = 16; off; off >>= 1) v += __shfl_xor_sync(0xffffffffu, v, off);
    if (lane == 0) red[w] = v;
    __syncthreads();
    float t = (threadIdx.x < 8) ? red[threadIdx.x] : 0.f;
    if (w == 0) {
        t += __shfl_xor_sync(0xffffffffu, t, 4);
        t += __shfl_xor_sync(0xffffffffu, t, 2);
        t += __shfl_xor_sync(0xffffffffu, t, 1);
        if (lane == 0) red[0] = t;
    }
    __syncthreads();
    const float r = red[0];
    __syncthreads();
    return r;
}

template<bool PAIR>
__global__ __launch_bounds__(256) void add_ln_kernel(
    const float* __restrict__ xres, const float* __restrict__ v,
    const float* __restrict__ g, const float* __restrict__ be,
    float* __restrict__ out, u16* __restrict__ oh, u16* __restrict__ ol)
{
    __shared__ float red[8];
    const size_t row = blockIdx.x;
    const int c0 = threadIdx.x * 4;
    const float* vr = v + row * CDIM;

    float vals[4];
    *(float4*)vals = *(const float4*)(vr + c0);
    float s = vals[0] + vals[1] + vals[2] + vals[3];
    const float mean = block_sum256(s, red) * (1.f / CDIM);

    float d2 = 0.f;
    #pragma unroll
    for (int i = 0; i < 4; ++i) {
        const float d = vals[i] - mean;
        d2 = fmaf(d, d, d2);
    }
    const float var = block_sum256(d2, red) * (1.f / CDIM);
    const float rstd = rsqrtf(var + 1e-5f);

    float4 xr = *(const float4*)(xres + row * CDIM + c0);
    float4 gg = *(const float4*)(g + c0);
    float4 bb = *(const float4*)(be + c0);
    float4 res;
    res.x = xr.x + (vals[0] - mean) * rstd * gg.x + bb.x;
    res.y = xr.y + (vals[1] - mean) * rstd * gg.y + bb.y;
    res.z = xr.z + (vals[2] - mean) * rstd * gg.z + bb.z;
    res.w = xr.w + (vals[3] - mean) * rstd * gg.w + bb.w;
    *(float4*)(out + row * CDIM + c0) = res;
    if (PAIR) {
        u16 h0 = bf_hi(res.x), h1 = bf_hi(res.y), h2 = bf_hi(res.z), h3 = bf_hi(res.w);
        u16 l0 = bf_lo(res.x, h0), l1 = bf_lo(res.y, h1), l2 = bf_lo(res.z, h2), l3 = bf_lo(res.w, h3);
        *(uint2*)(oh + row * CDIM + c0) = make_uint2((u32)h0 | ((u32)h1 << 16), (u32)h2 | ((u32)h3 << 16));
        *(uint2*)(ol + row * CDIM + c0) = make_uint2((u32)l0 | ((u32)l1 << 16), (u32)l2 | ((u32)l3 << 16));
    }
}

// ---------------- launch ----------------
extern "C" void kernel_launch(void* const* d_in, const int* in_sizes, int n_in,
                              void* d_out, int out_size)
{
    const float* x      = (const float*)d_in[0];
    const float* w_attn = (const float*)d_in[1];
    const float* b_attn = (const float*)d_in[2];
    const float* wa1    = (const float*)d_in[3];
    const float* ba1    = (const float*)d_in[4];
    const float* wa2    = (const float*)d_in[5];
    const float* ba2    = (const float*)d_in[6];
    const float* g1     = (const float*)d_in[7];
    const float* be1    = (const float*)d_in[8];
    const float* wf1    = (const float*)d_in[9];
    const float* bf1    = (const float*)d_in[10];
    const float* wf2    = (const float*)d_in[11];
    const float* bf2    = (const float*)d_in[12];
    const float* g2     = (const float*)d_in[13];
    const float* be2    = (const float*)d_in[14];
    float* out = (float*)d_out;

    float *tbuf, *x1;
    u16 *xh, *xl, *qkvh, *qkvl, *yh, *yl, *x1h, *x1l, *hh, *hl;
    u16 *wah, *wal, *w1h, *w1l, *w2h, *w2l, *w3h, *w3l, *w4h, *w4l;
    cudaGetSymbolAddress((void**)&tbuf, g_t);
    cudaGetSymbolAddress((void**)&x1, g_x1);
    cudaGetSymbolAddress((void**)&xh, g_xh);     cudaGetSymbolAddress((void**)&xl, g_xl);
    cudaGetSymbolAddress((void**)&qkvh, g_qkvh); cudaGetSymbolAddress((void**)&qkvl, g_qkvl);
    cudaGetSymbolAddress((void**)&yh, g_yh);     cudaGetSymbolAddress((void**)&yl, g_yl);
    cudaGetSymbolAddress((void**)&x1h, g_x1h);   cudaGetSymbolAddress((void**)&x1l, g_x1l);
    cudaGetSymbolAddress((void**)&hh, g_hh);     cudaGetSymbolAddress((void**)&hl, g_hl);
    cudaGetSymbolAddress((void**)&wah, g_wah);   cudaGetSymbolAddress((void**)&wal, g_wal);
    cudaGetSymbolAddress((void**)&w1h, g_w1h);   cudaGetSymbolAddress((void**)&w1l, g_w1l);
    cudaGetSymbolAddress((void**)&w2h, g_w2h);   cudaGetSymbolAddress((void**)&w2l, g_w2l);
    cudaGetSymbolAddress((void**)&w3h, g_w3h);   cudaGetSymbolAddress((void**)&w3l, g_w3l);
    cudaGetSymbolAddress((void**)&w4h, g_w4h);   cudaGetSymbolAddress((void**)&w4l, g_w4l);

    cudaFuncSetAttribute(mma_gemm<0>, cudaFuncAttributeMaxDynamicSharedMemorySize, MG_SMEM);
    cudaFuncSetAttribute(mma_gemm<1>, cudaFuncAttributeMaxDynamicSharedMemorySize, MG_SMEM);
    cudaFuncSetAttribute(mma_gemm<2>, cudaFuncAttributeMaxDynamicSharedMemorySize, MG_SMEM);
    cudaFuncSetAttribute(attn_mma, cudaFuncAttributeMaxDynamicSharedMemorySize, ATT_SMEM);

    const dim3 tb(32, 8);
    tdecomp_k<<<dim3(3 * CDIM / 32, CDIM / 32), tb>>>(w_attn, wah, wal, CDIM, 3 * CDIM);
    tdecomp_k<<<dim3(HID / 32, CDIM / 32), tb>>>(wa1, w1h, w1l, CDIM, HID);
    tdecomp_k<<<dim3(CDIM / 32, HID / 32), tb>>>(wa2, w2h, w2l, HID, CDIM);
    tdecomp_k<<<dim3(HID / 32, CDIM / 32), tb>>>(wf1, w3h, w3l, CDIM, HID);
    tdecomp_k<<<dim3(CDIM / 32, HID / 32), tb>>>(wf2, w4h, w4l, HID, CDIM);
    decomp_k<<<(ROWS * CDIM / 4 + 255) / 256, 256>>>(x, xh, xl, ROWS * CDIM / 4);

    // 1) qkv = x @ w_attn + b_attn -> bf16 hi/lo directly
    mma_gemm<2><<<dim3(3 * CDIM / 128, ROWS / 128), 256, MG_SMEM>>>(
        xh, xl, wah, wal, b_attn, nullptr, qkvh, qkvl, 3 * CDIM, CDIM);

    // 2) causal MHA (tensor cores, 128-row Q tiles) -> y hi/lo
    attn_mma<<<dim3(SEQ / 128, NHEAD, BATCH), 256, ATT_SMEM>>>(qkvh, qkvl, yh, yl);

    // 3) h = gelu(y @ wa1 + ba1) -> bf16 hi/lo
    mma_gemm<1><<<dim3(HID / 128, ROWS / 128), 256, MG_SMEM>>>(
        yh, yl, w1h, w1l, ba1, nullptr, hh, hl, HID, CDIM);

    // 4) t = h @ wa2 + ba2 (fp32)
    mma_gemm<0><<<dim3(CDIM / 128, ROWS / 128), 256, MG_SMEM>>>(
        hh, hl, w2h, w2l, ba2, tbuf, nullptr, nullptr, CDIM, HID);

    // 5) x1 = x + LN(t)
    add_ln_kernel<true><<<ROWS, 256>>>(x, tbuf, g1, be1, x1, x1h, x1l);

    // 6) h = gelu(x1 @ wf1 + bf1) -> bf16 hi/lo
    mma_gemm<1><<<dim3(HID / 128, ROWS / 128), 256, MG_SMEM>>>(
        x1h, x1l, w3h, w3l, bf1, nullptr, hh, hl, HID, CDIM);

    // 7) t = h @ wf2 + bf2 (fp32)
    mma_gemm<0><<<dim3(CDIM / 128, ROWS / 128), 256, MG_SMEM>>>(
        hh, hl, w4h, w4l, bf2, tbuf, nullptr, nullptr, CDIM, HID);

    // 8) out = x1 + LN(t)
    add_ln_kernel<false><<<ROWS, 256>>>(x1, tbuf, g2, be2, out, nullptr, nullptr);
}

// round 7
// speedup vs baseline: 1.0448x; 1.0080x over previous
#include <cuda_runtime.h>
#include <cuda_bf16.h>
#include <math.h>
#include <stdint.h>

// Problem constants
#define BATCH 2
#define SEQ   2048
#define CDIM  1024
#define NHEAD 16
#define HDIM  64
#define ROWS  (BATCH * SEQ)          // 4096
#define HID   (4 * CDIM)             // 4096

typedef unsigned short u16;
typedef unsigned int   u32;

// ---------------- scratch (static device globals; no allocation) ----------------
__device__ float g_t  [(size_t)ROWS * CDIM];
__device__ float g_x1 [(size_t)ROWS * CDIM];
__device__ u16 g_xh [(size_t)ROWS * CDIM],  g_xl [(size_t)ROWS * CDIM];
__device__ u16 g_qkvh[(size_t)ROWS * 3 * CDIM], g_qkvl[(size_t)ROWS * 3 * CDIM];
__device__ u16 g_yh [(size_t)ROWS * CDIM],  g_yl [(size_t)ROWS * CDIM];
__device__ u16 g_x1h[(size_t)ROWS * CDIM],  g_x1l[(size_t)ROWS * CDIM];
__device__ u16 g_hh [(size_t)ROWS * HID],   g_hl [(size_t)ROWS * HID];
__device__ u16 g_wah[(size_t)3*CDIM*CDIM], g_wal[(size_t)3*CDIM*CDIM];
__device__ u16 g_w1h[(size_t)HID*CDIM],    g_w1l[(size_t)HID*CDIM];
__device__ u16 g_w2h[(size_t)CDIM*HID],    g_w2l[(size_t)CDIM*HID];
__device__ u16 g_w3h[(size_t)HID*CDIM],    g_w3l[(size_t)HID*CDIM];
__device__ u16 g_w4h[(size_t)CDIM*HID],    g_w4l[(size_t)CDIM*HID];

// ---------------- helpers ----------------
__device__ __forceinline__ uint32_t smem_u32(const void* p) {
    uint32_t a;
    asm("{ .reg .u64 t; cvta.to.shared.u64 t, %1; cvt.u32.u64 %0, t; }" : "=r"(a) : "l"(p));
    return a;
}
__device__ __forceinline__ void cp16(uint32_t dst, const void* src) {
    asm volatile("cp.async.cg.shared.global [%0], [%1], 16;" :: "r"(dst), "l"(src) : "memory");
}
#define CP_COMMIT() asm volatile("cp.async.commit_group;" ::: "memory")
#define CP_WAIT(n)  asm volatile("cp.async.wait_group %0;" :: "n"(n) : "memory")

__device__ __forceinline__ void ldsm4(u32* r, u32 addr) {
    asm volatile("ldmatrix.sync.aligned.m8n8.x4.shared.b16 {%0,%1,%2,%3}, [%4];"
        : "=r"(r[0]), "=r"(r[1]), "=r"(r[2]), "=r"(r[3]) : "r"(addr));
}
__device__ __forceinline__ void ldsm4t(u32* r, u32 addr) {
    asm volatile("ldmatrix.sync.aligned.m8n8.x4.trans.shared.b16 {%0,%1,%2,%3}, [%4];"
        : "=r"(r[0]), "=r"(r[1]), "=r"(r[2]), "=r"(r[3]) : "r"(addr));
}
__device__ __forceinline__ void mma_bf16(float* d, const u32* a, const u32* b) {
    asm volatile("mma.sync.aligned.m16n8k16.row.col.f32.bf16.bf16.f32 "
        "{%0,%1,%2,%3}, {%4,%5,%6,%7}, {%8,%9}, {%0,%1,%2,%3};"
        : "+f"(d[0]), "+f"(d[1]), "+f"(d[2]), "+f"(d[3])
        : "r"(a[0]), "r"(a[1]), "r"(a[2]), "r"(a[3]), "r"(b[0]), "r"(b[1]));
}
__device__ __forceinline__ uint32_t swz(uint32_t off) { return off ^ ((off >> 3) & 0x70); }

__device__ __forceinline__ u16 bf_hi(float v) { return __bfloat16_as_ushort(__float2bfloat16(v)); }
__device__ __forceinline__ u16 bf_lo(float v, u16 hb) {
    return __bfloat16_as_ushort(__float2bfloat16(v - __bfloat162float(__ushort_as_bfloat16(hb))));
}

// ---------------- decompose (elementwise) ----------------
__global__ __launch_bounds__(256) void decomp_k(const float* __restrict__ x,
                                                u16* __restrict__ h, u16* __restrict__ l, int n4) {
    int i = blockIdx.x * 256 + threadIdx.x;
    if (i >= n4) return;
    float4 v = ((const float4*)x)[i];
    u16 h0 = bf_hi(v.x), h1 = bf_hi(v.y), h2 = bf_hi(v.z), h3 = bf_hi(v.w);
    u16 l0 = bf_lo(v.x, h0), l1 = bf_lo(v.y, h1), l2 = bf_lo(v.z, h2), l3 = bf_lo(v.w, h3);
    ((uint2*)h)[i] = make_uint2((u32)h0 | ((u32)h1 << 16), (u32)h2 | ((u32)h3 << 16));
    ((uint2*)l)[i] = make_uint2((u32)l0 | ((u32)l1 << 16), (u32)l2 | ((u32)l3 << 16));
}

// ---------------- transpose + decompose weights: W[K][N] fp32 -> T[N][K] bf16 hi/lo ----------------
__global__ __launch_bounds__(256) void tdecomp_k(const float* __restrict__ W,
                                                 u16* __restrict__ Th, u16* __restrict__ Tl,
                                                 int K, int N) {
    __shared__ float t[32][33];
    const int n0 = blockIdx.x * 32, k0 = blockIdx.y * 32;
    const int tx = threadIdx.x, ty = threadIdx.y;  // 32x8
    #pragma unroll
    for (int i = 0; i < 32; i += 8)
        t[ty + i][tx] = W[(size_t)(k0 + ty + i) * N + n0 + tx];
    __syncthreads();
    #pragma unroll
    for (int i = 0; i < 32; i += 8) {
        float v = t[tx][ty + i];
        size_t o = (size_t)(n0 + ty + i) * K + k0 + tx;
        u16 hb = bf_hi(v);
        Th[o] = hb;
        Tl[o] = bf_lo(v, hb);
    }
}

// ---------------- tensor-core GEMM via mma.sync ----------------
// OUT=0: fp32 C. OUT=1: gelu -> bf16 hi/lo. OUT=2: bf16 hi/lo (no gelu).
// BK=32, 2-stage cp.async, 64KB smem -> 2 CTAs/SM, reg-capped at 128.
// Tile rows packed 2-per-128B line: off(row, c16) = (row>>1)*128 + (row&1)*64 + c16*16.
#define BK 32
#define STAGE_B 32768
#define MG_SMEM (2 * STAGE_B)    // 64 KB

__device__ __forceinline__ uint32_t tile_off(int row, int c16) {
    return swz((uint32_t)(((row >> 1) * 128) + ((row & 1) * 64) + c16 * 16));
}

template<int OUT>
__global__ __launch_bounds__(256, 2) void mma_gemm(
    const u16* __restrict__ Ahi, const u16* __restrict__ Alo,
    const u16* __restrict__ Bhi, const u16* __restrict__ Blo,
    const float* __restrict__ bias,
    float* __restrict__ C, u16* __restrict__ Chi, u16* __restrict__ Clo,
    int N, int K)
{
    extern __shared__ char smem_raw[];
    const uint32_t sbase = smem_u32(smem_raw);

    const int tid = threadIdx.x, lane = tid & 31, wid = tid >> 5;
    const int warp_m = wid & 3, warp_n = wid >> 2;
    const int bm = blockIdx.y * 128, bn = blockIdx.x * 128;

    const u16* aH = Ahi + (size_t)bm * K;
    const u16* aL = Alo + (size_t)bm * K;
    const u16* bH = Bhi + (size_t)bn * K;
    const u16* bL = Blo + (size_t)bn * K;

    const int nk = K / BK;

    // stage layout: Ahi 0 | Alo 8K | Bhi 16K | Blo 24K (each 128 rows x 64B)
    auto load_stage = [&](int t) {
        const uint32_t st = sbase + (uint32_t)(t & 1) * STAGE_B;
        const int k0 = t * BK;
        #pragma unroll
        for (int i = 0; i < 2; ++i) {
            const int idx = i * 256 + tid;          // 0..511 segs per tile
            const int row = idx >> 2, seg = idx & 3;
            const uint32_t soff = tile_off(row, seg);
            const size_t goff = (size_t)row * K + k0 + seg * 8;
            cp16(st + soff,         aH + goff);
            cp16(st + 8192 + soff,  aL + goff);
            cp16(st + 16384 + soff, bH + goff);
            cp16(st + 24576 + soff, bL + goff);
        }
        CP_COMMIT();
    };

    float acc[2][8][4];
    #pragma unroll
    for (int mi = 0; mi < 2; ++mi)
        #pragma unroll
        for (int ni = 0; ni < 8; ++ni)
            #pragma unroll
            for (int j = 0; j < 4; ++j) acc[mi][ni][j] = 0.f;

    load_stage(0);

    const int lrow = lane & 15;
    const int kblk = lane >> 4;

    for (int t = 0; t < nk; ++t) {
        if (t + 1 < nk) {
            load_stage(t + 1);
            CP_WAIT(1);
        } else {
            CP_WAIT(0);
        }
        __syncthreads();

        const uint32_t st = sbase + (uint32_t)(t & 1) * STAGE_B;

        #pragma unroll
        for (int s = 0; s < BK / 16; ++s) {
            const int c16 = s * 2 + kblk;
            u32 a_hi[2][4], a_lo[2][4];
            #pragma unroll
            for (int mi = 0; mi < 2; ++mi) {
                const uint32_t off = tile_off(warp_m * 32 + mi * 16 + lrow, c16);
                ldsm4(a_hi[mi], st + off);
                ldsm4(a_lo[mi], st + 8192 + off);
            }
            u32 bb[8][2];
            // B hi terms: AhBh + AlBh
            #pragma unroll
            for (int nb = 0; nb < 4; ++nb) {
                const uint32_t off = tile_off(warp_n * 64 + nb * 16 + lrow, c16);
                u32 r[4];
                ldsm4(r, st + 16384 + off);
                bb[nb * 2][0] = r[0]; bb[nb * 2 + 1][0] = r[1];
                bb[nb * 2][1] = r[2]; bb[nb * 2 + 1][1] = r[3];
            }
            #pragma unroll
            for (int mi = 0; mi < 2; ++mi)
                #pragma unroll
                for (int ni = 0; ni < 8; ++ni) {
                    mma_bf16(acc[mi][ni], a_hi[mi], bb[ni]);
                    mma_bf16(acc[mi][ni], a_lo[mi], bb[ni]);
                }
            // B lo term: AhBl (reuse bb registers)
            #pragma unroll
            for (int nb = 0; nb < 4; ++nb) {
                const uint32_t off = tile_off(warp_n * 64 + nb * 16 + lrow, c16);
                u32 r[4];
                ldsm4(r, st + 24576 + off);
                bb[nb * 2][0] = r[0]; bb[nb * 2 + 1][0] = r[1];
                bb[nb * 2][1] = r[2]; bb[nb * 2 + 1][1] = r[3];
            }
            #pragma unroll
            for (int mi = 0; mi < 2; ++mi)
                #pragma unroll
                for (int ni = 0; ni < 8; ++ni)
                    mma_bf16(acc[mi][ni], a_hi[mi], bb[ni]);
        }
        __syncthreads();
    }

    #pragma unroll
    for (int ni = 0; ni < 8; ++ni) {
        const int col = bn + warp_n * 64 + ni * 8 + (lane & 3) * 2;
        const float b0 = bias[col], b1 = bias[col + 1];
        #pragma unroll
        for (int mi = 0; mi < 2; ++mi) {
            const int r0 = bm + warp_m * 32 + mi * 16 + (lane >> 2);
            #pragma unroll
            for (int half = 0; half < 2; ++half) {
                const int r = r0 + half * 8;
                float v0 = acc[mi][ni][half * 2 + 0] + b0;
                float v1 = acc[mi][ni][half * 2 + 1] + b1;
                if (OUT == 0) {
                    *(float2*)(C + (size_t)r * N + col) = make_float2(v0, v1);
                } else {
                    if (OUT == 1) {
                        v0 *= normcdff(v0);
                        v1 *= normcdff(v1);
                    }
                    u16 h0 = bf_hi(v0), h1 = bf_hi(v1);
                    u16 l0 = bf_lo(v0, h0), l1 = bf_lo(v1, h1);
                    *(u32*)(Chi + (size_t)r * N + col) = (u32)h0 | ((u32)h1 << 16);
                    *(u32*)(Clo + (size_t)r * N + col) = (u32)l0 | ((u32)l1 << 16);
                }
            }
        }
    }
}

// ---------------- tensor-core flash attention (causal), qkv split K|Q|V ----------------
// 256 threads (8 warps), 128 queries per CTA; heavy q-tiles scheduled first.
// 2-stage K/V ring (64 keys/stage). smem: Qh(16K) Ql(16K) | 2 x { Kh Kl Vh Vl } (8K each)
#define ATT_STAGE 32768
#define ATT_SMEM (32768 + 2 * ATT_STAGE)   // 96 KB

__global__ __launch_bounds__(256) void attn_mma(
    const u16* __restrict__ qkvh, const u16* __restrict__ qkvl,
    u16* __restrict__ yh, u16* __restrict__ yl)
{
    extern __shared__ char smem_raw[];
    const uint32_t sb = smem_u32(smem_raw);
    const int tid = threadIdx.x, lane = tid & 31, wid = tid >> 5;
    const int qt = gridDim.x - 1 - blockIdx.x;   // heavy tiles first
    const int h = blockIdx.y, b = blockIdx.z;
    const int q0 = qt * 128;
    const int gid = lane >> 2, qp = lane & 3;
    const size_t tokbase = (size_t)b * SEQ;
    const int rs = 3 * CDIM;

    // Q hi/lo load (128 rows; channel CDIM + h*64) — rides in stage-0 commit group
    #pragma unroll
    for (int i = 0; i < 4; ++i) {
        const int idx = i * 256 + tid;
        const int row = idx >> 3, seg = idx & 7;
        const uint32_t off = swz((uint32_t)(row * 128 + seg * 16));
        const size_t g = (tokbase + q0 + row) * rs + CDIM + h * HDIM + seg * 8;
        cp16(sb + off,         qkvh + g);
        cp16(sb + 16384 + off, qkvl + g);
    }

    auto load_stage = [&](int t) {
        const uint32_t st = sb + 32768 + (uint32_t)(t & 1) * ATT_STAGE;
        const int k0 = t * 64;
        #pragma unroll
        for (int i = 0; i < 2; ++i) {
            const int idx = i * 256 + tid;
            const int row = idx >> 3, seg = idx & 7;
            const uint32_t off = swz((uint32_t)(row * 128 + seg * 16));
            const size_t gk = (tokbase + k0 + row) * rs + h * HDIM + seg * 8;  // K at ch 0
            const size_t gv = gk + 2 * CDIM;                                   // V at ch 2C
            cp16(st + off,         qkvh + gk);
            cp16(st + 8192 + off,  qkvl + gk);
            cp16(st + 16384 + off, qkvh + gv);
            cp16(st + 24576 + off, qkvl + gv);
        }
        CP_COMMIT();
    };

    const int ntiles = 2 * qt + 2;
    load_stage(0);

    float m0 = -INFINITY, m1 = -INFINITY, l0 = 0.f, l1 = 0.f;
    float oacc[8][4];
    #pragma unroll
    for (int ni = 0; ni < 8; ++ni)
        #pragma unroll
        for (int j = 0; j < 4; ++j) oacc[ni][j] = 0.f;

    const int lr = lane & 15, ck = lane >> 4;
    const int wrow0 = q0 + wid * 16;   // warp's first query row

    for (int t = 0; t < ntiles; ++t) {
        if (t + 1 < ntiles) {
            load_stage(t + 1);
            CP_WAIT(1);
        } else {
            CP_WAIT(0);
        }
        __syncthreads();
        const uint32_t st = sb + 32768 + (uint32_t)(t & 1) * ATT_STAGE;
        const int k0 = t * 64;
        const bool active = (k0 <= wrow0 + 15);

        if (active) {
            // ---- S = Q K^T (bf16x3) ----
            float sacc[8][4];
            #pragma unroll
            for (int ni = 0; ni < 8; ++ni)
                #pragma unroll
                for (int j = 0; j < 4; ++j) sacc[ni][j] = 0.f;

            #pragma unroll
            for (int s = 0; s < 4; ++s) {
                const int c16 = s * 2 + ck;
                u32 aH[4], aL[4];
                {
                    const uint32_t off = swz((uint32_t)((wid * 16 + lr) * 128 + c16 * 16));
                    ldsm4(aH, sb + off);
                    ldsm4(aL, sb + 16384 + off);
                }
                u32 bH[8][2], bL[8][2];
                #pragma unroll
                for (int ng = 0; ng < 4; ++ng) {
                    const uint32_t off = swz((uint32_t)((ng * 16 + lr) * 128 + c16 * 16));
                    u32 r[4];
                    ldsm4(r, st + off);
                    bH[2 * ng][0] = r[0]; bH[2 * ng + 1][0] = r[1];
                    bH[2 * ng][1] = r[2]; bH[2 * ng + 1][1] = r[3];
                    ldsm4(r, st + 8192 + off);
                    bL[2 * ng][0] = r[0]; bL[2 * ng + 1][0] = r[1];
                    bL[2 * ng][1] = r[2]; bL[2 * ng + 1][1] = r[3];
                }
                #pragma unroll
                for (int ni = 0; ni < 8; ++ni) {
                    mma_bf16(sacc[ni], aH, bH[ni]);
                    mma_bf16(sacc[ni], aH, bL[ni]);
                    mma_bf16(sacc[ni], aL, bH[ni]);
                }
            }
            #pragma unroll
            for (int ni = 0; ni < 8; ++ni)
                #pragma unroll
                for (int j = 0; j < 4; ++j) sacc[ni][j] *= 0.125f;

            // causal mask (only when this k-tile can cross the diagonal for this warp)
            if (k0 + 63 > wrow0) {
                #pragma unroll
                for (int ni = 0; ni < 8; ++ni) {
                    const int kbase = k0 + ni * 8 + qp * 2;
                    #pragma unroll
                    for (int j = 0; j < 4; ++j) {
                        if (kbase + (j & 1) > wrow0 + gid + (j >> 1) * 8) sacc[ni][j] = -INFINITY;
                    }
                }
            }

            // ---- online softmax ----
            float mt0 = -INFINITY, mt1 = -INFINITY;
            #pragma unroll
            for (int ni = 0; ni < 8; ++ni) {
                mt0 = fmaxf(mt0, fmaxf(sacc[ni][0], sacc[ni][1]));
                mt1 = fmaxf(mt1, fmaxf(sacc[ni][2], sacc[ni][3]));
            }
            mt0 = fmaxf(mt0, __shfl_xor_sync(0xffffffffu, mt0, 1));
            mt0 = fmaxf(mt0, __shfl_xor_sync(0xffffffffu, mt0, 2));
            mt1 = fmaxf(mt1, __shfl_xor_sync(0xffffffffu, mt1, 1));
            mt1 = fmaxf(mt1, __shfl_xor_sync(0xffffffffu, mt1, 2));
            const float mn0 = fmaxf(m0, mt0), mn1 = fmaxf(m1, mt1);
            const float sc0 = __expf(m0 - mn0), sc1 = __expf(m1 - mn1);
            m0 = mn0; m1 = mn1;
            float ls0 = 0.f, ls1 = 0.f;
            #pragma unroll
            for (int ni = 0; ni < 8; ++ni) {
                sacc[ni][0] = __expf(sacc[ni][0] - mn0);
                sacc[ni][1] = __expf(sacc[ni][1] - mn0);
                sacc[ni][2] = __expf(sacc[ni][2] - mn1);
                sacc[ni][3] = __expf(sacc[ni][3] - mn1);
                ls0 += sacc[ni][0] + sacc[ni][1];
                ls1 += sacc[ni][2] + sacc[ni][3];
            }
            ls0 += __shfl_xor_sync(0xffffffffu, ls0, 1);
            ls0 += __shfl_xor_sync(0xffffffffu, ls0, 2);
            ls1 += __shfl_xor_sync(0xffffffffu, ls1, 1);
            ls1 += __shfl_xor_sync(0xffffffffu, ls1, 2);
            l0 = l0 * sc0 + ls0;
            l1 = l1 * sc1 + ls1;
            #pragma unroll
            for (int ni = 0; ni < 8; ++ni) {
                oacc[ni][0] *= sc0; oacc[ni][1] *= sc0;
                oacc[ni][2] *= sc1; oacc[ni][3] *= sc1;
            }

            // ---- pack P into A-frags (hi/lo) ----
            u32 aPh[4][4], aPl[4][4];
            #pragma unroll
            for (int s = 0; s < 4; ++s) {
                #pragma unroll
                for (int half = 0; half < 2; ++half) {
                    const float p0 = sacc[2 * s + half][0], p1 = sacc[2 * s + half][1];
                    const float p2 = sacc[2 * s + half][2], p3 = sacc[2 * s + half][3];
                    const u16 h0 = bf_hi(p0), h1 = bf_hi(p1), h2 = bf_hi(p2), h3 = bf_hi(p3);
                    aPh[s][half * 2 + 0] = (u32)h0 | ((u32)h1 << 16);
                    aPh[s][half * 2 + 1] = (u32)h2 | ((u32)h3 << 16);
                    const u16 q0b = bf_lo(p0, h0), q1b = bf_lo(p1, h1);
                    const u16 q2b = bf_lo(p2, h2), q3b = bf_lo(p3, h3);
                    aPl[s][half * 2 + 0] = (u32)q0b | ((u32)q1b << 16);
                    aPl[s][half * 2 + 1] = (u32)q2b | ((u32)q3b << 16);
                }
            }

            // ---- O += P V (bf16x3), V via ldmatrix.trans ----
            #pragma unroll
            for (int s = 0; s < 4; ++s) {
                u32 bVh[8][2], bVl[8][2];
                #pragma unroll
                for (int nd = 0; nd < 4; ++nd) {
                    const uint32_t off = swz((uint32_t)((s * 16 + lr) * 128 + nd * 32 + ck * 16));
                    u32 r[4];
                    ldsm4t(r, st + 16384 + off);
                    bVh[2 * nd][0] = r[0]; bVh[2 * nd][1] = r[1];
                    bVh[2 * nd + 1][0] = r[2]; bVh[2 * nd + 1][1] = r[3];
                    ldsm4t(r, st + 24576 + off);
                    bVl[2 * nd][0] = r[0]; bVl[2 * nd][1] = r[1];
                    bVl[2 * nd + 1][0] = r[2]; bVl[2 * nd + 1][1] = r[3];
                }
                #pragma unroll
                for (int ni = 0; ni < 8; ++ni) {
                    mma_bf16(oacc[ni], aPh[s], bVh[ni]);
                    mma_bf16(oacc[ni], aPh[s], bVl[ni]);
                    mma_bf16(oacc[ni], aPl[s], bVh[ni]);
                }
            }
        }
        __syncthreads();
    }

    // ---- writeout ----
    const float rl0 = 1.f / l0, rl1 = 1.f / l1;
    const int r0 = wrow0 + gid, r1 = r0 + 8;
    #pragma unroll
    for (int ni = 0; ni < 8; ++ni) {
        const int col = h * HDIM + ni * 8 + qp * 2;
        {
            const float v0 = oacc[ni][0] * rl0, v1 = oacc[ni][1] * rl0;
            const u16 h0 = bf_hi(v0), h1 = bf_hi(v1);
            const u16 l0b = bf_lo(v0, h0), l1b = bf_lo(v1, h1);
            const size_t o = (tokbase + r0) * CDIM + col;
            *(u32*)(yh + o) = (u32)h0 | ((u32)h1 << 16);
            *(u32*)(yl + o) = (u32)l0b | ((u32)l1b << 16);
        }
        {
            const float v0 = oacc[ni][2] * rl1, v1 = oacc[ni][3] * rl1;
            const u16 h0 = bf_hi(v0), h1 = bf_hi(v1);
            const u16 l0b = bf_lo(v0, h0), l1b = bf_lo(v1, h1);
            const size_t o = (tokbase + r1) * CDIM + col;
            *(u32*)(yh + o) = (u32)h0 | ((u32)h1 << 16);
            *(u32*)(yl + o) = (u32)l0b | ((u32)l1b << 16);
        }
    }
}

// ---------------- residual + LayerNorm ----------------
__device__ __forceinline__ float block_sum256(float v, float* red) {
    const int lane = threadIdx.x & 31;
    const int w = threadIdx.x >> 5;
    #pragma unroll
    for (int off = 16; off; off >>= 1) v += __shfl_xor_sync(0xffffffffu, v, off);
    if (lane == 0) red[w] = v;
    __syncthreads();
    float t = (threadIdx.x < 8) ? red[threadIdx.x] : 0.f;
    if (w == 0) {
        t += __shfl_xor_sync(0xffffffffu, t, 4);
        t += __shfl_xor_sync(0xffffffffu, t, 2);
        t += __shfl_xor_sync(0xffffffffu, t, 1);
        if (lane == 0) red[0] = t;
    }
    __syncthreads();
    const float r = red[0];
    __syncthreads();
    return r;
}

template<bool PAIR>
__global__ __launch_bounds__(256) void add_ln_kernel(
    const float* __restrict__ xres, const float* __restrict__ v,
    const float* __restrict__ g, const float* __restrict__ be,
    float* __restrict__ out, u16* __restrict__ oh, u16* __restrict__ ol)
{
    __shared__ float red[8];
    const size_t row = blockIdx.x;
    const int c0 = threadIdx.x * 4;
    const float* vr = v + row * CDIM;

    float vals[4];
    *(float4*)vals = *(const float4*)(vr + c0);
    float s = vals[0] + vals[1] + vals[2] + vals[3];
    const float mean = block_sum256(s, red) * (1.f / CDIM);

    float d2 = 0.f;
    #pragma unroll
    for (int i = 0; i < 4; ++i) {
        const float d = vals[i] - mean;
        d2 = fmaf(d, d, d2);
    }
    const float var = block_sum256(d2, red) * (1.f / CDIM);
    const float rstd = rsqrtf(var + 1e-5f);

    float4 xr = *(const float4*)(xres + row * CDIM + c0);
    float4 gg = *(const float4*)(g + c0);
    float4 bb = *(const float4*)(be + c0);
    float4 res;
    res.x = xr.x + (vals[0] - mean) * rstd * gg.x + bb.x;
    res.y = xr.y + (vals[1] - mean) * rstd * gg.y + bb.y;
    res.z = xr.z + (vals[2] - mean) * rstd * gg.z + bb.z;
    res.w = xr.w + (vals[3] - mean) * rstd * gg.w + bb.w;
    *(float4*)(out + row * CDIM + c0) = res;
    if (PAIR) {
        u16 h0 = bf_hi(res.x), h1 = bf_hi(res.y), h2 = bf_hi(res.z), h3 = bf_hi(res.w);
        u16 l0 = bf_lo(res.x, h0), l1 = bf_lo(res.y, h1), l2 = bf_lo(res.z, h2), l3 = bf_lo(res.w, h3);
        *(uint2*)(oh + row * CDIM + c0) = make_uint2((u32)h0 | ((u32)h1 << 16), (u32)h2 | ((u32)h3 << 16));
        *(uint2*)(ol + row * CDIM + c0) = make_uint2((u32)l0 | ((u32)l1 << 16), (u32)l2 | ((u32)l3 << 16));
    }
}

// ---------------- launch ----------------
extern "C" void kernel_launch(void* const* d_in, const int* in_sizes, int n_in,
                              void* d_out, int out_size)
{
    const float* x      = (const float*)d_in[0];
    const float* w_attn = (const float*)d_in[1];
    const float* b_attn = (const float*)d_in[2];
    const float* wa1    = (const float*)d_in[3];
    const float* ba1    = (const float*)d_in[4];
    const float* wa2    = (const float*)d_in[5];
    const float* ba2    = (const float*)d_in[6];
    const float* g1     = (const float*)d_in[7];
    const float* be1    = (const float*)d_in[8];
    const float* wf1    = (const float*)d_in[9];
    const float* bf1    = (const float*)d_in[10];
    const float* wf2    = (const float*)d_in[11];
    const float* bf2    = (const float*)d_in[12];
    const float* g2     = (const float*)d_in[13];
    const float* be2    = (const float*)d_in[14];
    float* out = (float*)d_out;

    float *tbuf, *x1;
    u16 *xh, *xl, *qkvh, *qkvl, *yh, *yl, *x1h, *x1l, *hh, *hl;
    u16 *wah, *wal, *w1h, *w1l, *w2h, *w2l, *w3h, *w3l, *w4h, *w4l;
    cudaGetSymbolAddress((void**)&tbuf, g_t);
    cudaGetSymbolAddress((void**)&x1, g_x1);
    cudaGetSymbolAddress((void**)&xh, g_xh);     cudaGetSymbolAddress((void**)&xl, g_xl);
    cudaGetSymbolAddress((void**)&qkvh, g_qkvh); cudaGetSymbolAddress((void**)&qkvl, g_qkvl);
    cudaGetSymbolAddress((void**)&yh, g_yh);     cudaGetSymbolAddress((void**)&yl, g_yl);
    cudaGetSymbolAddress((void**)&x1h, g_x1h);   cudaGetSymbolAddress((void**)&x1l, g_x1l);
    cudaGetSymbolAddress((void**)&hh, g_hh);     cudaGetSymbolAddress((void**)&hl, g_hl);
    cudaGetSymbolAddress((void**)&wah, g_wah);   cudaGetSymbolAddress((void**)&wal, g_wal);
    cudaGetSymbolAddress((void**)&w1h, g_w1h);   cudaGetSymbolAddress((void**)&w1l, g_w1l);
    cudaGetSymbolAddress((void**)&w2h, g_w2h);   cudaGetSymbolAddress((void**)&w2l, g_w2l);
    cudaGetSymbolAddress((void**)&w3h, g_w3h);   cudaGetSymbolAddress((void**)&w3l, g_w3l);
    cudaGetSymbolAddress((void**)&w4h, g_w4h);   cudaGetSymbolAddress((void**)&w4l, g_w4l);

    cudaFuncSetAttribute(mma_gemm<0>, cudaFuncAttributeMaxDynamicSharedMemorySize, MG_SMEM);
    cudaFuncSetAttribute(mma_gemm<1>, cudaFuncAttributeMaxDynamicSharedMemorySize, MG_SMEM);
    cudaFuncSetAttribute(mma_gemm<2>, cudaFuncAttributeMaxDynamicSharedMemorySize, MG_SMEM);
    cudaFuncSetAttribute(attn_mma, cudaFuncAttributeMaxDynamicSharedMemorySize, ATT_SMEM);

    const dim3 tb(32, 8);
    tdecomp_k<<<dim3(3 * CDIM / 32, CDIM / 32), tb>>>(w_attn, wah, wal, CDIM, 3 * CDIM);
    tdecomp_k<<<dim3(HID / 32, CDIM / 32), tb>>>(wa1, w1h, w1l, CDIM, HID);
    tdecomp_k<<<dim3(CDIM / 32, HID / 32), tb>>>(wa2, w2h, w2l, HID, CDIM);
    tdecomp_k<<<dim3(HID / 32, CDIM / 32), tb>>>(wf1, w3h, w3l, CDIM, HID);
    tdecomp_k<<<dim3(CDIM / 32, HID / 32), tb>>>(wf2, w4h, w4l, HID, CDIM);
    decomp_k<<<(ROWS * CDIM / 4 + 255) / 256, 256>>>(x, xh, xl, ROWS * CDIM / 4);

    // 1) qkv = x @ w_attn + b_attn -> bf16 hi/lo directly
    mma_gemm<2><<<dim3(3 * CDIM / 128, ROWS / 128), 256, MG_SMEM>>>(
        xh, xl, wah, wal, b_attn, nullptr, qkvh, qkvl, 3 * CDIM, CDIM);

    // 2) causal MHA (tensor cores, heavy-first scheduling) -> y hi/lo
    attn_mma<<<dim3(SEQ / 128, NHEAD, BATCH), 256, ATT_SMEM>>>(qkvh, qkvl, yh, yl);

    // 3) h = gelu(y @ wa1 + ba1) -> bf16 hi/lo
    mma_gemm<1><<<dim3(HID / 128, ROWS / 128), 256, MG_SMEM>>>(
        yh, yl, w1h, w1l, ba1, nullptr, hh, hl, HID, CDIM);

    // 4) t = h @ wa2 + ba2 (fp32)
    mma_gemm<0><<<dim3(CDIM / 128, ROWS / 128), 256, MG_SMEM>>>(
        hh, hl, w2h, w2l, ba2, tbuf, nullptr, nullptr, CDIM, HID);

    // 5) x1 = x + LN(t)
    add_ln_kernel<true><<<ROWS, 256>>>(x, tbuf, g1, be1, x1, x1h, x1l);

    // 6) h = gelu(x1 @ wf1 + bf1) -> bf16 hi/lo
    mma_gemm<1><<<dim3(HID / 128, ROWS / 128), 256, MG_SMEM>>>(
        x1h, x1l, w3h, w3l, bf1, nullptr, hh, hl, HID, CDIM);

    // 7) t = h @ wf2 + bf2 (fp32)
    mma_gemm<0><<<dim3(CDIM / 128, ROWS / 128), 256, MG_SMEM>>>(
        hh, hl, w4h, w4l, bf2, tbuf, nullptr, nullptr, CDIM, HID);

    // 8) out = x1 + LN(t)
    add_ln_kernel<false><<<ROWS, 256>>>(x1, tbuf, g2, be2, out, nullptr, nullptr);
}

// round 8
// speedup vs baseline: 1.3865x; 1.3271x over previous
#include <cuda_runtime.h>
#include <cuda_fp16.h>
#include <math.h>
#include <stdint.h>

// Problem constants
#define BATCH 2
#define SEQ   2048
#define CDIM  1024
#define NHEAD 16
#define HDIM  64
#define ROWS  (BATCH * SEQ)          // 4096
#define HID   (4 * CDIM)             // 4096

typedef unsigned short u16;
typedef unsigned int   u32;

// ---------------- scratch (static device globals; no allocation) ----------------
__device__ float g_t  [(size_t)ROWS * CDIM];
__device__ float g_x1 [(size_t)ROWS * CDIM];
__device__ u16 g_xh [(size_t)ROWS * CDIM],  g_xl [(size_t)ROWS * CDIM];
__device__ u16 g_qkvh[(size_t)ROWS * 3 * CDIM], g_qkvl[(size_t)ROWS * 3 * CDIM];
__device__ u16 g_yh [(size_t)ROWS * CDIM],  g_yl [(size_t)ROWS * CDIM];
__device__ u16 g_x1h[(size_t)ROWS * CDIM],  g_x1l[(size_t)ROWS * CDIM];
__device__ u16 g_hh [(size_t)ROWS * HID],   g_hl [(size_t)ROWS * HID];
// transposed fp16 weights (single precision level), layout [N][K]
__device__ u16 g_wa[(size_t)3*CDIM*CDIM];
__device__ u16 g_w1[(size_t)HID*CDIM];
__device__ u16 g_w2[(size_t)CDIM*HID];
__device__ u16 g_w3[(size_t)HID*CDIM];
__device__ u16 g_w4[(size_t)CDIM*HID];

// ---------------- helpers ----------------
__device__ __forceinline__ uint32_t smem_u32(const void* p) {
    uint32_t a;
    asm("{ .reg .u64 t; cvta.to.shared.u64 t, %1; cvt.u32.u64 %0, t; }" : "=r"(a) : "l"(p));
    return a;
}
__device__ __forceinline__ void cp16(uint32_t dst, const void* src) {
    asm volatile("cp.async.cg.shared.global [%0], [%1], 16;" :: "r"(dst), "l"(src) : "memory");
}
#define CP_COMMIT() asm volatile("cp.async.commit_group;" ::: "memory")
#define CP_WAIT(n)  asm volatile("cp.async.wait_group %0;" :: "n"(n) : "memory")

__device__ __forceinline__ void ldsm4(u32* r, u32 addr) {
    asm volatile("ldmatrix.sync.aligned.m8n8.x4.shared.b16 {%0,%1,%2,%3}, [%4];"
        : "=r"(r[0]), "=r"(r[1]), "=r"(r[2]), "=r"(r[3]) : "r"(addr));
}
__device__ __forceinline__ void ldsm4t(u32* r, u32 addr) {
    asm volatile("ldmatrix.sync.aligned.m8n8.x4.trans.shared.b16 {%0,%1,%2,%3}, [%4];"
        : "=r"(r[0]), "=r"(r[1]), "=r"(r[2]), "=r"(r[3]) : "r"(addr));
}
__device__ __forceinline__ void mma_fp16(float* d, const u32* a, const u32* b) {
    asm volatile("mma.sync.aligned.m16n8k16.row.col.f32.f16.f16.f32 "
        "{%0,%1,%2,%3}, {%4,%5,%6,%7}, {%8,%9}, {%0,%1,%2,%3};"
        : "+f"(d[0]), "+f"(d[1]), "+f"(d[2]), "+f"(d[3])
        : "r"(a[0]), "r"(a[1]), "r"(a[2]), "r"(a[3]), "r"(b[0]), "r"(b[1]));
}
__device__ __forceinline__ uint32_t swz(uint32_t off) { return off ^ ((off >> 3) & 0x70); }

__device__ __forceinline__ u16 fp_hi(float v) { return __half_as_ushort(__float2half_rn(v)); }
__device__ __forceinline__ u16 fp_lo(float v, u16 hb) {
    return __half_as_ushort(__float2half_rn(v - __half2float(__ushort_as_half(hb))));
}

// ---------------- decompose activations: fp32 -> fp16 hi/lo ----------------
__global__ __launch_bounds__(256) void decomp_k(const float* __restrict__ x,
                                                u16* __restrict__ h, u16* __restrict__ l, int n4) {
    int i = blockIdx.x * 256 + threadIdx.x;
    if (i >= n4) return;
    float4 v = ((const float4*)x)[i];
    u16 h0 = fp_hi(v.x), h1 = fp_hi(v.y), h2 = fp_hi(v.z), h3 = fp_hi(v.w);
    u16 l0 = fp_lo(v.x, h0), l1 = fp_lo(v.y, h1), l2 = fp_lo(v.z, h2), l3 = fp_lo(v.w, h3);
    ((uint2*)h)[i] = make_uint2((u32)h0 | ((u32)h1 << 16), (u32)h2 | ((u32)h3 << 16));
    ((uint2*)l)[i] = make_uint2((u32)l0 | ((u32)l1 << 16), (u32)l2 | ((u32)l3 << 16));
}

// ---------------- transpose weights: W[K][N] fp32 -> T[N][K] fp16 ----------------
__global__ __launch_bounds__(256) void tdecomp_k(const float* __restrict__ W,
                                                 u16* __restrict__ Th, int K, int N) {
    __shared__ float t[32][33];
    const int n0 = blockIdx.x * 32, k0 = blockIdx.y * 32;
    const int tx = threadIdx.x, ty = threadIdx.y;  // 32x8
    #pragma unroll
    for (int i = 0; i < 32; i += 8)
        t[ty + i][tx] = W[(size_t)(k0 + ty + i) * N + n0 + tx];
    __syncthreads();
    #pragma unroll
    for (int i = 0; i < 32; i += 8) {
        float v = t[tx][ty + i];
        Th[(size_t)(n0 + ty + i) * K + k0 + tx] = fp_hi(v);
    }
}

// ---------------- tensor-core GEMM via mma.sync (fp16, A-split x2) ----------------
// C = act((Ah+Al) @ Bh^T + bias).  A: [M][K] fp16 hi/lo. B: [N][K] fp16.
// OUT=0: fp32 C. OUT=1: gelu -> fp16 hi/lo. OUT=2: fp16 hi/lo (no gelu).
// BK=32, 2-stage cp.async, 48KB smem, reg-capped (256,2).
#define BK 32
#define STAGE_B 24576
#define MG_SMEM (2 * STAGE_B)    // 48 KB

__device__ __forceinline__ uint32_t tile_off(int row, int c16) {
    return swz((uint32_t)(((row >> 1) * 128) + ((row & 1) * 64) + c16 * 16));
}

template<int OUT>
__global__ __launch_bounds__(256, 2) void mma_gemm(
    const u16* __restrict__ Ahi, const u16* __restrict__ Alo,
    const u16* __restrict__ B,
    const float* __restrict__ bias,
    float* __restrict__ C, u16* __restrict__ Chi, u16* __restrict__ Clo,
    int N, int K)
{
    extern __shared__ char smem_raw[];
    const uint32_t sbase = smem_u32(smem_raw);

    const int tid = threadIdx.x, lane = tid & 31, wid = tid >> 5;
    const int warp_m = wid & 3, warp_n = wid >> 2;
    const int bm = blockIdx.y * 128, bn = blockIdx.x * 128;

    const u16* aH = Ahi + (size_t)bm * K;
    const u16* aL = Alo + (size_t)bm * K;
    const u16* bH = B + (size_t)bn * K;

    const int nk = K / BK;

    // stage layout: Ah 0 | Al 8K | Bh 16K  (each 128 rows x 64B)
    auto load_stage = [&](int t) {
        const uint32_t st = sbase + (uint32_t)(t & 1) * STAGE_B;
        const int k0 = t * BK;
        #pragma unroll
        for (int i = 0; i < 2; ++i) {
            const int idx = i * 256 + tid;          // 0..511 segs per tile
            const int row = idx >> 2, seg = idx & 3;
            const uint32_t soff = tile_off(row, seg);
            const size_t goff = (size_t)row * K + k0 + seg * 8;
            cp16(st + soff,         aH + goff);
            cp16(st + 8192 + soff,  aL + goff);
            cp16(st + 16384 + soff, bH + goff);
        }
        CP_COMMIT();
    };

    float acc[2][8][4];
    #pragma unroll
    for (int mi = 0; mi < 2; ++mi)
        #pragma unroll
        for (int ni = 0; ni < 8; ++ni)
            #pragma unroll
            for (int j = 0; j < 4; ++j) acc[mi][ni][j] = 0.f;

    load_stage(0);

    const int lrow = lane & 15;
    const int kblk = lane >> 4;

    for (int t = 0; t < nk; ++t) {
        if (t + 1 < nk) {
            load_stage(t + 1);
            CP_WAIT(1);
        } else {
            CP_WAIT(0);
        }
        __syncthreads();

        const uint32_t st = sbase + (uint32_t)(t & 1) * STAGE_B;

        #pragma unroll
        for (int s = 0; s < BK / 16; ++s) {
            const int c16 = s * 2 + kblk;
            u32 a_hi[2][4], a_lo[2][4];
            #pragma unroll
            for (int mi = 0; mi < 2; ++mi) {
                const uint32_t off = tile_off(warp_m * 32 + mi * 16 + lrow, c16);
                ldsm4(a_hi[mi], st + off);
                ldsm4(a_lo[mi], st + 8192 + off);
            }
            u32 bb[8][2];
            #pragma unroll
            for (int nb = 0; nb < 4; ++nb) {
                const uint32_t off = tile_off(warp_n * 64 + nb * 16 + lrow, c16);
                u32 r[4];
                ldsm4(r, st + 16384 + off);
                bb[nb * 2][0] = r[0]; bb[nb * 2 + 1][0] = r[1];
                bb[nb * 2][1] = r[2]; bb[nb * 2 + 1][1] = r[3];
            }
            #pragma unroll
            for (int mi = 0; mi < 2; ++mi)
                #pragma unroll
                for (int ni = 0; ni < 8; ++ni) {
                    mma_fp16(acc[mi][ni], a_hi[mi], bb[ni]);
                    mma_fp16(acc[mi][ni], a_lo[mi], bb[ni]);
                }
        }
        __syncthreads();
    }

    #pragma unroll
    for (int ni = 0; ni < 8; ++ni) {
        const int col = bn + warp_n * 64 + ni * 8 + (lane & 3) * 2;
        const float b0 = bias[col], b1 = bias[col + 1];
        #pragma unroll
        for (int mi = 0; mi < 2; ++mi) {
            const int r0 = bm + warp_m * 32 + mi * 16 + (lane >> 2);
            #pragma unroll
            for (int half = 0; half < 2; ++half) {
                const int r = r0 + half * 8;
                float v0 = acc[mi][ni][half * 2 + 0] + b0;
                float v1 = acc[mi][ni][half * 2 + 1] + b1;
                if (OUT == 0) {
                    *(float2*)(C + (size_t)r * N + col) = make_float2(v0, v1);
                } else {
                    if (OUT == 1) {
                        v0 *= normcdff(v0);
                        v1 *= normcdff(v1);
                    }
                    u16 h0 = fp_hi(v0), h1 = fp_hi(v1);
                    u16 l0 = fp_lo(v0, h0), l1 = fp_lo(v1, h1);
                    *(u32*)(Chi + (size_t)r * N + col) = (u32)h0 | ((u32)h1 << 16);
                    *(u32*)(Clo + (size_t)r * N + col) = (u32)l0 | ((u32)l1 << 16);
                }
            }
        }
    }
}

// ---------------- tensor-core flash attention (causal, fp16 x3), qkv split K|Q|V ----------------
// 256 threads (8 warps), 128 queries per CTA; heavy q-tiles first.
// 2-stage K/V ring (64 keys/stage). smem: Qh(16K) Ql(16K) | 2 x { Kh Kl Vh Vl } (8K each)
#define ATT_STAGE 32768
#define ATT_SMEM (32768 + 2 * ATT_STAGE)   // 96 KB

__global__ __launch_bounds__(256) void attn_mma(
    const u16* __restrict__ qkvh, const u16* __restrict__ qkvl,
    u16* __restrict__ yh, u16* __restrict__ yl)
{
    extern __shared__ char smem_raw[];
    const uint32_t sb = smem_u32(smem_raw);
    const int tid = threadIdx.x, lane = tid & 31, wid = tid >> 5;
    const int qt = gridDim.x - 1 - blockIdx.x;   // heavy tiles first
    const int h = blockIdx.y, b = blockIdx.z;
    const int q0 = qt * 128;
    const int gid = lane >> 2, qp = lane & 3;
    const size_t tokbase = (size_t)b * SEQ;
    const int rs = 3 * CDIM;

    // Q hi/lo load (128 rows; channel CDIM + h*64) — rides in stage-0 commit group
    #pragma unroll
    for (int i = 0; i < 4; ++i) {
        const int idx = i * 256 + tid;
        const int row = idx >> 3, seg = idx & 7;
        const uint32_t off = swz((uint32_t)(row * 128 + seg * 16));
        const size_t g = (tokbase + q0 + row) * rs + CDIM + h * HDIM + seg * 8;
        cp16(sb + off,         qkvh + g);
        cp16(sb + 16384 + off, qkvl + g);
    }

    auto load_stage = [&](int t) {
        const uint32_t st = sb + 32768 + (uint32_t)(t & 1) * ATT_STAGE;
        const int k0 = t * 64;
        #pragma unroll
        for (int i = 0; i < 2; ++i) {
            const int idx = i * 256 + tid;
            const int row = idx >> 3, seg = idx & 7;
            const uint32_t off = swz((uint32_t)(row * 128 + seg * 16));
            const size_t gk = (tokbase + k0 + row) * rs + h * HDIM + seg * 8;  // K at ch 0
            const size_t gv = gk + 2 * CDIM;                                   // V at ch 2C
            cp16(st + off,         qkvh + gk);
            cp16(st + 8192 + off,  qkvl + gk);
            cp16(st + 16384 + off, qkvh + gv);
            cp16(st + 24576 + off, qkvl + gv);
        }
        CP_COMMIT();
    };

    const int ntiles = 2 * qt + 2;
    load_stage(0);

    float m0 = -INFINITY, m1 = -INFINITY, l0 = 0.f, l1 = 0.f;
    float oacc[8][4];
    #pragma unroll
    for (int ni = 0; ni < 8; ++ni)
        #pragma unroll
        for (int j = 0; j < 4; ++j) oacc[ni][j] = 0.f;

    const int lr = lane & 15, ck = lane >> 4;
    const int wrow0 = q0 + wid * 16;   // warp's first query row

    for (int t = 0; t < ntiles; ++t) {
        if (t + 1 < ntiles) {
            load_stage(t + 1);
            CP_WAIT(1);
        } else {
            CP_WAIT(0);
        }
        __syncthreads();
        const uint32_t st = sb + 32768 + (uint32_t)(t & 1) * ATT_STAGE;
        const int k0 = t * 64;
        const bool active = (k0 <= wrow0 + 15);

        if (active) {
            // ---- S = Q K^T (fp16 x3) ----
            float sacc[8][4];
            #pragma unroll
            for (int ni = 0; ni < 8; ++ni)
                #pragma unroll
                for (int j = 0; j < 4; ++j) sacc[ni][j] = 0.f;

            #pragma unroll
            for (int s = 0; s < 4; ++s) {
                const int c16 = s * 2 + ck;
                u32 aH[4], aL[4];
                {
                    const uint32_t off = swz((uint32_t)((wid * 16 + lr) * 128 + c16 * 16));
                    ldsm4(aH, sb + off);
                    ldsm4(aL, sb + 16384 + off);
                }
                u32 bH[8][2], bL[8][2];
                #pragma unroll
                for (int ng = 0; ng < 4; ++ng) {
                    const uint32_t off = swz((uint32_t)((ng * 16 + lr) * 128 + c16 * 16));
                    u32 r[4];
                    ldsm4(r, st + off);
                    bH[2 * ng][0] = r[0]; bH[2 * ng + 1][0] = r[1];
                    bH[2 * ng][1] = r[2]; bH[2 * ng + 1][1] = r[3];
                    ldsm4(r, st + 8192 + off);
                    bL[2 * ng][0] = r[0]; bL[2 * ng + 1][0] = r[1];
                    bL[2 * ng][1] = r[2]; bL[2 * ng + 1][1] = r[3];
                }
                #pragma unroll
                for (int ni = 0; ni < 8; ++ni) {
                    mma_fp16(sacc[ni], aH, bH[ni]);
                    mma_fp16(sacc[ni], aH, bL[ni]);
                    mma_fp16(sacc[ni], aL, bH[ni]);
                }
            }
            #pragma unroll
            for (int ni = 0; ni < 8; ++ni)
                #pragma unroll
                for (int j = 0; j < 4; ++j) sacc[ni][j] *= 0.125f;

            // causal mask (only when this k-tile can cross the diagonal for this warp)
            if (k0 + 63 > wrow0) {
                #pragma unroll
                for (int ni = 0; ni < 8; ++ni) {
                    const int kbase = k0 + ni * 8 + qp * 2;
                    #pragma unroll
                    for (int j = 0; j < 4; ++j) {
                        if (kbase + (j & 1) > wrow0 + gid + (j >> 1) * 8) sacc[ni][j] = -INFINITY;
                    }
                }
            }

            // ---- online softmax ----
            float mt0 = -INFINITY, mt1 = -INFINITY;
            #pragma unroll
            for (int ni = 0; ni < 8; ++ni) {
                mt0 = fmaxf(mt0, fmaxf(sacc[ni][0], sacc[ni][1]));
                mt1 = fmaxf(mt1, fmaxf(sacc[ni][2], sacc[ni][3]));
            }
            mt0 = fmaxf(mt0, __shfl_xor_sync(0xffffffffu, mt0, 1));
            mt0 = fmaxf(mt0, __shfl_xor_sync(0xffffffffu, mt0, 2));
            mt1 = fmaxf(mt1, __shfl_xor_sync(0xffffffffu, mt1, 1));
            mt1 = fmaxf(mt1, __shfl_xor_sync(0xffffffffu, mt1, 2));
            const float mn0 = fmaxf(m0, mt0), mn1 = fmaxf(m1, mt1);
            const float sc0 = __expf(m0 - mn0), sc1 = __expf(m1 - mn1);
            m0 = mn0; m1 = mn1;
            float ls0 = 0.f, ls1 = 0.f;
            #pragma unroll
            for (int ni = 0; ni < 8; ++ni) {
                sacc[ni][0] = __expf(sacc[ni][0] - mn0);
                sacc[ni][1] = __expf(sacc[ni][1] - mn0);
                sacc[ni][2] = __expf(sacc[ni][2] - mn1);
                sacc[ni][3] = __expf(sacc[ni][3] - mn1);
                ls0 += sacc[ni][0] + sacc[ni][1];
                ls1 += sacc[ni][2] + sacc[ni][3];
            }
            ls0 += __shfl_xor_sync(0xffffffffu, ls0, 1);
            ls0 += __shfl_xor_sync(0xffffffffu, ls0, 2);
            ls1 += __shfl_xor_sync(0xffffffffu, ls1, 1);
            ls1 += __shfl_xor_sync(0xffffffffu, ls1, 2);
            l0 = l0 * sc0 + ls0;
            l1 = l1 * sc1 + ls1;
            #pragma unroll
            for (int ni = 0; ni < 8; ++ni) {
                oacc[ni][0] *= sc0; oacc[ni][1] *= sc0;
                oacc[ni][2] *= sc1; oacc[ni][3] *= sc1;
            }

            // ---- pack P into A-frags (fp16 hi/lo) ----
            u32 aPh[4][4], aPl[4][4];
            #pragma unroll
            for (int s = 0; s < 4; ++s) {
                #pragma unroll
                for (int half = 0; half < 2; ++half) {
                    const float p0 = sacc[2 * s + half][0], p1 = sacc[2 * s + half][1];
                    const float p2 = sacc[2 * s + half][2], p3 = sacc[2 * s + half][3];
                    const u16 h0 = fp_hi(p0), h1 = fp_hi(p1), h2 = fp_hi(p2), h3 = fp_hi(p3);
                    aPh[s][half * 2 + 0] = (u32)h0 | ((u32)h1 << 16);
                    aPh[s][half * 2 + 1] = (u32)h2 | ((u32)h3 << 16);
                    const u16 q0b = fp_lo(p0, h0), q1b = fp_lo(p1, h1);
                    const u16 q2b = fp_lo(p2, h2), q3b = fp_lo(p3, h3);
                    aPl[s][half * 2 + 0] = (u32)q0b | ((u32)q1b << 16);
                    aPl[s][half * 2 + 1] = (u32)q2b | ((u32)q3b << 16);
                }
            }

            // ---- O += P V (fp16 x3), V via ldmatrix.trans ----
            #pragma unroll
            for (int s = 0; s < 4; ++s) {
                u32 bVh[8][2], bVl[8][2];
                #pragma unroll
                for (int nd = 0; nd < 4; ++nd) {
                    const uint32_t off = swz((uint32_t)((s * 16 + lr) * 128 + nd * 32 + ck * 16));
                    u32 r[4];
                    ldsm4t(r, st + 16384 + off);
                    bVh[2 * nd][0] = r[0]; bVh[2 * nd][1] = r[1];
                    bVh[2 * nd + 1][0] = r[2]; bVh[2 * nd + 1][1] = r[3];
                    ldsm4t(r, st + 24576 + off);
                    bVl[2 * nd][0] = r[0]; bVl[2 * nd][1] = r[1];
                    bVl[2 * nd + 1][0] = r[2]; bVl[2 * nd + 1][1] = r[3];
                }
                #pragma unroll
                for (int ni = 0; ni < 8; ++ni) {
                    mma_fp16(oacc[ni], aPh[s], bVh[ni]);
                    mma_fp16(oacc[ni], aPh[s], bVl[ni]);
                    mma_fp16(oacc[ni], aPl[s], bVh[ni]);
                }
            }
        }
        __syncthreads();
    }

    // ---- writeout ----
    const float rl0 = 1.f / l0, rl1 = 1.f / l1;
    const int r0 = wrow0 + gid, r1 = r0 + 8;
    #pragma unroll
    for (int ni = 0; ni < 8; ++ni) {
        const int col = h * HDIM + ni * 8 + qp * 2;
        {
            const float v0 = oacc[ni][0] * rl0, v1 = oacc[ni][1] * rl0;
            const u16 h0 = fp_hi(v0), h1 = fp_hi(v1);
            const u16 l0b = fp_lo(v0, h0), l1b = fp_lo(v1, h1);
            const size_t o = (tokbase + r0) * CDIM + col;
            *(u32*)(yh + o) = (u32)h0 | ((u32)h1 << 16);
            *(u32*)(yl + o) = (u32)l0b | ((u32)l1b << 16);
        }
        {
            const float v0 = oacc[ni][2] * rl1, v1 = oacc[ni][3] * rl1;
            const u16 h0 = fp_hi(v0), h1 = fp_hi(v1);
            const u16 l0b = fp_lo(v0, h0), l1b = fp_lo(v1, h1);
            const size_t o = (tokbase + r1) * CDIM + col;
            *(u32*)(yh + o) = (u32)h0 | ((u32)h1 << 16);
            *(u32*)(yl + o) = (u32)l0b | ((u32)l1b << 16);
        }
    }
}

// ---------------- residual + LayerNorm ----------------
__device__ __forceinline__ float block_sum256(float v, float* red) {
    const int lane = threadIdx.x & 31;
    const int w = threadIdx.x >> 5;
    #pragma unroll
    for (int off = 16; off; off >>= 1) v += __shfl_xor_sync(0xffffffffu, v, off);
    if (lane == 0) red[w] = v;
    __syncthreads();
    float t = (threadIdx.x < 8) ? red[threadIdx.x] : 0.f;
    if (w == 0) {
        t += __shfl_xor_sync(0xffffffffu, t, 4);
        t += __shfl_xor_sync(0xffffffffu, t, 2);
        t += __shfl_xor_sync(0xffffffffu, t, 1);
        if (lane == 0) red[0] = t;
    }
    __syncthreads();
    const float r = red[0];
    __syncthreads();
    return r;
}

template<bool PAIR>
__global__ __launch_bounds__(256) void add_ln_kernel(
    const float* __restrict__ xres, const float* __restrict__ v,
    const float* __restrict__ g, const float* __restrict__ be,
    float* __restrict__ out, u16* __restrict__ oh, u16* __restrict__ ol)
{
    __shared__ float red[8];
    const size_t row = blockIdx.x;
    const int c0 = threadIdx.x * 4;
    const float* vr = v + row * CDIM;

    float vals[4];
    *(float4*)vals = *(const float4*)(vr + c0);
    float s = vals[0] + vals[1] + vals[2] + vals[3];
    const float mean = block_sum256(s, red) * (1.f / CDIM);

    float d2 = 0.f;
    #pragma unroll
    for (int i = 0; i < 4; ++i) {
        const float d = vals[i] - mean;
        d2 = fmaf(d, d, d2);
    }
    const float var = block_sum256(d2, red) * (1.f / CDIM);
    const float rstd = rsqrtf(var + 1e-5f);

    float4 xr = *(const float4*)(xres + row * CDIM + c0);
    float4 gg = *(const float4*)(g + c0);
    float4 bb = *(const float4*)(be + c0);
    float4 res;
    res.x = xr.x + (vals[0] - mean) * rstd * gg.x + bb.x;
    res.y = xr.y + (vals[1] - mean) * rstd * gg.y + bb.y;
    res.z = xr.z + (vals[2] - mean) * rstd * gg.z + bb.z;
    res.w = xr.w + (vals[3] - mean) * rstd * gg.w + bb.w;
    *(float4*)(out + row * CDIM + c0) = res;
    if (PAIR) {
        u16 h0 = fp_hi(res.x), h1 = fp_hi(res.y), h2 = fp_hi(res.z), h3 = fp_hi(res.w);
        u16 l0 = fp_lo(res.x, h0), l1 = fp_lo(res.y, h1), l2 = fp_lo(res.z, h2), l3 = fp_lo(res.w, h3);
        *(uint2*)(oh + row * CDIM + c0) = make_uint2((u32)h0 | ((u32)h1 << 16), (u32)h2 | ((u32)h3 << 16));
        *(uint2*)(ol + row * CDIM + c0) = make_uint2((u32)l0 | ((u32)l1 << 16), (u32)l2 | ((u32)l3 << 16));
    }
}

// ---------------- launch ----------------
extern "C" void kernel_launch(void* const* d_in, const int* in_sizes, int n_in,
                              void* d_out, int out_size)
{
    const float* x      = (const float*)d_in[0];
    const float* w_attn = (const float*)d_in[1];
    const float* b_attn = (const float*)d_in[2];
    const float* wa1    = (const float*)d_in[3];
    const float* ba1    = (const float*)d_in[4];
    const float* wa2    = (const float*)d_in[5];
    const float* ba2    = (const float*)d_in[6];
    const float* g1     = (const float*)d_in[7];
    const float* be1    = (const float*)d_in[8];
    const float* wf1    = (const float*)d_in[9];
    const float* bf1    = (const float*)d_in[10];
    const float* wf2    = (const float*)d_in[11];
    const float* bf2    = (const float*)d_in[12];
    const float* g2     = (const float*)d_in[13];
    const float* be2    = (const float*)d_in[14];
    float* out = (float*)d_out;

    float *tbuf, *x1;
    u16 *xh, *xl, *qkvh, *qkvl, *yh, *yl, *x1h, *x1l, *hh, *hl;
    u16 *wa, *w1, *w2, *w3, *w4;
    cudaGetSymbolAddress((void**)&tbuf, g_t);
    cudaGetSymbolAddress((void**)&x1, g_x1);
    cudaGetSymbolAddress((void**)&xh, g_xh);     cudaGetSymbolAddress((void**)&xl, g_xl);
    cudaGetSymbolAddress((void**)&qkvh, g_qkvh); cudaGetSymbolAddress((void**)&qkvl, g_qkvl);
    cudaGetSymbolAddress((void**)&yh, g_yh);     cudaGetSymbolAddress((void**)&yl, g_yl);
    cudaGetSymbolAddress((void**)&x1h, g_x1h);   cudaGetSymbolAddress((void**)&x1l, g_x1l);
    cudaGetSymbolAddress((void**)&hh, g_hh);     cudaGetSymbolAddress((void**)&hl, g_hl);
    cudaGetSymbolAddress((void**)&wa, g_wa);
    cudaGetSymbolAddress((void**)&w1, g_w1);
    cudaGetSymbolAddress((void**)&w2, g_w2);
    cudaGetSymbolAddress((void**)&w3, g_w3);
    cudaGetSymbolAddress((void**)&w4, g_w4);

    cudaFuncSetAttribute(mma_gemm<0>, cudaFuncAttributeMaxDynamicSharedMemorySize, MG_SMEM);
    cudaFuncSetAttribute(mma_gemm<1>, cudaFuncAttributeMaxDynamicSharedMemorySize, MG_SMEM);
    cudaFuncSetAttribute(mma_gemm<2>, cudaFuncAttributeMaxDynamicSharedMemorySize, MG_SMEM);
    cudaFuncSetAttribute(attn_mma, cudaFuncAttributeMaxDynamicSharedMemorySize, ATT_SMEM);

    const dim3 tb(32, 8);
    // Launch order arranged so launch index 5 (ncu -s 5 -c 1) is the qkv GEMM.
    tdecomp_k<<<dim3(3 * CDIM / 32, CDIM / 32), tb>>>(w_attn, wa, CDIM, 3 * CDIM);  // 0
    tdecomp_k<<<dim3(HID / 32, CDIM / 32), tb>>>(wa1, w1, CDIM, HID);               // 1
    tdecomp_k<<<dim3(CDIM / 32, HID / 32), tb>>>(wa2, w2, HID, CDIM);               // 2
    tdecomp_k<<<dim3(HID / 32, CDIM / 32), tb>>>(wf1, w3, CDIM, HID);               // 3
    decomp_k<<<(ROWS * CDIM / 4 + 255) / 256, 256>>>(x, xh, xl, ROWS * CDIM / 4);   // 4

    // 5) qkv = x @ w_attn + b_attn -> fp16 hi/lo   (ncu-profiled launch)
    mma_gemm<2><<<dim3(3 * CDIM / 128, ROWS / 128), 256, MG_SMEM>>>(
        xh, xl, wa, b_attn, nullptr, qkvh, qkvl, 3 * CDIM, CDIM);

    tdecomp_k<<<dim3(CDIM / 32, HID / 32), tb>>>(wf2, w4, HID, CDIM);               // 6

    // causal MHA (tensor cores) -> y hi/lo
    attn_mma<<<dim3(SEQ / 128, NHEAD, BATCH), 256, ATT_SMEM>>>(qkvh, qkvl, yh, yl);

    // h = gelu(y @ wa1 + ba1) -> fp16 hi/lo
    mma_gemm<1><<<dim3(HID / 128, ROWS / 128), 256, MG_SMEM>>>(
        yh, yl, w1, ba1, nullptr, hh, hl, HID, CDIM);

    // t = h @ wa2 + ba2 (fp32)
    mma_gemm<0><<<dim3(CDIM / 128, ROWS / 128), 256, MG_SMEM>>>(
        hh, hl, w2, ba2, tbuf, nullptr, nullptr, CDIM, HID);

    // x1 = x + LN(t)
    add_ln_kernel<true><<<ROWS, 256>>>(x, tbuf, g1, be1, x1, x1h, x1l);

    // h = gelu(x1 @ wf1 + bf1) -> fp16 hi/lo
    mma_gemm<1><<<dim3(HID / 128, ROWS / 128), 256, MG_SMEM>>>(
        x1h, x1l, w3, bf1, nullptr, hh, hl, HID, CDIM);

    // t = h @ wf2 + bf2 (fp32)
    mma_gemm<0><<<dim3(CDIM / 128, ROWS / 128), 256, MG_SMEM>>>(
        hh, hl, w4, bf2, tbuf, nullptr, nullptr, CDIM, HID);

    // out = x1 + LN(t)
    add_ln_kernel<false><<<ROWS, 256>>>(x1, tbuf, g2, be2, out, nullptr, nullptr);
}

// round 10
// speedup vs baseline: 1.9200x; 1.3847x over previous
#include <cuda_runtime.h>
#include <cuda_fp16.h>
#include <math.h>
#include <stdint.h>

// Problem constants
#define BATCH 2
#define SEQ   2048
#define CDIM  1024
#define NHEAD 16
#define HDIM  64
#define ROWS  (BATCH * SEQ)          // 4096
#define HID   (4 * CDIM)             // 4096

typedef unsigned short u16;
typedef unsigned int   u32;

// ---------------- scratch (static device globals; no allocation) ----------------
__device__ float g_t  [(size_t)ROWS * CDIM];
__device__ float g_x1 [(size_t)ROWS * CDIM];
__device__ u16 g_xh [(size_t)ROWS * CDIM],  g_xl [(size_t)ROWS * CDIM];
__device__ u16 g_qkvh[(size_t)ROWS * 3 * CDIM], g_qkvl[(size_t)ROWS * 3 * CDIM];
__device__ u16 g_yh [(size_t)ROWS * CDIM];
__device__ u16 g_x1h[(size_t)ROWS * CDIM];
__device__ u16 g_hh [(size_t)ROWS * HID];
// transposed fp16 weights, layout [N][K]
__device__ u16 g_wa[(size_t)3*CDIM*CDIM];
__device__ u16 g_w1[(size_t)HID*CDIM];
__device__ u16 g_w2[(size_t)CDIM*HID];
__device__ u16 g_w3[(size_t)HID*CDIM];
__device__ u16 g_w4[(size_t)CDIM*HID];

// ---------------- helpers ----------------
__device__ __forceinline__ uint32_t smem_u32(const void* p) {
    uint32_t a;
    asm("{ .reg .u64 t; cvta.to.shared.u64 t, %1; cvt.u32.u64 %0, t; }" : "=r"(a) : "l"(p));
    return a;
}
__device__ __forceinline__ void cp16(uint32_t dst, const void* src) {
    asm volatile("cp.async.cg.shared.global [%0], [%1], 16;" :: "r"(dst), "l"(src) : "memory");
}
#define CP_COMMIT() asm volatile("cp.async.commit_group;" ::: "memory")
#define CP_WAIT(n)  asm volatile("cp.async.wait_group %0;" :: "n"(n) : "memory")

__device__ __forceinline__ void ldsm4(u32* r, u32 addr) {
    asm volatile("ldmatrix.sync.aligned.m8n8.x4.shared.b16 {%0,%1,%2,%3}, [%4];"
        : "=r"(r[0]), "=r"(r[1]), "=r"(r[2]), "=r"(r[3]) : "r"(addr));
}
__device__ __forceinline__ void ldsm4t(u32* r, u32 addr) {
    asm volatile("ldmatrix.sync.aligned.m8n8.x4.trans.shared.b16 {%0,%1,%2,%3}, [%4];"
        : "=r"(r[0]), "=r"(r[1]), "=r"(r[2]), "=r"(r[3]) : "r"(addr));
}
__device__ __forceinline__ void mma_fp16(float* d, const u32* a, const u32* b) {
    asm volatile("mma.sync.aligned.m16n8k16.row.col.f32.f16.f16.f32 "
        "{%0,%1,%2,%3}, {%4,%5,%6,%7}, {%8,%9}, {%0,%1,%2,%3};"
        : "+f"(d[0]), "+f"(d[1]), "+f"(d[2]), "+f"(d[3])
        : "r"(a[0]), "r"(a[1]), "r"(a[2]), "r"(a[3]), "r"(b[0]), "r"(b[1]));
}
__device__ __forceinline__ uint32_t swz(uint32_t off) { return off ^ ((off >> 3) & 0x70); }

__device__ __forceinline__ u16 fp_hi(float v) { return __half_as_ushort(__float2half_rn(v)); }
__device__ __forceinline__ u16 fp_lo(float v, u16 hb) {
    return __half_as_ushort(__float2half_rn(v - __half2float(__ushort_as_half(hb))));
}

// ---------------- decompose activations: fp32 -> fp16 hi/lo ----------------
__global__ __launch_bounds__(256) void decomp_k(const float* __restrict__ x,
                                                u16* __restrict__ h, u16* __restrict__ l, int n4) {
    int i = blockIdx.x * 256 + threadIdx.x;
    if (i >= n4) return;
    float4 v = ((const float4*)x)[i];
    u16 h0 = fp_hi(v.x), h1 = fp_hi(v.y), h2 = fp_hi(v.z), h3 = fp_hi(v.w);
    u16 l0 = fp_lo(v.x, h0), l1 = fp_lo(v.y, h1), l2 = fp_lo(v.z, h2), l3 = fp_lo(v.w, h3);
    ((uint2*)h)[i] = make_uint2((u32)h0 | ((u32)h1 << 16), (u32)h2 | ((u32)h3 << 16));
    ((uint2*)l)[i] = make_uint2((u32)l0 | ((u32)l1 << 16), (u32)l2 | ((u32)l3 << 16));
}

// ---------------- transpose weights: W[K][N] fp32 -> T[N][K] fp16 ----------------
__global__ __launch_bounds__(256) void tdecomp_k(const float* __restrict__ W,
                                                 u16* __restrict__ Th, int K, int N) {
    __shared__ float t[32][33];
    const int n0 = blockIdx.x * 32, k0 = blockIdx.y * 32;
    const int tx = threadIdx.x, ty = threadIdx.y;  // 32x8
    #pragma unroll
    for (int i = 0; i < 32; i += 8)
        t[ty + i][tx] = W[(size_t)(k0 + ty + i) * N + n0 + tx];
    __syncthreads();
    #pragma unroll
    for (int i = 0; i < 32; i += 8) {
        float v = t[tx][ty + i];
        Th[(size_t)(n0 + ty + i) * K + k0 + tx] = fp_hi(v);
    }
}

// ---------------- tensor-core GEMM via mma.sync (fp16) ----------------
// TERMS=2: C = (Ah+Al) @ B^T.  TERMS=1: C = Ah @ B^T.
// OUT=0: fp32 C + bias. OUT=1: gelu -> fp16 hi only. OUT=2: fp16 hi/lo.
// BK=32, 2-stage cp.async. Stage: A hi [A lo] B, 8KB each.
#define BK 32

__device__ __forceinline__ uint32_t tile_off(int row, int c16) {
    return swz((uint32_t)(((row >> 1) * 128) + ((row & 1) * 64) + c16 * 16));
}

template<int OUT, int TERMS>
__global__ __launch_bounds__(256, 2) void mma_gemm(
    const u16* __restrict__ Ahi, const u16* __restrict__ Alo,
    const u16* __restrict__ B,
    const float* __restrict__ bias,
    float* __restrict__ C, u16* __restrict__ Chi, u16* __restrict__ Clo,
    int N, int K)
{
    extern __shared__ char smem_raw[];
    const uint32_t sbase = smem_u32(smem_raw);
    const uint32_t STAGE = (TERMS + 1) * 8192;
    const uint32_t BOFF  = TERMS * 8192;

    const int tid = threadIdx.x, lane = tid & 31, wid = tid >> 5;
    const int warp_m = wid & 3, warp_n = wid >> 2;
    const int bm = blockIdx.y * 128, bn = blockIdx.x * 128;

    const u16* aH = Ahi + (size_t)bm * K;
    const u16* aL = (TERMS == 2) ? (Alo + (size_t)bm * K) : nullptr;
    const u16* bH = B + (size_t)bn * K;

    const int nk = K / BK;

    auto load_stage = [&](int t) {
        const uint32_t st = sbase + (uint32_t)(t & 1) * STAGE;
        const int k0 = t * BK;
        #pragma unroll
        for (int i = 0; i < 2; ++i) {
            const int idx = i * 256 + tid;          // 512 segs per tile
            const int row = idx >> 2, seg = idx & 3;
            const uint32_t soff = tile_off(row, seg);
            const size_t goff = (size_t)row * K + k0 + seg * 8;
            cp16(st + soff, aH + goff);
            if (TERMS == 2) cp16(st + 8192 + soff, aL + goff);
            cp16(st + BOFF + soff, bH + goff);
        }
        CP_COMMIT();
    };

    float acc[2][8][4];
    #pragma unroll
    for (int mi = 0; mi < 2; ++mi)
        #pragma unroll
        for (int ni = 0; ni < 8; ++ni)
            #pragma unroll
            for (int j = 0; j < 4; ++j) acc[mi][ni][j] = 0.f;

    load_stage(0);

    const int lrow = lane & 15;
    const int kblk = lane >> 4;

    for (int t = 0; t < nk; ++t) {
        if (t + 1 < nk) {
            load_stage(t + 1);
            CP_WAIT(1);
        } else {
            CP_WAIT(0);
        }
        __syncthreads();

        const uint32_t st = sbase + (uint32_t)(t & 1) * STAGE;

        #pragma unroll
        for (int s = 0; s < BK / 16; ++s) {
            const int c16 = s * 2 + kblk;
            u32 a_hi[2][4], a_lo[2][4];
            #pragma unroll
            for (int mi = 0; mi < 2; ++mi) {
                const uint32_t off = tile_off(warp_m * 32 + mi * 16 + lrow, c16);
                ldsm4(a_hi[mi], st + off);
                if (TERMS == 2) ldsm4(a_lo[mi], st + 8192 + off);
            }
            u32 bb[8][2];
            #pragma unroll
            for (int nb = 0; nb < 4; ++nb) {
                const uint32_t off = tile_off(warp_n * 64 + nb * 16 + lrow, c16);
                u32 r[4];
                ldsm4(r, st + BOFF + off);
                bb[nb * 2][0] = r[0]; bb[nb * 2 + 1][0] = r[1];
                bb[nb * 2][1] = r[2]; bb[nb * 2 + 1][1] = r[3];
            }
            #pragma unroll
            for (int mi = 0; mi < 2; ++mi)
                #pragma unroll
                for (int ni = 0; ni < 8; ++ni) {
                    mma_fp16(acc[mi][ni], a_hi[mi], bb[ni]);
                    if (TERMS == 2) mma_fp16(acc[mi][ni], a_lo[mi], bb[ni]);
                }
        }
        __syncthreads();
    }

    #pragma unroll
    for (int ni = 0; ni < 8; ++ni) {
        const int col = bn + warp_n * 64 + ni * 8 + (lane & 3) * 2;
        const float b0 = bias[col], b1 = bias[col + 1];
        #pragma unroll
        for (int mi = 0; mi < 2; ++mi) {
            const int r0 = bm + warp_m * 32 + mi * 16 + (lane >> 2);
            #pragma unroll
            for (int half = 0; half < 2; ++half) {
                const int r = r0 + half * 8;
                float v0 = acc[mi][ni][half * 2 + 0] + b0;
                float v1 = acc[mi][ni][half * 2 + 1] + b1;
                if (OUT == 0) {
                    *(float2*)(C + (size_t)r * N + col) = make_float2(v0, v1);
                } else if (OUT == 1) {
                    v0 *= normcdff(v0);
                    v1 *= normcdff(v1);
                    u16 h0 = fp_hi(v0), h1 = fp_hi(v1);
                    *(u32*)(Chi + (size_t)r * N + col) = (u32)h0 | ((u32)h1 << 16);
                } else {
                    u16 h0 = fp_hi(v0), h1 = fp_hi(v1);
                    u16 l0 = fp_lo(v0, h0), l1 = fp_lo(v1, h1);
                    *(u32*)(Chi + (size_t)r * N + col) = (u32)h0 | ((u32)h1 << 16);
                    *(u32*)(Clo + (size_t)r * N + col) = (u32)l0 | ((u32)l1 << 16);
                }
            }
        }
    }
}

// ---------------- tensor-core flash attention (causal, fp16 x3), qkv split K|Q|V ----------------
// 256 threads (8 warps), 128 queries per CTA; heavy q-tiles first. Writes y hi only.
#define ATT_STAGE 32768
#define ATT_SMEM (32768 + 2 * ATT_STAGE)   // 96 KB

__global__ __launch_bounds__(256) void attn_mma(
    const u16* __restrict__ qkvh, const u16* __restrict__ qkvl,
    u16* __restrict__ yh)
{
    extern __shared__ char smem_raw[];
    const uint32_t sb = smem_u32(smem_raw);
    const int tid = threadIdx.x, lane = tid & 31, wid = tid >> 5;
    const int qt = gridDim.x - 1 - blockIdx.x;   // heavy tiles first
    const int h = blockIdx.y, b = blockIdx.z;
    const int q0 = qt * 128;
    const int gid = lane >> 2, qp = lane & 3;
    const size_t tokbase = (size_t)b * SEQ;
    const int rs = 3 * CDIM;

    #pragma unroll
    for (int i = 0; i < 4; ++i) {
        const int idx = i * 256 + tid;
        const int row = idx >> 3, seg = idx & 7;
        const uint32_t off = swz((uint32_t)(row * 128 + seg * 16));
        const size_t g = (tokbase + q0 + row) * rs + CDIM + h * HDIM + seg * 8;
        cp16(sb + off,         qkvh + g);
        cp16(sb + 16384 + off, qkvl + g);
    }

    auto load_stage = [&](int t) {
        const uint32_t st = sb + 32768 + (uint32_t)(t & 1) * ATT_STAGE;
        const int k0 = t * 64;
        #pragma unroll
        for (int i = 0; i < 2; ++i) {
            const int idx = i * 256 + tid;
            const int row = idx >> 3, seg = idx & 7;
            const uint32_t off = swz((uint32_t)(row * 128 + seg * 16));
            const size_t gk = (tokbase + k0 + row) * rs + h * HDIM + seg * 8;
            const size_t gv = gk + 2 * CDIM;
            cp16(st + off,         qkvh + gk);
            cp16(st + 8192 + off,  qkvl + gk);
            cp16(st + 16384 + off, qkvh + gv);
            cp16(st + 24576 + off, qkvl + gv);
        }
        CP_COMMIT();
    };

    const int ntiles = 2 * qt + 2;
    load_stage(0);

    float m0 = -INFINITY, m1 = -INFINITY, l0 = 0.f, l1 = 0.f;
    float oacc[8][4];
    #pragma unroll
    for (int ni = 0; ni < 8; ++ni)
        #pragma unroll
        for (int j = 0; j < 4; ++j) oacc[ni][j] = 0.f;

    const int lr = lane & 15, ck = lane >> 4;
    const int wrow0 = q0 + wid * 16;

    for (int t = 0; t < ntiles; ++t) {
        if (t + 1 < ntiles) {
            load_stage(t + 1);
            CP_WAIT(1);
        } else {
            CP_WAIT(0);
        }
        __syncthreads();
        const uint32_t st = sb + 32768 + (uint32_t)(t & 1) * ATT_STAGE;
        const int k0 = t * 64;
        const bool active = (k0 <= wrow0 + 15);

        if (active) {
            float sacc[8][4];
            #pragma unroll
            for (int ni = 0; ni < 8; ++ni)
                #pragma unroll
                for (int j = 0; j < 4; ++j) sacc[ni][j] = 0.f;

            #pragma unroll
            for (int s = 0; s < 4; ++s) {
                const int c16 = s * 2 + ck;
                u32 aH[4], aL[4];
                {
                    const uint32_t off = swz((uint32_t)((wid * 16 + lr) * 128 + c16 * 16));
                    ldsm4(aH, sb + off);
                    ldsm4(aL, sb + 16384 + off);
                }
                u32 bH[8][2], bL[8][2];
                #pragma unroll
                for (int ng = 0; ng < 4; ++ng) {
                    const uint32_t off = swz((uint32_t)((ng * 16 + lr) * 128 + c16 * 16));
                    u32 r[4];
                    ldsm4(r, st + off);
                    bH[2 * ng][0] = r[0]; bH[2 * ng + 1][0] = r[1];
                    bH[2 * ng][1] = r[2]; bH[2 * ng + 1][1] = r[3];
                    ldsm4(r, st + 8192 + off);
                    bL[2 * ng][0] = r[0]; bL[2 * ng + 1][0] = r[1];
                    bL[2 * ng][1] = r[2]; bL[2 * ng + 1][1] = r[3];
                }
                #pragma unroll
                for (int ni = 0; ni < 8; ++ni) {
                    mma_fp16(sacc[ni], aH, bH[ni]);
                    mma_fp16(sacc[ni], aH, bL[ni]);
                    mma_fp16(sacc[ni], aL, bH[ni]);
                }
            }
            #pragma unroll
            for (int ni = 0; ni < 8; ++ni)
                #pragma unroll
                for (int j = 0; j < 4; ++j) sacc[ni][j] *= 0.125f;

            if (k0 + 63 > wrow0) {
                #pragma unroll
                for (int ni = 0; ni < 8; ++ni) {
                    const int kbase = k0 + ni * 8 + qp * 2;
                    #pragma unroll
                    for (int j = 0; j < 4; ++j) {
                        if (kbase + (j & 1) > wrow0 + gid + (j >> 1) * 8) sacc[ni][j] = -INFINITY;
                    }
                }
            }

            float mt0 = -INFINITY, mt1 = -INFINITY;
            #pragma unroll
            for (int ni = 0; ni < 8; ++ni) {
                mt0 = fmaxf(mt0, fmaxf(sacc[ni][0], sacc[ni][1]));
                mt1 = fmaxf(mt1, fmaxf(sacc[ni][2], sacc[ni][3]));
            }
            mt0 = fmaxf(mt0, __shfl_xor_sync(0xffffffffu, mt0, 1));
            mt0 = fmaxf(mt0, __shfl_xor_sync(0xffffffffu, mt0, 2));
            mt1 = fmaxf(mt1, __shfl_xor_sync(0xffffffffu, mt1, 1));
            mt1 = fmaxf(mt1, __shfl_xor_sync(0xffffffffu, mt1, 2));
            const float mn0 = fmaxf(m0, mt0), mn1 = fmaxf(m1, mt1);
            const float sc0 = __expf(m0 - mn0), sc1 = __expf(m1 - mn1);
            m0 = mn0; m1 = mn1;
            float ls0 = 0.f, ls1 = 0.f;
            #pragma unroll
            for (int ni = 0; ni < 8; ++ni) {
                sacc[ni][0] = __expf(sacc[ni][0] - mn0);
                sacc[ni][1] = __expf(sacc[ni][1] - mn0);
                sacc[ni][2] = __expf(sacc[ni][2] - mn1);
                sacc[ni][3] = __expf(sacc[ni][3] - mn1);
                ls0 += sacc[ni][0] + sacc[ni][1];
                ls1 += sacc[ni][2] + sacc[ni][3];
            }
            ls0 += __shfl_xor_sync(0xffffffffu, ls0, 1);
            ls0 += __shfl_xor_sync(0xffffffffu, ls0, 2);
            ls1 += __shfl_xor_sync(0xffffffffu, ls1, 1);
            ls1 += __shfl_xor_sync(0xffffffffu, ls1, 2);
            l0 = l0 * sc0 + ls0;
            l1 = l1 * sc1 + ls1;
            #pragma unroll
            for (int ni = 0; ni < 8; ++ni) {
                oacc[ni][0] *= sc0; oacc[ni][1] *= sc0;
                oacc[ni][2] *= sc1; oacc[ni][3] *= sc1;
            }

            u32 aPh[4][4], aPl[4][4];
            #pragma unroll
            for (int s = 0; s < 4; ++s) {
                #pragma unroll
                for (int half = 0; half < 2; ++half) {
                    const float p0 = sacc[2 * s + half][0], p1 = sacc[2 * s + half][1];
                    const float p2 = sacc[2 * s + half][2], p3 = sacc[2 * s + half][3];
                    const u16 h0 = fp_hi(p0), h1 = fp_hi(p1), h2 = fp_hi(p2), h3 = fp_hi(p3);
                    aPh[s][half * 2 + 0] = (u32)h0 | ((u32)h1 << 16);
                    aPh[s][half * 2 + 1] = (u32)h2 | ((u32)h3 << 16);
                    const u16 q0b = fp_lo(p0, h0), q1b = fp_lo(p1, h1);
                    const u16 q2b = fp_lo(p2, h2), q3b = fp_lo(p3, h3);
                    aPl[s][half * 2 + 0] = (u32)q0b | ((u32)q1b << 16);
                    aPl[s][half * 2 + 1] = (u32)q2b | ((u32)q3b << 16);
                }
            }

            #pragma unroll
            for (int s = 0; s < 4; ++s) {
                u32 bVh[8][2], bVl[8][2];
                #pragma unroll
                for (int nd = 0; nd < 4; ++nd) {
                    const uint32_t off = swz((uint32_t)((s * 16 + lr) * 128 + nd * 32 + ck * 16));
                    u32 r[4];
                    ldsm4t(r, st + 16384 + off);
                    bVh[2 * nd][0] = r[0]; bVh[2 * nd][1] = r[1];
                    bVh[2 * nd + 1][0] = r[2]; bVh[2 * nd + 1][1] = r[3];
                    ldsm4t(r, st + 24576 + off);
                    bVl[2 * nd][0] = r[0]; bVl[2 * nd][1] = r[1];
                    bVl[2 * nd + 1][0] = r[2]; bVl[2 * nd + 1][1] = r[3];
                }
                #pragma unroll
                for (int ni = 0; ni < 8; ++ni) {
                    mma_fp16(oacc[ni], aPh[s], bVh[ni]);
                    mma_fp16(oacc[ni], aPh[s], bVl[ni]);
                    mma_fp16(oacc[ni], aPl[s], bVh[ni]);
                }
            }
        }
        __syncthreads();
    }

    // writeout: y hi only (consumed by 1-term FF1)
    const float rl0 = 1.f / l0, rl1 = 1.f / l1;
    const int r0 = wrow0 + gid, r1 = r0 + 8;
    #pragma unroll
    for (int ni = 0; ni < 8; ++ni) {
        const int col = h * HDIM + ni * 8 + qp * 2;
        {
            const float v0 = oacc[ni][0] * rl0, v1 = oacc[ni][1] * rl0;
            const u16 h0 = fp_hi(v0), h1 = fp_hi(v1);
            *(u32*)(yh + (tokbase + r0) * CDIM + col) = (u32)h0 | ((u32)h1 << 16);
        }
        {
            const float v0 = oacc[ni][2] * rl1, v1 = oacc[ni][3] * rl1;
            const u16 h0 = fp_hi(v0), h1 = fp_hi(v1);
            *(u32*)(yh + (tokbase + r1) * CDIM + col) = (u32)h0 | ((u32)h1 << 16);
        }
    }
}

// ---------------- residual + LayerNorm ----------------
__device__ __forceinline__ float block_sum256(float v, float* red) {
    const int lane = threadIdx.x & 31;
    const int w = threadIdx.x >> 5;
    #pragma unroll
    for (int off = 16; off; off >>= 1) v += __shfl_xor_sync(0xffffffffu, v, off);
    if (lane == 0) red[w] = v;
    __syncthreads();
    float t = (threadIdx.x < 8) ? red[threadIdx.x] : 0.f;
    if (w == 0) {
        t += __shfl_xor_sync(0xffffffffu, t, 4);
        t += __shfl_xor_sync(0xffffffffu, t, 2);
        t += __shfl_xor_sync(0xffffffffu, t, 1);
        if (lane == 0) red[0] = t;
    }
    __syncthreads();
    const float r = red[0];
    __syncthreads();
    return r;
}

template<bool PAIR>
__global__ __launch_bounds__(256) void add_ln_kernel(
    const float* __restrict__ xres, const float* __restrict__ v,
    const float* __restrict__ g, const float* __restrict__ be,
    float* __restrict__ out, u16* __restrict__ oh)
{
    __shared__ float red[8];
    const size_t row = blockIdx.x;
    const int c0 = threadIdx.x * 4;
    const float* vr = v + row * CDIM;

    float vals[4];
    *(float4*)vals = *(const float4*)(vr + c0);
    float s = vals[0] + vals[1] + vals[2] + vals[3];
    const float mean = block_sum256(s, red) * (1.f / CDIM);

    float d2 = 0.f;
    #pragma unroll
    for (int i = 0; i < 4; ++i) {
        const float d = vals[i] - mean;
        d2 = fmaf(d, d, d2);
    }
    const float var = block_sum256(d2, red) * (1.f / CDIM);
    const float rstd = rsqrtf(var + 1e-5f);

    float4 xr = *(const float4*)(xres + row * CDIM + c0);
    float4 gg = *(const float4*)(g + c0);
    float4 bb = *(const float4*)(be + c0);
    float4 res;
    res.x = xr.x + (vals[0] - mean) * rstd * gg.x + bb.x;
    res.y = xr.y + (vals[1] - mean) * rstd * gg.y + bb.y;
    res.z = xr.z + (vals[2] - mean) * rstd * gg.z + bb.z;
    res.w = xr.w + (vals[3] - mean) * rstd * gg.w + bb.w;
    *(float4*)(out + row * CDIM + c0) = res;
    if (PAIR) {
        u16 h0 = fp_hi(res.x), h1 = fp_hi(res.y), h2 = fp_hi(res.z), h3 = fp_hi(res.w);
        *(uint2*)(oh + row * CDIM + c0) =
            make_uint2((u32)h0 | ((u32)h1 << 16), (u32)h2 | ((u32)h3 << 16));
    }
}

// ---------------- launch ----------------
extern "C" void kernel_launch(void* const* d_in, const int* in_sizes, int n_in,
                              void* d_out, int out_size)
{
    const float* x      = (const float*)d_in[0];
    const float* w_attn = (const float*)d_in[1];
    const float* b_attn = (const float*)d_in[2];
    const float* wa1    = (const float*)d_in[3];
    const float* ba1    = (const float*)d_in[4];
    const float* wa2    = (const float*)d_in[5];
    const float* ba2    = (const float*)d_in[6];
    const float* g1     = (const float*)d_in[7];
    const float* be1    = (const float*)d_in[8];
    const float* wf1    = (const float*)d_in[9];
    const float* bf1    = (const float*)d_in[10];
    const float* wf2    = (const float*)d_in[11];
    const float* bf2    = (const float*)d_in[12];
    const float* g2     = (const float*)d_in[13];
    const float* be2    = (const float*)d_in[14];
    float* out = (float*)d_out;

    float *tbuf, *x1;
    u16 *xh, *xl, *qkvh, *qkvl, *yh, *x1h, *hh;
    u16 *wa, *w1, *w2, *w3, *w4;
    cudaGetSymbolAddress((void**)&tbuf, g_t);
    cudaGetSymbolAddress((void**)&x1, g_x1);
    cudaGetSymbolAddress((void**)&xh, g_xh);     cudaGetSymbolAddress((void**)&xl, g_xl);
    cudaGetSymbolAddress((void**)&qkvh, g_qkvh); cudaGetSymbolAddress((void**)&qkvl, g_qkvl);
    cudaGetSymbolAddress((void**)&yh, g_yh);
    cudaGetSymbolAddress((void**)&x1h, g_x1h);
    cudaGetSymbolAddress((void**)&hh, g_hh);
    cudaGetSymbolAddress((void**)&wa, g_wa);
    cudaGetSymbolAddress((void**)&w1, g_w1);
    cudaGetSymbolAddress((void**)&w2, g_w2);
    cudaGetSymbolAddress((void**)&w3, g_w3);
    cudaGetSymbolAddress((void**)&w4, g_w4);

    const int SM22 = 3 * 8192 * 2;   // TERMS=2 smem (48 KB)
    const int SM21 = 2 * 8192 * 2;   // TERMS=1 smem (32 KB)
    cudaFuncSetAttribute(mma_gemm<2,2>, cudaFuncAttributeMaxDynamicSharedMemorySize, SM22);
    cudaFuncSetAttribute(mma_gemm<1,1>, cudaFuncAttributeMaxDynamicSharedMemorySize, SM21);
    cudaFuncSetAttribute(mma_gemm<0,1>, cudaFuncAttributeMaxDynamicSharedMemorySize, SM21);
    cudaFuncSetAttribute(attn_mma, cudaFuncAttributeMaxDynamicSharedMemorySize, ATT_SMEM);

    const dim3 tb(32, 8);
    // order chosen so ncu (-s 5) lands on qkv GEMM (offset 2) or attn (offset 0)
    tdecomp_k<<<dim3(3 * CDIM / 32, CDIM / 32), tb>>>(w_attn, wa, CDIM, 3 * CDIM);  // 0
    decomp_k<<<(ROWS * CDIM / 4 + 255) / 256, 256>>>(x, xh, xl, ROWS * CDIM / 4);   // 1
    tdecomp_k<<<dim3(HID / 32, CDIM / 32), tb>>>(wa1, w1, CDIM, HID);               // 2

    // 3) qkv = x @ w_attn + b_attn -> fp16 hi/lo (TERMS=2)
    mma_gemm<2,2><<<dim3(3 * CDIM / 128, ROWS / 128), 256, SM22>>>(
        xh, xl, wa, b_attn, nullptr, qkvh, qkvl, 3 * CDIM, CDIM);

    tdecomp_k<<<dim3(CDIM / 32, HID / 32), tb>>>(wa2, w2, HID, CDIM);               // 4

    // 5) causal MHA -> y hi
    attn_mma<<<dim3(SEQ / 128, NHEAD, BATCH), 256, ATT_SMEM>>>(qkvh, qkvl, yh);

    tdecomp_k<<<dim3(HID / 32, CDIM / 32), tb>>>(wf1, w3, CDIM, HID);               // 6

    // h = gelu(y @ wa1 + ba1) -> fp16 hi (TERMS=1)
    mma_gemm<1,1><<<dim3(HID / 128, ROWS / 128), 256, SM21>>>(
        yh, nullptr, w1, ba1, nullptr, hh, nullptr, HID, CDIM);

    tdecomp_k<<<dim3(CDIM / 32, HID / 32), tb>>>(wf2, w4, HID, CDIM);               // 8

    // t = h @ wa2 + ba2 (fp32, TERMS=1)
    mma_gemm<0,1><<<dim3(CDIM / 128, ROWS / 128), 256, SM21>>>(
        hh, nullptr, w2, ba2, tbuf, nullptr, nullptr, CDIM, HID);

    // x1 = x + LN(t)
    add_ln_kernel<true><<<ROWS, 256>>>(x, tbuf, g1, be1, x1, x1h);

    // h = gelu(x1 @ wf1 + bf1) -> fp16 hi (TERMS=1)
    mma_gemm<1,1><<<dim3(HID / 128, ROWS / 128), 256, SM21>>>(
        x1h, nullptr, w3, bf1, nullptr, hh, nullptr, HID, CDIM);

    // t = h @ wf2 + bf2 (fp32, TERMS=1)
    mma_gemm<0,1><<<dim3(CDIM / 128, ROWS / 128), 256, SM21>>>(
        hh, nullptr, w4, bf2, tbuf, nullptr, nullptr, CDIM, HID);

    // out = x1 + LN(t)
    add_ln_kernel<false><<<ROWS, 256>>>(x1, tbuf, g2, be2, out, nullptr);
}

// round 11
// speedup vs baseline: 2.2227x; 1.1577x over previous
#include <cuda_runtime.h>
#include <cuda_fp16.h>
#include <math.h>
#include <stdint.h>

// Problem constants
#define BATCH 2
#define SEQ   2048
#define CDIM  1024
#define NHEAD 16
#define HDIM  64
#define ROWS  (BATCH * SEQ)          // 4096
#define HID   (4 * CDIM)             // 4096

typedef unsigned short u16;
typedef unsigned int   u32;

// ---------------- scratch (static device globals; no allocation) ----------------
__device__ float g_t  [(size_t)ROWS * CDIM];
__device__ float g_x1 [(size_t)ROWS * CDIM];
__device__ u16 g_xh [(size_t)ROWS * CDIM],  g_xl [(size_t)ROWS * CDIM];
__device__ u16 g_qkvh[(size_t)ROWS * 3 * CDIM], g_qkvl[(size_t)ROWS * 3 * CDIM];
__device__ u16 g_yh [(size_t)ROWS * CDIM];
__device__ u16 g_x1h[(size_t)ROWS * CDIM];
__device__ u16 g_hh [(size_t)ROWS * HID];
// transposed fp16 weights, layout [N][K]
__device__ u16 g_wa[(size_t)3*CDIM*CDIM];
__device__ u16 g_w1[(size_t)HID*CDIM];
__device__ u16 g_w2[(size_t)CDIM*HID];
__device__ u16 g_w3[(size_t)HID*CDIM];
__device__ u16 g_w4[(size_t)CDIM*HID];

// ---------------- helpers ----------------
__device__ __forceinline__ uint32_t smem_u32(const void* p) {
    uint32_t a;
    asm("{ .reg .u64 t; cvta.to.shared.u64 t, %1; cvt.u32.u64 %0, t; }" : "=r"(a) : "l"(p));
    return a;
}
__device__ __forceinline__ void cp16(uint32_t dst, const void* src) {
    asm volatile("cp.async.cg.shared.global [%0], [%1], 16;" :: "r"(dst), "l"(src) : "memory");
}
#define CP_COMMIT() asm volatile("cp.async.commit_group;" ::: "memory")
#define CP_WAIT(n)  asm volatile("cp.async.wait_group %0;" :: "n"(n) : "memory")

__device__ __forceinline__ void ldsm4(u32* r, u32 addr) {
    asm volatile("ldmatrix.sync.aligned.m8n8.x4.shared.b16 {%0,%1,%2,%3}, [%4];"
        : "=r"(r[0]), "=r"(r[1]), "=r"(r[2]), "=r"(r[3]) : "r"(addr));
}
__device__ __forceinline__ void ldsm4t(u32* r, u32 addr) {
    asm volatile("ldmatrix.sync.aligned.m8n8.x4.trans.shared.b16 {%0,%1,%2,%3}, [%4];"
        : "=r"(r[0]), "=r"(r[1]), "=r"(r[2]), "=r"(r[3]) : "r"(addr));
}
__device__ __forceinline__ void mma_fp16(float* d, const u32* a, const u32* b) {
    asm volatile("mma.sync.aligned.m16n8k16.row.col.f32.f16.f16.f32 "
        "{%0,%1,%2,%3}, {%4,%5,%6,%7}, {%8,%9}, {%0,%1,%2,%3};"
        : "+f"(d[0]), "+f"(d[1]), "+f"(d[2]), "+f"(d[3])
        : "r"(a[0]), "r"(a[1]), "r"(a[2]), "r"(a[3]), "r"(b[0]), "r"(b[1]));
}
__device__ __forceinline__ uint32_t swz(uint32_t off) { return off ^ ((off >> 3) & 0x70); }

__device__ __forceinline__ u16 fp_hi(float v) { return __half_as_ushort(__float2half_rn(v)); }
__device__ __forceinline__ u16 fp_lo(float v, u16 hb) {
    return __half_as_ushort(__float2half_rn(v - __half2float(__ushort_as_half(hb))));
}

// ---------------- decompose activations: fp32 -> fp16 hi/lo ----------------
__global__ __launch_bounds__(256) void decomp_k(const float* __restrict__ x,
                                                u16* __restrict__ h, u16* __restrict__ l, int n4) {
    int i = blockIdx.x * 256 + threadIdx.x;
    if (i >= n4) return;
    float4 v = ((const float4*)x)[i];
    u16 h0 = fp_hi(v.x), h1 = fp_hi(v.y), h2 = fp_hi(v.z), h3 = fp_hi(v.w);
    u16 l0 = fp_lo(v.x, h0), l1 = fp_lo(v.y, h1), l2 = fp_lo(v.z, h2), l3 = fp_lo(v.w, h3);
    ((uint2*)h)[i] = make_uint2((u32)h0 | ((u32)h1 << 16), (u32)h2 | ((u32)h3 << 16));
    ((uint2*)l)[i] = make_uint2((u32)l0 | ((u32)l1 << 16), (u32)l2 | ((u32)l3 << 16));
}

// ---------------- transpose weights: W[K][N] fp32 -> T[N][K] fp16 ----------------
__global__ __launch_bounds__(256) void tdecomp_k(const float* __restrict__ W,
                                                 u16* __restrict__ Th, int K, int N) {
    __shared__ float t[32][33];
    const int n0 = blockIdx.x * 32, k0 = blockIdx.y * 32;
    const int tx = threadIdx.x, ty = threadIdx.y;  // 32x8
    #pragma unroll
    for (int i = 0; i < 32; i += 8)
        t[ty + i][tx] = W[(size_t)(k0 + ty + i) * N + n0 + tx];
    __syncthreads();
    #pragma unroll
    for (int i = 0; i < 32; i += 8) {
        float v = t[tx][ty + i];
        Th[(size_t)(n0 + ty + i) * K + k0 + tx] = fp_hi(v);
    }
}

// ---------------- tensor-core GEMM via mma.sync (fp16) ----------------
// TERMS=2: C = (Ah+Al) @ B^T.  TERMS=1: C = Ah @ B^T.
// OUT=0: fp32 C + bias. OUT=1: gelu -> fp16 hi only. OUT=2: fp16 hi/lo.
// BK=64, 2-stage cp.async. Tiles 128x64 = 16 KB each (full 128B rows).
#define BK 64

template<int OUT, int TERMS>
__global__ __launch_bounds__(256, 2) void mma_gemm(
    const u16* __restrict__ Ahi, const u16* __restrict__ Alo,
    const u16* __restrict__ B,
    const float* __restrict__ bias,
    float* __restrict__ C, u16* __restrict__ Chi, u16* __restrict__ Clo,
    int N, int K)
{
    extern __shared__ char smem_raw[];
    const uint32_t sbase = smem_u32(smem_raw);
    const uint32_t STAGE = (TERMS + 1) * 16384;
    const uint32_t BOFF  = TERMS * 16384;

    const int tid = threadIdx.x, lane = tid & 31, wid = tid >> 5;
    const int warp_m = wid & 3, warp_n = wid >> 2;
    const int bm = blockIdx.y * 128, bn = blockIdx.x * 128;

    const u16* aH = Ahi + (size_t)bm * K;
    const u16* aL = (TERMS == 2) ? (Alo + (size_t)bm * K) : nullptr;
    const u16* bH = B + (size_t)bn * K;

    const int nk = K / BK;

    auto load_stage = [&](int t) {
        const uint32_t st = sbase + (uint32_t)(t & 1) * STAGE;
        const int k0 = t * BK;
        #pragma unroll
        for (int i = 0; i < 4; ++i) {
            const int idx = i * 256 + tid;          // 1024 segs per 16KB tile
            const int row = idx >> 3, seg = idx & 7;
            const uint32_t soff = swz((uint32_t)(row * 128 + seg * 16));
            const size_t goff = (size_t)row * K + k0 + seg * 8;
            cp16(st + soff, aH + goff);
            if (TERMS == 2) cp16(st + 16384 + soff, aL + goff);
            cp16(st + BOFF + soff, bH + goff);
        }
        CP_COMMIT();
    };

    float acc[2][8][4];
    #pragma unroll
    for (int mi = 0; mi < 2; ++mi)
        #pragma unroll
        for (int ni = 0; ni < 8; ++ni)
            #pragma unroll
            for (int j = 0; j < 4; ++j) acc[mi][ni][j] = 0.f;

    load_stage(0);

    const int lrow = lane & 15;
    const int kblk = lane >> 4;

    for (int t = 0; t < nk; ++t) {
        if (t + 1 < nk) {
            load_stage(t + 1);
            CP_WAIT(1);
        } else {
            CP_WAIT(0);
        }
        __syncthreads();

        const uint32_t st = sbase + (uint32_t)(t & 1) * STAGE;

        #pragma unroll
        for (int s = 0; s < BK / 16; ++s) {
            const int c16 = s * 2 + kblk;
            u32 a_hi[2][4], a_lo[2][4];
            #pragma unroll
            for (int mi = 0; mi < 2; ++mi) {
                const uint32_t off = swz((uint32_t)((warp_m * 32 + mi * 16 + lrow) * 128 + c16 * 16));
                ldsm4(a_hi[mi], st + off);
                if (TERMS == 2) ldsm4(a_lo[mi], st + 16384 + off);
            }
            u32 bb[8][2];
            #pragma unroll
            for (int nb = 0; nb < 4; ++nb) {
                const uint32_t off = swz((uint32_t)((warp_n * 64 + nb * 16 + lrow) * 128 + c16 * 16));
                u32 r[4];
                ldsm4(r, st + BOFF + off);
                bb[nb * 2][0] = r[0]; bb[nb * 2 + 1][0] = r[1];
                bb[nb * 2][1] = r[2]; bb[nb * 2 + 1][1] = r[3];
            }
            #pragma unroll
            for (int mi = 0; mi < 2; ++mi)
                #pragma unroll
                for (int ni = 0; ni < 8; ++ni) {
                    mma_fp16(acc[mi][ni], a_hi[mi], bb[ni]);
                    if (TERMS == 2) mma_fp16(acc[mi][ni], a_lo[mi], bb[ni]);
                }
        }
        __syncthreads();
    }

    #pragma unroll
    for (int ni = 0; ni < 8; ++ni) {
        const int col = bn + warp_n * 64 + ni * 8 + (lane & 3) * 2;
        const float b0 = bias[col], b1 = bias[col + 1];
        #pragma unroll
        for (int mi = 0; mi < 2; ++mi) {
            const int r0 = bm + warp_m * 32 + mi * 16 + (lane >> 2);
            #pragma unroll
            for (int half = 0; half < 2; ++half) {
                const int r = r0 + half * 8;
                float v0 = acc[mi][ni][half * 2 + 0] + b0;
                float v1 = acc[mi][ni][half * 2 + 1] + b1;
                if (OUT == 0) {
                    *(float2*)(C + (size_t)r * N + col) = make_float2(v0, v1);
                } else if (OUT == 1) {
                    v0 *= normcdff(v0);
                    v1 *= normcdff(v1);
                    u16 h0 = fp_hi(v0), h1 = fp_hi(v1);
                    *(u32*)(Chi + (size_t)r * N + col) = (u32)h0 | ((u32)h1 << 16);
                } else {
                    u16 h0 = fp_hi(v0), h1 = fp_hi(v1);
                    u16 l0 = fp_lo(v0, h0), l1 = fp_lo(v1, h1);
                    *(u32*)(Chi + (size_t)r * N + col) = (u32)h0 | ((u32)h1 << 16);
                    *(u32*)(Clo + (size_t)r * N + col) = (u32)l0 | ((u32)l1 << 16);
                }
            }
        }
    }
}

// ---------------- tensor-core flash attention (causal, fp16 2-term), qkv split K|Q|V ----------------
// S = Qh (Kh + Kl)^T ; O = Ph (Vh + Vl). 256 threads, 128 queries/CTA, heavy-first.
// smem: Qh(16K) | 2 x { Kh Kl Vh Vl } (8K each)
#define ATT_STAGE 32768
#define ATT_SMEM (16384 + 2 * ATT_STAGE)   // 80 KB

__global__ __launch_bounds__(256) void attn_mma(
    const u16* __restrict__ qkvh, const u16* __restrict__ qkvl,
    u16* __restrict__ yh)
{
    extern __shared__ char smem_raw[];
    const uint32_t sb = smem_u32(smem_raw);
    const int tid = threadIdx.x, lane = tid & 31, wid = tid >> 5;
    const int qt = gridDim.x - 1 - blockIdx.x;   // heavy tiles first
    const int h = blockIdx.y, b = blockIdx.z;
    const int q0 = qt * 128;
    const int gid = lane >> 2, qp = lane & 3;
    const size_t tokbase = (size_t)b * SEQ;
    const int rs = 3 * CDIM;

    // Q hi load (128 rows)
    #pragma unroll
    for (int i = 0; i < 4; ++i) {
        const int idx = i * 256 + tid;
        const int row = idx >> 3, seg = idx & 7;
        const uint32_t off = swz((uint32_t)(row * 128 + seg * 16));
        const size_t g = (tokbase + q0 + row) * rs + CDIM + h * HDIM + seg * 8;
        cp16(sb + off, qkvh + g);
    }

    auto load_stage = [&](int t) {
        const uint32_t st = sb + 16384 + (uint32_t)(t & 1) * ATT_STAGE;
        const int k0 = t * 64;
        #pragma unroll
        for (int i = 0; i < 2; ++i) {
            const int idx = i * 256 + tid;
            const int row = idx >> 3, seg = idx & 7;
            const uint32_t off = swz((uint32_t)(row * 128 + seg * 16));
            const size_t gk = (tokbase + k0 + row) * rs + h * HDIM + seg * 8;
            const size_t gv = gk + 2 * CDIM;
            cp16(st + off,         qkvh + gk);
            cp16(st + 8192 + off,  qkvl + gk);
            cp16(st + 16384 + off, qkvh + gv);
            cp16(st + 24576 + off, qkvl + gv);
        }
        CP_COMMIT();
    };

    const int ntiles = 2 * qt + 2;
    load_stage(0);

    float m0 = -INFINITY, m1 = -INFINITY, l0 = 0.f, l1 = 0.f;
    float oacc[8][4];
    #pragma unroll
    for (int ni = 0; ni < 8; ++ni)
        #pragma unroll
        for (int j = 0; j < 4; ++j) oacc[ni][j] = 0.f;

    const int lr = lane & 15, ck = lane >> 4;
    const int wrow0 = q0 + wid * 16;

    for (int t = 0; t < ntiles; ++t) {
        if (t + 1 < ntiles) {
            load_stage(t + 1);
            CP_WAIT(1);
        } else {
            CP_WAIT(0);
        }
        __syncthreads();
        const uint32_t st = sb + 16384 + (uint32_t)(t & 1) * ATT_STAGE;
        const int k0 = t * 64;
        const bool active = (k0 <= wrow0 + 15);

        if (active) {
            float sacc[8][4];
            #pragma unroll
            for (int ni = 0; ni < 8; ++ni)
                #pragma unroll
                for (int j = 0; j < 4; ++j) sacc[ni][j] = 0.f;

            #pragma unroll
            for (int s = 0; s < 4; ++s) {
                const int c16 = s * 2 + ck;
                u32 aH[4];
                {
                    const uint32_t off = swz((uint32_t)((wid * 16 + lr) * 128 + c16 * 16));
                    ldsm4(aH, sb + off);
                }
                u32 bH[8][2], bL[8][2];
                #pragma unroll
                for (int ng = 0; ng < 4; ++ng) {
                    const uint32_t off = swz((uint32_t)((ng * 16 + lr) * 128 + c16 * 16));
                    u32 r[4];
                    ldsm4(r, st + off);
                    bH[2 * ng][0] = r[0]; bH[2 * ng + 1][0] = r[1];
                    bH[2 * ng][1] = r[2]; bH[2 * ng + 1][1] = r[3];
                    ldsm4(r, st + 8192 + off);
                    bL[2 * ng][0] = r[0]; bL[2 * ng + 1][0] = r[1];
                    bL[2 * ng][1] = r[2]; bL[2 * ng + 1][1] = r[3];
                }
                #pragma unroll
                for (int ni = 0; ni < 8; ++ni) {
                    mma_fp16(sacc[ni], aH, bH[ni]);
                    mma_fp16(sacc[ni], aH, bL[ni]);
                }
            }
            #pragma unroll
            for (int ni = 0; ni < 8; ++ni)
                #pragma unroll
                for (int j = 0; j < 4; ++j) sacc[ni][j] *= 0.125f;

            if (k0 + 63 > wrow0) {
                #pragma unroll
                for (int ni = 0; ni < 8; ++ni) {
                    const int kbase = k0 + ni * 8 + qp * 2;
                    #pragma unroll
                    for (int j = 0; j < 4; ++j) {
                        if (kbase + (j & 1) > wrow0 + gid + (j >> 1) * 8) sacc[ni][j] = -INFINITY;
                    }
                }
            }

            float mt0 = -INFINITY, mt1 = -INFINITY;
            #pragma unroll
            for (int ni = 0; ni < 8; ++ni) {
                mt0 = fmaxf(mt0, fmaxf(sacc[ni][0], sacc[ni][1]));
                mt1 = fmaxf(mt1, fmaxf(sacc[ni][2], sacc[ni][3]));
            }
            mt0 = fmaxf(mt0, __shfl_xor_sync(0xffffffffu, mt0, 1));
            mt0 = fmaxf(mt0, __shfl_xor_sync(0xffffffffu, mt0, 2));
            mt1 = fmaxf(mt1, __shfl_xor_sync(0xffffffffu, mt1, 1));
            mt1 = fmaxf(mt1, __shfl_xor_sync(0xffffffffu, mt1, 2));
            const float mn0 = fmaxf(m0, mt0), mn1 = fmaxf(m1, mt1);
            const float sc0 = __expf(m0 - mn0), sc1 = __expf(m1 - mn1);
            m0 = mn0; m1 = mn1;
            float ls0 = 0.f, ls1 = 0.f;
            #pragma unroll
            for (int ni = 0; ni < 8; ++ni) {
                sacc[ni][0] = __expf(sacc[ni][0] - mn0);
                sacc[ni][1] = __expf(sacc[ni][1] - mn0);
                sacc[ni][2] = __expf(sacc[ni][2] - mn1);
                sacc[ni][3] = __expf(sacc[ni][3] - mn1);
                ls0 += sacc[ni][0] + sacc[ni][1];
                ls1 += sacc[ni][2] + sacc[ni][3];
            }
            ls0 += __shfl_xor_sync(0xffffffffu, ls0, 1);
            ls0 += __shfl_xor_sync(0xffffffffu, ls0, 2);
            ls1 += __shfl_xor_sync(0xffffffffu, ls1, 1);
            ls1 += __shfl_xor_sync(0xffffffffu, ls1, 2);
            l0 = l0 * sc0 + ls0;
            l1 = l1 * sc1 + ls1;
            #pragma unroll
            for (int ni = 0; ni < 8; ++ni) {
                oacc[ni][0] *= sc0; oacc[ni][1] *= sc0;
                oacc[ni][2] *= sc1; oacc[ni][3] *= sc1;
            }

            // pack P (hi only)
            u32 aPh[4][4];
            #pragma unroll
            for (int s = 0; s < 4; ++s) {
                #pragma unroll
                for (int half = 0; half < 2; ++half) {
                    const float p0 = sacc[2 * s + half][0], p1 = sacc[2 * s + half][1];
                    const float p2 = sacc[2 * s + half][2], p3 = sacc[2 * s + half][3];
                    const u16 h0 = fp_hi(p0), h1 = fp_hi(p1), h2 = fp_hi(p2), h3 = fp_hi(p3);
                    aPh[s][half * 2 + 0] = (u32)h0 | ((u32)h1 << 16);
                    aPh[s][half * 2 + 1] = (u32)h2 | ((u32)h3 << 16);
                }
            }

            // O += Ph (Vh + Vl)
            #pragma unroll
            for (int s = 0; s < 4; ++s) {
                u32 bVh[8][2], bVl[8][2];
                #pragma unroll
                for (int nd = 0; nd < 4; ++nd) {
                    const uint32_t off = swz((uint32_t)((s * 16 + lr) * 128 + nd * 32 + ck * 16));
                    u32 r[4];
                    ldsm4t(r, st + 16384 + off);
                    bVh[2 * nd][0] = r[0]; bVh[2 * nd][1] = r[1];
                    bVh[2 * nd + 1][0] = r[2]; bVh[2 * nd + 1][1] = r[3];
                    ldsm4t(r, st + 24576 + off);
                    bVl[2 * nd][0] = r[0]; bVl[2 * nd][1] = r[1];
                    bVl[2 * nd + 1][0] = r[2]; bVl[2 * nd + 1][1] = r[3];
                }
                #pragma unroll
                for (int ni = 0; ni < 8; ++ni) {
                    mma_fp16(oacc[ni], aPh[s], bVh[ni]);
                    mma_fp16(oacc[ni], aPh[s], bVl[ni]);
                }
            }
        }
        __syncthreads();
    }

    const float rl0 = 1.f / l0, rl1 = 1.f / l1;
    const int r0 = wrow0 + gid, r1 = r0 + 8;
    #pragma unroll
    for (int ni = 0; ni < 8; ++ni) {
        const int col = h * HDIM + ni * 8 + qp * 2;
        {
            const float v0 = oacc[ni][0] * rl0, v1 = oacc[ni][1] * rl0;
            const u16 h0 = fp_hi(v0), h1 = fp_hi(v1);
            *(u32*)(yh + (tokbase + r0) * CDIM + col) = (u32)h0 | ((u32)h1 << 16);
        }
        {
            const float v0 = oacc[ni][2] * rl1, v1 = oacc[ni][3] * rl1;
            const u16 h0 = fp_hi(v0), h1 = fp_hi(v1);
            *(u32*)(yh + (tokbase + r1) * CDIM + col) = (u32)h0 | ((u32)h1 << 16);
        }
    }
}

// ---------------- residual + LayerNorm ----------------
__device__ __forceinline__ float block_sum256(float v, float* red) {
    const int lane = threadIdx.x & 31;
    const int w = threadIdx.x >> 5;
    #pragma unroll
    for (int off = 16; off; off >>= 1) v += __shfl_xor_sync(0xffffffffu, v, off);
    if (lane == 0) red[w] = v;
    __syncthreads();
    float t = (threadIdx.x < 8) ? red[threadIdx.x] : 0.f;
    if (w == 0) {
        t += __shfl_xor_sync(0xffffffffu, t, 4);
        t += __shfl_xor_sync(0xffffffffu, t, 2);
        t += __shfl_xor_sync(0xffffffffu, t, 1);
        if (lane == 0) red[0] = t;
    }
    __syncthreads();
    const float r = red[0];
    __syncthreads();
    return r;
}

template<bool PAIR>
__global__ __launch_bounds__(256) void add_ln_kernel(
    const float* __restrict__ xres, const float* __restrict__ v,
    const float* __restrict__ g, const float* __restrict__ be,
    float* __restrict__ out, u16* __restrict__ oh)
{
    __shared__ float red[8];
    const size_t row = blockIdx.x;
    const int c0 = threadIdx.x * 4;
    const float* vr = v + row * CDIM;

    float vals[4];
    *(float4*)vals = *(const float4*)(vr + c0);
    float s = vals[0] + vals[1] + vals[2] + vals[3];
    const float mean = block_sum256(s, red) * (1.f / CDIM);

    float d2 = 0.f;
    #pragma unroll
    for (int i = 0; i < 4; ++i) {
        const float d = vals[i] - mean;
        d2 = fmaf(d, d, d2);
    }
    const float var = block_sum256(d2, red) * (1.f / CDIM);
    const float rstd = rsqrtf(var + 1e-5f);

    float4 xr = *(const float4*)(xres + row * CDIM + c0);
    float4 gg = *(const float4*)(g + c0);
    float4 bb = *(const float4*)(be + c0);
    float4 res;
    res.x = xr.x + (vals[0] - mean) * rstd * gg.x + bb.x;
    res.y = xr.y + (vals[1] - mean) * rstd * gg.y + bb.y;
    res.z = xr.z + (vals[2] - mean) * rstd * gg.z + bb.z;
    res.w = xr.w + (vals[3] - mean) * rstd * gg.w + bb.w;
    *(float4*)(out + row * CDIM + c0) = res;
    if (PAIR) {
        u16 h0 = fp_hi(res.x), h1 = fp_hi(res.y), h2 = fp_hi(res.z), h3 = fp_hi(res.w);
        *(uint2*)(oh + row * CDIM + c0) =
            make_uint2((u32)h0 | ((u32)h1 << 16), (u32)h2 | ((u32)h3 << 16));
    }
}

// ---------------- launch ----------------
extern "C" void kernel_launch(void* const* d_in, const int* in_sizes, int n_in,
                              void* d_out, int out_size)
{
    const float* x      = (const float*)d_in[0];
    const float* w_attn = (const float*)d_in[1];
    const float* b_attn = (const float*)d_in[2];
    const float* wa1    = (const float*)d_in[3];
    const float* ba1    = (const float*)d_in[4];
    const float* wa2    = (const float*)d_in[5];
    const float* ba2    = (const float*)d_in[6];
    const float* g1     = (const float*)d_in[7];
    const float* be1    = (const float*)d_in[8];
    const float* wf1    = (const float*)d_in[9];
    const float* bf1    = (const float*)d_in[10];
    const float* wf2    = (const float*)d_in[11];
    const float* bf2    = (const float*)d_in[12];
    const float* g2     = (const float*)d_in[13];
    const float* be2    = (const float*)d_in[14];
    float* out = (float*)d_out;

    float *tbuf, *x1;
    u16 *xh, *xl, *qkvh, *qkvl, *yh, *x1h, *hh;
    u16 *wa, *w1, *w2, *w3, *w4;
    cudaGetSymbolAddress((void**)&tbuf, g_t);
    cudaGetSymbolAddress((void**)&x1, g_x1);
    cudaGetSymbolAddress((void**)&xh, g_xh);     cudaGetSymbolAddress((void**)&xl, g_xl);
    cudaGetSymbolAddress((void**)&qkvh, g_qkvh); cudaGetSymbolAddress((void**)&qkvl, g_qkvl);
    cudaGetSymbolAddress((void**)&yh, g_yh);
    cudaGetSymbolAddress((void**)&x1h, g_x1h);
    cudaGetSymbolAddress((void**)&hh, g_hh);
    cudaGetSymbolAddress((void**)&wa, g_wa);
    cudaGetSymbolAddress((void**)&w1, g_w1);
    cudaGetSymbolAddress((void**)&w2, g_w2);
    cudaGetSymbolAddress((void**)&w3, g_w3);
    cudaGetSymbolAddress((void**)&w4, g_w4);

    const int SM22 = 3 * 16384 * 2;   // TERMS=2 smem (96 KB)
    const int SM21 = 2 * 16384 * 2;   // TERMS=1 smem (64 KB)
    cudaFuncSetAttribute(mma_gemm<2,2>, cudaFuncAttributeMaxDynamicSharedMemorySize, SM22);
    cudaFuncSetAttribute(mma_gemm<1,1>, cudaFuncAttributeMaxDynamicSharedMemorySize, SM21);
    cudaFuncSetAttribute(mma_gemm<0,1>, cudaFuncAttributeMaxDynamicSharedMemorySize, SM21);
    cudaFuncSetAttribute(attn_mma, cudaFuncAttributeMaxDynamicSharedMemorySize, ATT_SMEM);

    const dim3 tb(32, 8);
    tdecomp_k<<<dim3(3 * CDIM / 32, CDIM / 32), tb>>>(w_attn, wa, CDIM, 3 * CDIM);  // 0
    decomp_k<<<(ROWS * CDIM / 4 + 255) / 256, 256>>>(x, xh, xl, ROWS * CDIM / 4);   // 1
    tdecomp_k<<<dim3(HID / 32, CDIM / 32), tb>>>(wa1, w1, CDIM, HID);               // 2

    // 3) qkv = x @ w_attn + b_attn -> fp16 hi/lo (TERMS=2)
    mma_gemm<2,2><<<dim3(3 * CDIM / 128, ROWS / 128), 256, SM22>>>(
        xh, xl, wa, b_attn, nullptr, qkvh, qkvl, 3 * CDIM, CDIM);

    tdecomp_k<<<dim3(CDIM / 32, HID / 32), tb>>>(wa2, w2, HID, CDIM);               // 4

    // 5) causal MHA -> y hi
    attn_mma<<<dim3(SEQ / 128, NHEAD, BATCH), 256, ATT_SMEM>>>(qkvh, qkvl, yh);

    tdecomp_k<<<dim3(HID / 32, CDIM / 32), tb>>>(wf1, w3, CDIM, HID);               // 6

    // h = gelu(y @ wa1 + ba1) -> fp16 hi (TERMS=1)
    mma_gemm<1,1><<<dim3(HID / 128, ROWS / 128), 256, SM21>>>(
        yh, nullptr, w1, ba1, nullptr, hh, nullptr, HID, CDIM);

    tdecomp_k<<<dim3(CDIM / 32, HID / 32), tb>>>(wf2, w4, HID, CDIM);               // 8

    // t = h @ wa2 + ba2 (fp32, TERMS=1)
    mma_gemm<0,1><<<dim3(CDIM / 128, ROWS / 128), 256, SM21>>>(
        hh, nullptr, w2, ba2, tbuf, nullptr, nullptr, CDIM, HID);

    // x1 = x + LN(t)
    add_ln_kernel<true><<<ROWS, 256>>>(x, tbuf, g1, be1, x1, x1h);

    // h = gelu(x1 @ wf1 + bf1) -> fp16 hi (TERMS=1)
    mma_gemm<1,1><<<dim3(HID / 128, ROWS / 128), 256, SM21>>>(
        x1h, nullptr, w3, bf1, nullptr, hh, nullptr, HID, CDIM);

    // t = h @ wf2 + bf2 (fp32, TERMS=1)
    mma_gemm<0,1><<<dim3(CDIM / 128, ROWS / 128), 256, SM21>>>(
        hh, nullptr, w4, bf2, tbuf, nullptr, nullptr, CDIM, HID);

    // out = x1 + LN(t)
    add_ln_kernel<false><<<ROWS, 256>>>(x1, tbuf, g2, be2, out, nullptr);
}

// round 12
// speedup vs baseline: 2.6817x; 1.2065x over previous
#include <cuda_runtime.h>
#include <cuda_fp16.h>
#include <math.h>
#include <stdint.h>

// Problem constants
#define BATCH 2
#define SEQ   2048
#define CDIM  1024
#define NHEAD 16
#define HDIM  64
#define ROWS  (BATCH * SEQ)          // 4096
#define HID   (4 * CDIM)             // 4096

typedef unsigned short u16;
typedef unsigned int   u32;

// ---------------- scratch (static device globals; no allocation) ----------------
__device__ float g_t  [(size_t)ROWS * CDIM];
__device__ float g_x1 [(size_t)ROWS * CDIM];
__device__ u16 g_xh  [(size_t)ROWS * CDIM];
__device__ u16 g_qkvh[(size_t)ROWS * 3 * CDIM];
__device__ u16 g_yh  [(size_t)ROWS * CDIM];
__device__ u16 g_x1h [(size_t)ROWS * CDIM];
__device__ u16 g_hh  [(size_t)ROWS * HID];
// transposed fp16 weights, layout [N][K]
__device__ u16 g_wa[(size_t)3*CDIM*CDIM];
__device__ u16 g_w1[(size_t)HID*CDIM];
__device__ u16 g_w2[(size_t)CDIM*HID];
__device__ u16 g_w3[(size_t)HID*CDIM];
__device__ u16 g_w4[(size_t)CDIM*HID];

// ---------------- helpers ----------------
__device__ __forceinline__ uint32_t smem_u32(const void* p) {
    uint32_t a;
    asm("{ .reg .u64 t; cvta.to.shared.u64 t, %1; cvt.u32.u64 %0, t; }" : "=r"(a) : "l"(p));
    return a;
}
__device__ __forceinline__ void cp16(uint32_t dst, const void* src) {
    asm volatile("cp.async.cg.shared.global [%0], [%1], 16;" :: "r"(dst), "l"(src) : "memory");
}
#define CP_COMMIT() asm volatile("cp.async.commit_group;" ::: "memory")
#define CP_WAIT(n)  asm volatile("cp.async.wait_group %0;" :: "n"(n) : "memory")

__device__ __forceinline__ void ldsm4(u32* r, u32 addr) {
    asm volatile("ldmatrix.sync.aligned.m8n8.x4.shared.b16 {%0,%1,%2,%3}, [%4];"
        : "=r"(r[0]), "=r"(r[1]), "=r"(r[2]), "=r"(r[3]) : "r"(addr));
}
__device__ __forceinline__ void ldsm4t(u32* r, u32 addr) {
    asm volatile("ldmatrix.sync.aligned.m8n8.x4.trans.shared.b16 {%0,%1,%2,%3}, [%4];"
        : "=r"(r[0]), "=r"(r[1]), "=r"(r[2]), "=r"(r[3]) : "r"(addr));
}
__device__ __forceinline__ void mma_fp16(float* d, const u32* a, const u32* b) {
    asm volatile("mma.sync.aligned.m16n8k16.row.col.f32.f16.f16.f32 "
        "{%0,%1,%2,%3}, {%4,%5,%6,%7}, {%8,%9}, {%0,%1,%2,%3};"
        : "+f"(d[0]), "+f"(d[1]), "+f"(d[2]), "+f"(d[3])
        : "r"(a[0]), "r"(a[1]), "r"(a[2]), "r"(a[3]), "r"(b[0]), "r"(b[1]));
}
__device__ __forceinline__ uint32_t swz(uint32_t off) { return off ^ ((off >> 3) & 0x70); }

__device__ __forceinline__ u16 fp_hi(float v) { return __half_as_ushort(__float2half_rn(v)); }

// ---------------- convert activations: fp32 -> fp16 ----------------
__global__ __launch_bounds__(256) void conv_k(const float* __restrict__ x,
                                              u16* __restrict__ h, int n4) {
    int i = blockIdx.x * 256 + threadIdx.x;
    if (i >= n4) return;
    float4 v = ((const float4*)x)[i];
    u16 h0 = fp_hi(v.x), h1 = fp_hi(v.y), h2 = fp_hi(v.z), h3 = fp_hi(v.w);
    ((uint2*)h)[i] = make_uint2((u32)h0 | ((u32)h1 << 16), (u32)h2 | ((u32)h3 << 16));
}

// ---------------- transpose weights: W[K][N] fp32 -> T[N][K] fp16 ----------------
__global__ __launch_bounds__(256) void tdecomp_k(const float* __restrict__ W,
                                                 u16* __restrict__ Th, int K, int N) {
    __shared__ float t[32][33];
    const int n0 = blockIdx.x * 32, k0 = blockIdx.y * 32;
    const int tx = threadIdx.x, ty = threadIdx.y;  // 32x8
    #pragma unroll
    for (int i = 0; i < 32; i += 8)
        t[ty + i][tx] = W[(size_t)(k0 + ty + i) * N + n0 + tx];
    __syncthreads();
    #pragma unroll
    for (int i = 0; i < 32; i += 8) {
        float v = t[tx][ty + i];
        Th[(size_t)(n0 + ty + i) * K + k0 + tx] = fp_hi(v);
    }
}

// ---------------- tensor-core GEMM via mma.sync (fp16, 1-term) ----------------
// C = A @ B^T (+bias).  OUT=0: fp32 C. OUT=1: gelu -> fp16. OUT=2: fp16 (no gelu).
// BK=64, 2-stage cp.async, 64KB smem -> 2 CTAs/SM. Tiles 128x64 = 16 KB.
#define BK 64
#define STAGE_B 32768
#define MG_SMEM (2 * STAGE_B)   // 64 KB

template<int OUT>
__global__ __launch_bounds__(256, 2) void mma_gemm(
    const u16* __restrict__ A, const u16* __restrict__ B,
    const float* __restrict__ bias,
    float* __restrict__ C, u16* __restrict__ Ch,
    int N, int K)
{
    extern __shared__ char smem_raw[];
    const uint32_t sbase = smem_u32(smem_raw);

    const int tid = threadIdx.x, lane = tid & 31, wid = tid >> 5;
    const int warp_m = wid & 3, warp_n = wid >> 2;
    const int bm = blockIdx.y * 128, bn = blockIdx.x * 128;

    const u16* aP = A + (size_t)bm * K;
    const u16* bP = B + (size_t)bn * K;

    const int nk = K / BK;

    auto load_stage = [&](int t) {
        const uint32_t st = sbase + (uint32_t)(t & 1) * STAGE_B;
        const int k0 = t * BK;
        #pragma unroll
        for (int i = 0; i < 4; ++i) {
            const int idx = i * 256 + tid;          // 1024 segs per 16KB tile
            const int row = idx >> 3, seg = idx & 7;
            const uint32_t soff = swz((uint32_t)(row * 128 + seg * 16));
            const size_t goff = (size_t)row * K + k0 + seg * 8;
            cp16(st + soff,         aP + goff);
            cp16(st + 16384 + soff, bP + goff);
        }
        CP_COMMIT();
    };

    float acc[2][8][4];
    #pragma unroll
    for (int mi = 0; mi < 2; ++mi)
        #pragma unroll
        for (int ni = 0; ni < 8; ++ni)
            #pragma unroll
            for (int j = 0; j < 4; ++j) acc[mi][ni][j] = 0.f;

    load_stage(0);

    const int lrow = lane & 15;
    const int kblk = lane >> 4;

    for (int t = 0; t < nk; ++t) {
        if (t + 1 < nk) {
            load_stage(t + 1);
            CP_WAIT(1);
        } else {
            CP_WAIT(0);
        }
        __syncthreads();

        const uint32_t st = sbase + (uint32_t)(t & 1) * STAGE_B;

        #pragma unroll
        for (int s = 0; s < BK / 16; ++s) {
            const int c16 = s * 2 + kblk;
            u32 aa[2][4];
            #pragma unroll
            for (int mi = 0; mi < 2; ++mi) {
                const uint32_t off = swz((uint32_t)((warp_m * 32 + mi * 16 + lrow) * 128 + c16 * 16));
                ldsm4(aa[mi], st + off);
            }
            u32 bb[8][2];
            #pragma unroll
            for (int nb = 0; nb < 4; ++nb) {
                const uint32_t off = swz((uint32_t)((warp_n * 64 + nb * 16 + lrow) * 128 + c16 * 16));
                u32 r[4];
                ldsm4(r, st + 16384 + off);
                bb[nb * 2][0] = r[0]; bb[nb * 2 + 1][0] = r[1];
                bb[nb * 2][1] = r[2]; bb[nb * 2 + 1][1] = r[3];
            }
            #pragma unroll
            for (int mi = 0; mi < 2; ++mi)
                #pragma unroll
                for (int ni = 0; ni < 8; ++ni)
                    mma_fp16(acc[mi][ni], aa[mi], bb[ni]);
        }
        __syncthreads();
    }

    #pragma unroll
    for (int ni = 0; ni < 8; ++ni) {
        const int col = bn + warp_n * 64 + ni * 8 + (lane & 3) * 2;
        const float b0 = bias[col], b1 = bias[col + 1];
        #pragma unroll
        for (int mi = 0; mi < 2; ++mi) {
            const int r0 = bm + warp_m * 32 + mi * 16 + (lane >> 2);
            #pragma unroll
            for (int half = 0; half < 2; ++half) {
                const int r = r0 + half * 8;
                float v0 = acc[mi][ni][half * 2 + 0] + b0;
                float v1 = acc[mi][ni][half * 2 + 1] + b1;
                if (OUT == 0) {
                    *(float2*)(C + (size_t)r * N + col) = make_float2(v0, v1);
                } else {
                    if (OUT == 1) {
                        v0 *= normcdff(v0);
                        v1 *= normcdff(v1);
                    }
                    u16 h0 = fp_hi(v0), h1 = fp_hi(v1);
                    *(u32*)(Ch + (size_t)r * N + col) = (u32)h0 | ((u32)h1 << 16);
                }
            }
        }
    }
}

// ---------------- tensor-core flash attention (causal, fp16 1-term), qkv split K|Q|V ----------------
// S = Q K^T ; O = P V. 256 threads, 128 queries/CTA, heavy-first.
// smem: Q(16K) | 2 x { K(8K) V(8K) }  = 48 KB
#define ATT_STAGE 16384
#define ATT_SMEM (16384 + 2 * ATT_STAGE)   // 48 KB

__global__ __launch_bounds__(256, 2) void attn_mma(
    const u16* __restrict__ qkvh, u16* __restrict__ yh)
{
    extern __shared__ char smem_raw[];
    const uint32_t sb = smem_u32(smem_raw);
    const int tid = threadIdx.x, lane = tid & 31, wid = tid >> 5;
    const int qt = gridDim.x - 1 - blockIdx.x;   // heavy tiles first
    const int h = blockIdx.y, b = blockIdx.z;
    const int q0 = qt * 128;
    const int gid = lane >> 2, qp = lane & 3;
    const size_t tokbase = (size_t)b * SEQ;
    const int rs = 3 * CDIM;

    // Q load (128 rows)
    #pragma unroll
    for (int i = 0; i < 4; ++i) {
        const int idx = i * 256 + tid;
        const int row = idx >> 3, seg = idx & 7;
        const uint32_t off = swz((uint32_t)(row * 128 + seg * 16));
        const size_t g = (tokbase + q0 + row) * rs + CDIM + h * HDIM + seg * 8;
        cp16(sb + off, qkvh + g);
    }

    auto load_stage = [&](int t) {
        const uint32_t st = sb + 16384 + (uint32_t)(t & 1) * ATT_STAGE;
        const int k0 = t * 64;
        #pragma unroll
        for (int i = 0; i < 2; ++i) {
            const int idx = i * 256 + tid;
            const int row = idx >> 3, seg = idx & 7;
            const uint32_t off = swz((uint32_t)(row * 128 + seg * 16));
            const size_t gk = (tokbase + k0 + row) * rs + h * HDIM + seg * 8;
            cp16(st + off,        qkvh + gk);            // K at ch 0
            cp16(st + 8192 + off, qkvh + gk + 2 * CDIM); // V at ch 2C
        }
        CP_COMMIT();
    };

    const int ntiles = 2 * qt + 2;
    load_stage(0);

    float m0 = -INFINITY, m1 = -INFINITY, l0 = 0.f, l1 = 0.f;
    float oacc[8][4];
    #pragma unroll
    for (int ni = 0; ni < 8; ++ni)
        #pragma unroll
        for (int j = 0; j < 4; ++j) oacc[ni][j] = 0.f;

    const int lr = lane & 15, ck = lane >> 4;
    const int wrow0 = q0 + wid * 16;

    for (int t = 0; t < ntiles; ++t) {
        if (t + 1 < ntiles) {
            load_stage(t + 1);
            CP_WAIT(1);
        } else {
            CP_WAIT(0);
        }
        __syncthreads();
        const uint32_t st = sb + 16384 + (uint32_t)(t & 1) * ATT_STAGE;
        const int k0 = t * 64;
        const bool active = (k0 <= wrow0 + 15);

        if (active) {
            float sacc[8][4];
            #pragma unroll
            for (int ni = 0; ni < 8; ++ni)
                #pragma unroll
                for (int j = 0; j < 4; ++j) sacc[ni][j] = 0.f;

            #pragma unroll
            for (int s = 0; s < 4; ++s) {
                const int c16 = s * 2 + ck;
                u32 aQ[4];
                {
                    const uint32_t off = swz((uint32_t)((wid * 16 + lr) * 128 + c16 * 16));
                    ldsm4(aQ, sb + off);
                }
                u32 bK[8][2];
                #pragma unroll
                for (int ng = 0; ng < 4; ++ng) {
                    const uint32_t off = swz((uint32_t)((ng * 16 + lr) * 128 + c16 * 16));
                    u32 r[4];
                    ldsm4(r, st + off);
                    bK[2 * ng][0] = r[0]; bK[2 * ng + 1][0] = r[1];
                    bK[2 * ng][1] = r[2]; bK[2 * ng + 1][1] = r[3];
                }
                #pragma unroll
                for (int ni = 0; ni < 8; ++ni)
                    mma_fp16(sacc[ni], aQ, bK[ni]);
            }
            #pragma unroll
            for (int ni = 0; ni < 8; ++ni)
                #pragma unroll
                for (int j = 0; j < 4; ++j) sacc[ni][j] *= 0.125f;

            if (k0 + 63 > wrow0) {
                #pragma unroll
                for (int ni = 0; ni < 8; ++ni) {
                    const int kbase = k0 + ni * 8 + qp * 2;
                    #pragma unroll
                    for (int j = 0; j < 4; ++j) {
                        if (kbase + (j & 1) > wrow0 + gid + (j >> 1) * 8) sacc[ni][j] = -INFINITY;
                    }
                }
            }

            float mt0 = -INFINITY, mt1 = -INFINITY;
            #pragma unroll
            for (int ni = 0; ni < 8; ++ni) {
                mt0 = fmaxf(mt0, fmaxf(sacc[ni][0], sacc[ni][1]));
                mt1 = fmaxf(mt1, fmaxf(sacc[ni][2], sacc[ni][3]));
            }
            mt0 = fmaxf(mt0, __shfl_xor_sync(0xffffffffu, mt0, 1));
            mt0 = fmaxf(mt0, __shfl_xor_sync(0xffffffffu, mt0, 2));
            mt1 = fmaxf(mt1, __shfl_xor_sync(0xffffffffu, mt1, 1));
            mt1 = fmaxf(mt1, __shfl_xor_sync(0xffffffffu, mt1, 2));
            const float mn0 = fmaxf(m0, mt0), mn1 = fmaxf(m1, mt1);
            const float sc0 = __expf(m0 - mn0), sc1 = __expf(m1 - mn1);
            m0 = mn0; m1 = mn1;
            float ls0 = 0.f, ls1 = 0.f;
            #pragma unroll
            for (int ni = 0; ni < 8; ++ni) {
                sacc[ni][0] = __expf(sacc[ni][0] - mn0);
                sacc[ni][1] = __expf(sacc[ni][1] - mn0);
                sacc[ni][2] = __expf(sacc[ni][2] - mn1);
                sacc[ni][3] = __expf(sacc[ni][3] - mn1);
                ls0 += sacc[ni][0] + sacc[ni][1];
                ls1 += sacc[ni][2] + sacc[ni][3];
            }
            ls0 += __shfl_xor_sync(0xffffffffu, ls0, 1);
            ls0 += __shfl_xor_sync(0xffffffffu, ls0, 2);
            ls1 += __shfl_xor_sync(0xffffffffu, ls1, 1);
            ls1 += __shfl_xor_sync(0xffffffffu, ls1, 2);
            l0 = l0 * sc0 + ls0;
            l1 = l1 * sc1 + ls1;
            #pragma unroll
            for (int ni = 0; ni < 8; ++ni) {
                oacc[ni][0] *= sc0; oacc[ni][1] *= sc0;
                oacc[ni][2] *= sc1; oacc[ni][3] *= sc1;
            }

            // pack P (fp16)
            u32 aP[4][4];
            #pragma unroll
            for (int s = 0; s < 4; ++s) {
                #pragma unroll
                for (int half = 0; half < 2; ++half) {
                    const float p0 = sacc[2 * s + half][0], p1 = sacc[2 * s + half][1];
                    const float p2 = sacc[2 * s + half][2], p3 = sacc[2 * s + half][3];
                    const u16 h0 = fp_hi(p0), h1 = fp_hi(p1), h2 = fp_hi(p2), h3 = fp_hi(p3);
                    aP[s][half * 2 + 0] = (u32)h0 | ((u32)h1 << 16);
                    aP[s][half * 2 + 1] = (u32)h2 | ((u32)h3 << 16);
                }
            }

            // O += P V
            #pragma unroll
            for (int s = 0; s < 4; ++s) {
                u32 bV[8][2];
                #pragma unroll
                for (int nd = 0; nd < 4; ++nd) {
                    const uint32_t off = swz((uint32_t)((s * 16 + lr) * 128 + nd * 32 + ck * 16));
                    u32 r[4];
                    ldsm4t(r, st + 8192 + off);
                    bV[2 * nd][0] = r[0]; bV[2 * nd][1] = r[1];
                    bV[2 * nd + 1][0] = r[2]; bV[2 * nd + 1][1] = r[3];
                }
                #pragma unroll
                for (int ni = 0; ni < 8; ++ni)
                    mma_fp16(oacc[ni], aP[s], bV[ni]);
            }
        }
        __syncthreads();
    }

    const float rl0 = 1.f / l0, rl1 = 1.f / l1;
    const int r0 = wrow0 + gid, r1 = r0 + 8;
    #pragma unroll
    for (int ni = 0; ni < 8; ++ni) {
        const int col = h * HDIM + ni * 8 + qp * 2;
        {
            const float v0 = oacc[ni][0] * rl0, v1 = oacc[ni][1] * rl0;
            const u16 h0 = fp_hi(v0), h1 = fp_hi(v1);
            *(u32*)(yh + (tokbase + r0) * CDIM + col) = (u32)h0 | ((u32)h1 << 16);
        }
        {
            const float v0 = oacc[ni][2] * rl1, v1 = oacc[ni][3] * rl1;
            const u16 h0 = fp_hi(v0), h1 = fp_hi(v1);
            *(u32*)(yh + (tokbase + r1) * CDIM + col) = (u32)h0 | ((u32)h1 << 16);
        }
    }
}

// ---------------- residual + LayerNorm ----------------
__device__ __forceinline__ float block_sum256(float v, float* red) {
    const int lane = threadIdx.x & 31;
    const int w = threadIdx.x >> 5;
    #pragma unroll
    for (int off = 16; off; off >>= 1) v += __shfl_xor_sync(0xffffffffu, v, off);
    if (lane == 0) red[w] = v;
    __syncthreads();
    float t = (threadIdx.x < 8) ? red[threadIdx.x] : 0.f;
    if (w == 0) {
        t += __shfl_xor_sync(0xffffffffu, t, 4);
        t += __shfl_xor_sync(0xffffffffu, t, 2);
        t += __shfl_xor_sync(0xffffffffu, t, 1);
        if (lane == 0) red[0] = t;
    }
    __syncthreads();
    const float r = red[0];
    __syncthreads();
    return r;
}

template<bool PAIR>
__global__ __launch_bounds__(256) void add_ln_kernel(
    const float* __restrict__ xres, const float* __restrict__ v,
    const float* __restrict__ g, const float* __restrict__ be,
    float* __restrict__ out, u16* __restrict__ oh)
{
    __shared__ float red[8];
    const size_t row = blockIdx.x;
    const int c0 = threadIdx.x * 4;
    const float* vr = v + row * CDIM;

    float vals[4];
    *(float4*)vals = *(const float4*)(vr + c0);
    float s = vals[0] + vals[1] + vals[2] + vals[3];
    const float mean = block_sum256(s, red) * (1.f / CDIM);

    float d2 = 0.f;
    #pragma unroll
    for (int i = 0; i < 4; ++i) {
        const float d = vals[i] - mean;
        d2 = fmaf(d, d, d2);
    }
    const float var = block_sum256(d2, red) * (1.f / CDIM);
    const float rstd = rsqrtf(var + 1e-5f);

    float4 xr = *(const float4*)(xres + row * CDIM + c0);
    float4 gg = *(const float4*)(g + c0);
    float4 bb = *(const float4*)(be + c0);
    float4 res;
    res.x = xr.x + (vals[0] - mean) * rstd * gg.x + bb.x;
    res.y = xr.y + (vals[1] - mean) * rstd * gg.y + bb.y;
    res.z = xr.z + (vals[2] - mean) * rstd * gg.z + bb.z;
    res.w = xr.w + (vals[3] - mean) * rstd * gg.w + bb.w;
    *(float4*)(out + row * CDIM + c0) = res;
    if (PAIR) {
        u16 h0 = fp_hi(res.x), h1 = fp_hi(res.y), h2 = fp_hi(res.z), h3 = fp_hi(res.w);
        *(uint2*)(oh + row * CDIM + c0) =
            make_uint2((u32)h0 | ((u32)h1 << 16), (u32)h2 | ((u32)h3 << 16));
    }
}

// ---------------- launch ----------------
extern "C" void kernel_launch(void* const* d_in, const int* in_sizes, int n_in,
                              void* d_out, int out_size)
{
    const float* x      = (const float*)d_in[0];
    const float* w_attn = (const float*)d_in[1];
    const float* b_attn = (const float*)d_in[2];
    const float* wa1    = (const float*)d_in[3];
    const float* ba1    = (const float*)d_in[4];
    const float* wa2    = (const float*)d_in[5];
    const float* ba2    = (const float*)d_in[6];
    const float* g1     = (const float*)d_in[7];
    const float* be1    = (const float*)d_in[8];
    const float* wf1    = (const float*)d_in[9];
    const float* bf1    = (const float*)d_in[10];
    const float* wf2    = (const float*)d_in[11];
    const float* bf2    = (const float*)d_in[12];
    const float* g2     = (const float*)d_in[13];
    const float* be2    = (const float*)d_in[14];
    float* out = (float*)d_out;

    float *tbuf, *x1;
    u16 *xh, *qkvh, *yh, *x1h, *hh;
    u16 *wa, *w1, *w2, *w3, *w4;
    cudaGetSymbolAddress((void**)&tbuf, g_t);
    cudaGetSymbolAddress((void**)&x1, g_x1);
    cudaGetSymbolAddress((void**)&xh, g_xh);
    cudaGetSymbolAddress((void**)&qkvh, g_qkvh);
    cudaGetSymbolAddress((void**)&yh, g_yh);
    cudaGetSymbolAddress((void**)&x1h, g_x1h);
    cudaGetSymbolAddress((void**)&hh, g_hh);
    cudaGetSymbolAddress((void**)&wa, g_wa);
    cudaGetSymbolAddress((void**)&w1, g_w1);
    cudaGetSymbolAddress((void**)&w2, g_w2);
    cudaGetSymbolAddress((void**)&w3, g_w3);
    cudaGetSymbolAddress((void**)&w4, g_w4);

    cudaFuncSetAttribute(mma_gemm<0>, cudaFuncAttributeMaxDynamicSharedMemorySize, MG_SMEM);
    cudaFuncSetAttribute(mma_gemm<1>, cudaFuncAttributeMaxDynamicSharedMemorySize, MG_SMEM);
    cudaFuncSetAttribute(mma_gemm<2>, cudaFuncAttributeMaxDynamicSharedMemorySize, MG_SMEM);
    cudaFuncSetAttribute(attn_mma, cudaFuncAttributeMaxDynamicSharedMemorySize, ATT_SMEM);

    const dim3 tb(32, 8);
    tdecomp_k<<<dim3(3 * CDIM / 32, CDIM / 32), tb>>>(w_attn, wa, CDIM, 3 * CDIM);  // 0
    conv_k<<<(ROWS * CDIM / 4 + 255) / 256, 256>>>(x, xh, ROWS * CDIM / 4);         // 1
    tdecomp_k<<<dim3(HID / 32, CDIM / 32), tb>>>(wa1, w1, CDIM, HID);               // 2

    // 3) qkv = x @ w_attn + b_attn -> fp16
    mma_gemm<2><<<dim3(3 * CDIM / 128, ROWS / 128), 256, MG_SMEM>>>(
        xh, wa, b_attn, nullptr, qkvh, 3 * CDIM, CDIM);

    tdecomp_k<<<dim3(CDIM / 32, HID / 32), tb>>>(wa2, w2, HID, CDIM);               // 4

    // 5) causal MHA -> y
    attn_mma<<<dim3(SEQ / 128, NHEAD, BATCH), 256, ATT_SMEM>>>(qkvh, yh);

    tdecomp_k<<<dim3(HID / 32, CDIM / 32), tb>>>(wf1, w3, CDIM, HID);               // 6

    // h = gelu(y @ wa1 + ba1)
    mma_gemm<1><<<dim3(HID / 128, ROWS / 128), 256, MG_SMEM>>>(
        yh, w1, ba1, nullptr, hh, HID, CDIM);

    tdecomp_k<<<dim3(CDIM / 32, HID / 32), tb>>>(wf2, w4, HID, CDIM);               // 8

    // t = h @ wa2 + ba2 (fp32)
    mma_gemm<0><<<dim3(CDIM / 128, ROWS / 128), 256, MG_SMEM>>>(
        hh, w2, ba2, tbuf, nullptr, CDIM, HID);

    // x1 = x + LN(t)
    add_ln_kernel<true><<<ROWS, 256>>>(x, tbuf, g1, be1, x1, x1h);

    // h = gelu(x1 @ wf1 + bf1)
    mma_gemm<1><<<dim3(HID / 128, ROWS / 128), 256, MG_SMEM>>>(
        x1h, w3, bf1, nullptr, hh, HID, CDIM);

    // t = h @ wf2 + bf2 (fp32)
    mma_gemm<0><<<dim3(CDIM / 128, ROWS / 128), 256, MG_SMEM>>>(
        hh, w4, bf2, tbuf, nullptr, CDIM, HID);

    // out = x1 + LN(t)
    add_ln_kernel<false><<<ROWS, 256>>>(x1, tbuf, g2, be2, out, nullptr);
}

// round 14
// speedup vs baseline: 2.7412x; 1.0222x over previous
#include <cuda_runtime.h>
#include <cuda_fp16.h>
#include <math.h>
#include <stdint.h>

// Problem constants
#define BATCH 2
#define SEQ   2048
#define CDIM  1024
#define NHEAD 16
#define HDIM  64
#define ROWS  (BATCH * SEQ)          // 4096
#define HID   (4 * CDIM)             // 4096

typedef unsigned short u16;
typedef unsigned int   u32;

// ---------------- scratch (static device globals; no allocation) ----------------
__device__ float g_t  [(size_t)ROWS * CDIM];
__device__ float g_x1 [(size_t)ROWS * CDIM];
__device__ u16 g_xh  [(size_t)ROWS * CDIM];
__device__ u16 g_qkvh[(size_t)ROWS * 3 * CDIM];
__device__ u16 g_yh  [(size_t)ROWS * CDIM];
__device__ u16 g_x1h [(size_t)ROWS * CDIM];
__device__ u16 g_hh  [(size_t)ROWS * HID];
// transposed fp16 weights, layout [N][K]
__device__ u16 g_wa[(size_t)3*CDIM*CDIM];
__device__ u16 g_w1[(size_t)HID*CDIM];
__device__ u16 g_w2[(size_t)CDIM*HID];
__device__ u16 g_w3[(size_t)HID*CDIM];
__device__ u16 g_w4[(size_t)CDIM*HID];

// ---------------- helpers ----------------
__device__ __forceinline__ uint32_t smem_u32(const void* p) {
    uint32_t a;
    asm("{ .reg .u64 t; cvta.to.shared.u64 t, %1; cvt.u32.u64 %0, t; }" : "=r"(a) : "l"(p));
    return a;
}
__device__ __forceinline__ void cp16(uint32_t dst, const void* src) {
    asm volatile("cp.async.cg.shared.global [%0], [%1], 16;" :: "r"(dst), "l"(src) : "memory");
}
#define CP_COMMIT() asm volatile("cp.async.commit_group;" ::: "memory")
#define CP_WAIT(n)  asm volatile("cp.async.wait_group %0;" :: "n"(n) : "memory")

__device__ __forceinline__ void ldsm4(u32* r, u32 addr) {
    asm volatile("ldmatrix.sync.aligned.m8n8.x4.shared.b16 {%0,%1,%2,%3}, [%4];"
        : "=r"(r[0]), "=r"(r[1]), "=r"(r[2]), "=r"(r[3]) : "r"(addr));
}
__device__ __forceinline__ void ldsm4t(u32* r, u32 addr) {
    asm volatile("ldmatrix.sync.aligned.m8n8.x4.trans.shared.b16 {%0,%1,%2,%3}, [%4];"
        : "=r"(r[0]), "=r"(r[1]), "=r"(r[2]), "=r"(r[3]) : "r"(addr));
}
__device__ __forceinline__ void mma_fp16(float* d, const u32* a, const u32* b) {
    asm volatile("mma.sync.aligned.m16n8k16.row.col.f32.f16.f16.f32 "
        "{%0,%1,%2,%3}, {%4,%5,%6,%7}, {%8,%9}, {%0,%1,%2,%3};"
        : "+f"(d[0]), "+f"(d[1]), "+f"(d[2]), "+f"(d[3])
        : "r"(a[0]), "r"(a[1]), "r"(a[2]), "r"(a[3]), "r"(b[0]), "r"(b[1]));
}
__device__ __forceinline__ uint32_t swz(uint32_t off) { return off ^ ((off >> 3) & 0x70); }

__device__ __forceinline__ u16 fp_hi(float v) { return __half_as_ushort(__float2half_rn(v)); }

// ---------------- convert activations: fp32 -> fp16 ----------------
__global__ __launch_bounds__(256) void conv_k(const float* __restrict__ x,
                                              u16* __restrict__ h, int n4) {
    int i = blockIdx.x * 256 + threadIdx.x;
    if (i >= n4) return;
    float4 v = ((const float4*)x)[i];
    u16 h0 = fp_hi(v.x), h1 = fp_hi(v.y), h2 = fp_hi(v.z), h3 = fp_hi(v.w);
    ((uint2*)h)[i] = make_uint2((u32)h0 | ((u32)h1 << 16), (u32)h2 | ((u32)h3 << 16));
}

// ---------------- transpose weights: W[K][N] fp32 -> T[N][K] fp16 ----------------
__global__ __launch_bounds__(256) void tdecomp_k(const float* __restrict__ W,
                                                 u16* __restrict__ Th, int K, int N) {
    __shared__ float t[32][33];
    const int n0 = blockIdx.x * 32, k0 = blockIdx.y * 32;
    const int tx = threadIdx.x, ty = threadIdx.y;  // 32x8
    #pragma unroll
    for (int i = 0; i < 32; i += 8)
        t[ty + i][tx] = W[(size_t)(k0 + ty + i) * N + n0 + tx];
    __syncthreads();
    #pragma unroll
    for (int i = 0; i < 32; i += 8) {
        float v = t[tx][ty + i];
        Th[(size_t)(n0 + ty + i) * K + k0 + tx] = fp_hi(v);
    }
}

// ---------------- tensor-core GEMM via mma.sync (fp16, 1-term) ----------------
// C = A @ B^T (+bias).  OUT=0: fp32 C. OUT=1: gelu -> fp16. OUT=2: fp16 (no gelu).
// BK=64, 2-stage cp.async, 64KB smem -> 2 CTAs/SM. Tiles 128x64 = 16 KB.
#define BK 64
#define STAGE_B 32768
#define MG_SMEM (2 * STAGE_B)   // 64 KB

template<int OUT>
__global__ __launch_bounds__(256, 2) void mma_gemm(
    const u16* __restrict__ A, const u16* __restrict__ B,
    const float* __restrict__ bias,
    float* __restrict__ C, u16* __restrict__ Ch,
    int N, int K)
{
    extern __shared__ char smem_raw[];
    const uint32_t sbase = smem_u32(smem_raw);

    const int tid = threadIdx.x, lane = tid & 31, wid = tid >> 5;
    const int warp_m = wid & 3, warp_n = wid >> 2;
    const int bm = blockIdx.y * 128, bn = blockIdx.x * 128;

    const u16* aP = A + (size_t)bm * K;
    const u16* bP = B + (size_t)bn * K;

    const int nk = K / BK;

    auto load_stage = [&](int t) {
        const uint32_t st = sbase + (uint32_t)(t & 1) * STAGE_B;
        const int k0 = t * BK;
        #pragma unroll
        for (int i = 0; i < 4; ++i) {
            const int idx = i * 256 + tid;          // 1024 segs per 16KB tile
            const int row = idx >> 3, seg = idx & 7;
            const uint32_t soff = swz((uint32_t)(row * 128 + seg * 16));
            const size_t goff = (size_t)row * K + k0 + seg * 8;
            cp16(st + soff,         aP + goff);
            cp16(st + 16384 + soff, bP + goff);
        }
        CP_COMMIT();
    };

    float acc[2][8][4];
    #pragma unroll
    for (int mi = 0; mi < 2; ++mi)
        #pragma unroll
        for (int ni = 0; ni < 8; ++ni)
            #pragma unroll
            for (int j = 0; j < 4; ++j) acc[mi][ni][j] = 0.f;

    load_stage(0);

    const int lrow = lane & 15;
    const int kblk = lane >> 4;

    for (int t = 0; t < nk; ++t) {
        if (t + 1 < nk) {
            load_stage(t + 1);
            CP_WAIT(1);
        } else {
            CP_WAIT(0);
        }
        __syncthreads();

        const uint32_t st = sbase + (uint32_t)(t & 1) * STAGE_B;

        #pragma unroll
        for (int s = 0; s < BK / 16; ++s) {
            const int c16 = s * 2 + kblk;
            u32 aa[2][4];
            #pragma unroll
            for (int mi = 0; mi < 2; ++mi) {
                const uint32_t off = swz((uint32_t)((warp_m * 32 + mi * 16 + lrow) * 128 + c16 * 16));
                ldsm4(aa[mi], st + off);
            }
            u32 bb[8][2];
            #pragma unroll
            for (int nb = 0; nb < 4; ++nb) {
                const uint32_t off = swz((uint32_t)((warp_n * 64 + nb * 16 + lrow) * 128 + c16 * 16));
                u32 r[4];
                ldsm4(r, st + 16384 + off);
                bb[nb * 2][0] = r[0]; bb[nb * 2 + 1][0] = r[1];
                bb[nb * 2][1] = r[2]; bb[nb * 2 + 1][1] = r[3];
            }
            #pragma unroll
            for (int mi = 0; mi < 2; ++mi)
                #pragma unroll
                for (int ni = 0; ni < 8; ++ni)
                    mma_fp16(acc[mi][ni], aa[mi], bb[ni]);
        }
        __syncthreads();
    }

    #pragma unroll
    for (int ni = 0; ni < 8; ++ni) {
        const int col = bn + warp_n * 64 + ni * 8 + (lane & 3) * 2;
        const float b0 = bias[col], b1 = bias[col + 1];
        #pragma unroll
        for (int mi = 0; mi < 2; ++mi) {
            const int r0 = bm + warp_m * 32 + mi * 16 + (lane >> 2);
            #pragma unroll
            for (int half = 0; half < 2; ++half) {
                const int r = r0 + half * 8;
                float v0 = acc[mi][ni][half * 2 + 0] + b0;
                float v1 = acc[mi][ni][half * 2 + 1] + b1;
                if (OUT == 0) {
                    *(float2*)(C + (size_t)r * N + col) = make_float2(v0, v1);
                } else {
                    if (OUT == 1) {
                        v0 *= normcdff(v0);
                        v1 *= normcdff(v1);
                    }
                    u16 h0 = fp_hi(v0), h1 = fp_hi(v1);
                    *(u32*)(Ch + (size_t)r * N + col) = (u32)h0 | ((u32)h1 << 16);
                }
            }
        }
    }
}

// ---------------- tensor-core flash attention (causal, fp16 1-term), qkv split K|Q|V ----------------
// S = Q K^T ; O = P V. 256 threads, 128 queries/CTA, heavy-first.
// smem: Q(16K) | 2 x { K(8K) V(8K) }  = 48 KB
#define ATT_STAGE 16384
#define ATT_SMEM (16384 + 2 * ATT_STAGE)   // 48 KB

__global__ __launch_bounds__(256, 2) void attn_mma(
    const u16* __restrict__ qkvh, u16* __restrict__ yh)
{
    extern __shared__ char smem_raw[];
    const uint32_t sb = smem_u32(smem_raw);
    const int tid = threadIdx.x, lane = tid & 31, wid = tid >> 5;
    const int qt = gridDim.x - 1 - blockIdx.x;   // heavy tiles first
    const int h = blockIdx.y, b = blockIdx.z;
    const int q0 = qt * 128;
    const int gid = lane >> 2, qp = lane & 3;
    const size_t tokbase = (size_t)b * SEQ;
    const int rs = 3 * CDIM;

    // Q load (128 rows)
    #pragma unroll
    for (int i = 0; i < 4; ++i) {
        const int idx = i * 256 + tid;
        const int row = idx >> 3, seg = idx & 7;
        const uint32_t off = swz((uint32_t)(row * 128 + seg * 16));
        const size_t g = (tokbase + q0 + row) * rs + CDIM + h * HDIM + seg * 8;
        cp16(sb + off, qkvh + g);
    }

    auto load_stage = [&](int t) {
        const uint32_t st = sb + 16384 + (uint32_t)(t & 1) * ATT_STAGE;
        const int k0 = t * 64;
        #pragma unroll
        for (int i = 0; i < 2; ++i) {
            const int idx = i * 256 + tid;
            const int row = idx >> 3, seg = idx & 7;
            const uint32_t off = swz((uint32_t)(row * 128 + seg * 16));
            const size_t gk = (tokbase + k0 + row) * rs + h * HDIM + seg * 8;
            cp16(st + off,        qkvh + gk);            // K at ch 0
            cp16(st + 8192 + off, qkvh + gk + 2 * CDIM); // V at ch 2C
        }
        CP_COMMIT();
    };

    const int ntiles = 2 * qt + 2;
    load_stage(0);

    float m0 = -INFINITY, m1 = -INFINITY, l0 = 0.f, l1 = 0.f;
    float oacc[8][4];
    #pragma unroll
    for (int ni = 0; ni < 8; ++ni)
        #pragma unroll
        for (int j = 0; j < 4; ++j) oacc[ni][j] = 0.f;

    const int lr = lane & 15, ck = lane >> 4;
    const int wrow0 = q0 + wid * 16;

    for (int t = 0; t < ntiles; ++t) {
        if (t + 1 < ntiles) {
            load_stage(t + 1);
            CP_WAIT(1);
        } else {
            CP_WAIT(0);
        }
        __syncthreads();
        const uint32_t st = sb + 16384 + (uint32_t)(t & 1) * ATT_STAGE;
        const int k0 = t * 64;
        const bool active = (k0 <= wrow0 + 15);

        if (active) {
            float sacc[8][4];
            #pragma unroll
            for (int ni = 0; ni < 8; ++ni)
                #pragma unroll
                for (int j = 0; j < 4; ++j) sacc[ni][j] = 0.f;

            #pragma unroll
            for (int s = 0; s < 4; ++s) {
                const int c16 = s * 2 + ck;
                u32 aQ[4];
                {
                    const uint32_t off = swz((uint32_t)((wid * 16 + lr) * 128 + c16 * 16));
                    ldsm4(aQ, sb + off);
                }
                u32 bK[8][2];
                #pragma unroll
                for (int ng = 0; ng < 4; ++ng) {
                    const uint32_t off = swz((uint32_t)((ng * 16 + lr) * 128 + c16 * 16));
                    u32 r[4];
                    ldsm4(r, st + off);
                    bK[2 * ng][0] = r[0]; bK[2 * ng + 1][0] = r[1];
                    bK[2 * ng][1] = r[2]; bK[2 * ng + 1][1] = r[3];
                }
                #pragma unroll
                for (int ni = 0; ni < 8; ++ni)
                    mma_fp16(sacc[ni], aQ, bK[ni]);
            }
            #pragma unroll
            for (int ni = 0; ni < 8; ++ni)
                #pragma unroll
                for (int j = 0; j < 4; ++j) sacc[ni][j] *= 0.125f;

            if (k0 + 63 > wrow0) {
                #pragma unroll
                for (int ni = 0; ni < 8; ++ni) {
                    const int kbase = k0 + ni * 8 + qp * 2;
                    #pragma unroll
                    for (int j = 0; j < 4; ++j) {
                        if (kbase + (j & 1) > wrow0 + gid + (j >> 1) * 8) sacc[ni][j] = -INFINITY;
                    }
                }
            }

            float mt0 = -INFINITY, mt1 = -INFINITY;
            #pragma unroll
            for (int ni = 0; ni < 8; ++ni) {
                mt0 = fmaxf(mt0, fmaxf(sacc[ni][0], sacc[ni][1]));
                mt1 = fmaxf(mt1, fmaxf(sacc[ni][2], sacc[ni][3]));
            }
            mt0 = fmaxf(mt0, __shfl_xor_sync(0xffffffffu, mt0, 1));
            mt0 = fmaxf(mt0, __shfl_xor_sync(0xffffffffu, mt0, 2));
            mt1 = fmaxf(mt1, __shfl_xor_sync(0xffffffffu, mt1, 1));
            mt1 = fmaxf(mt1, __shfl_xor_sync(0xffffffffu, mt1, 2));
            const float mn0 = fmaxf(m0, mt0), mn1 = fmaxf(m1, mt1);
            const float sc0 = __expf(m0 - mn0), sc1 = __expf(m1 - mn1);
            m0 = mn0; m1 = mn1;
            float ls0 = 0.f, ls1 = 0.f;
            #pragma unroll
            for (int ni = 0; ni < 8; ++ni) {
                sacc[ni][0] = __expf(sacc[ni][0] - mn0);
                sacc[ni][1] = __expf(sacc[ni][1] - mn0);
                sacc[ni][2] = __expf(sacc[ni][2] - mn1);
                sacc[ni][3] = __expf(sacc[ni][3] - mn1);
                ls0 += sacc[ni][0] + sacc[ni][1];
                ls1 += sacc[ni][2] + sacc[ni][3];
            }
            ls0 += __shfl_xor_sync(0xffffffffu, ls0, 1);
            ls0 += __shfl_xor_sync(0xffffffffu, ls0, 2);
            ls1 += __shfl_xor_sync(0xffffffffu, ls1, 1);
            ls1 += __shfl_xor_sync(0xffffffffu, ls1, 2);
            l0 = l0 * sc0 + ls0;
            l1 = l1 * sc1 + ls1;
            #pragma unroll
            for (int ni = 0; ni < 8; ++ni) {
                oacc[ni][0] *= sc0; oacc[ni][1] *= sc0;
                oacc[ni][2] *= sc1; oacc[ni][3] *= sc1;
            }

            // pack P (fp16)
            u32 aP[4][4];
            #pragma unroll
            for (int s = 0; s < 4; ++s) {
                #pragma unroll
                for (int half = 0; half < 2; ++half) {
                    const float p0 = sacc[2 * s + half][0], p1 = sacc[2 * s + half][1];
                    const float p2 = sacc[2 * s + half][2], p3 = sacc[2 * s + half][3];
                    const u16 h0 = fp_hi(p0), h1 = fp_hi(p1), h2 = fp_hi(p2), h3 = fp_hi(p3);
                    aP[s][half * 2 + 0] = (u32)h0 | ((u32)h1 << 16);
                    aP[s][half * 2 + 1] = (u32)h2 | ((u32)h3 << 16);
                }
            }

            // O += P V
            #pragma unroll
            for (int s = 0; s < 4; ++s) {
                u32 bV[8][2];
                #pragma unroll
                for (int nd = 0; nd < 4; ++nd) {
                    const uint32_t off = swz((uint32_t)((s * 16 + lr) * 128 + nd * 32 + ck * 16));
                    u32 r[4];
                    ldsm4t(r, st + 8192 + off);
                    bV[2 * nd][0] = r[0]; bV[2 * nd][1] = r[1];
                    bV[2 * nd + 1][0] = r[2]; bV[2 * nd + 1][1] = r[3];
                }
                #pragma unroll
                for (int ni = 0; ni < 8; ++ni)
                    mma_fp16(oacc[ni], aP[s], bV[ni]);
            }
        }
        __syncthreads();
    }

    const float rl0 = 1.f / l0, rl1 = 1.f / l1;
    const int r0 = wrow0 + gid, r1 = r0 + 8;
    #pragma unroll
    for (int ni = 0; ni < 8; ++ni) {
        const int col = h * HDIM + ni * 8 + qp * 2;
        {
            const float v0 = oacc[ni][0] * rl0, v1 = oacc[ni][1] * rl0;
            const u16 h0 = fp_hi(v0), h1 = fp_hi(v1);
            *(u32*)(yh + (tokbase + r0) * CDIM + col) = (u32)h0 | ((u32)h1 << 16);
        }
        {
            const float v0 = oacc[ni][2] * rl1, v1 = oacc[ni][3] * rl1;
            const u16 h0 = fp_hi(v0), h1 = fp_hi(v1);
            *(u32*)(yh + (tokbase + r1) * CDIM + col) = (u32)h0 | ((u32)h1 << 16);
        }
    }
}

// ---------------- residual + LayerNorm ----------------
__device__ __forceinline__ float block_sum256(float v, float* red) {
    const int lane = threadIdx.x & 31;
    const int w = threadIdx.x >> 5;
    #pragma unroll
    for (int off = 16; off; off >>= 1) v += __shfl_xor_sync(0xffffffffu, v, off);
    if (lane == 0) red[w] = v;
    __syncthreads();
    float t = (threadIdx.x < 8) ? red[threadIdx.x] : 0.f;
    if (w == 0) {
        t += __shfl_xor_sync(0xffffffffu, t, 4);
        t += __shfl_xor_sync(0xffffffffu, t, 2);
        t += __shfl_xor_sync(0xffffffffu, t, 1);
        if (lane == 0) red[0] = t;
    }
    __syncthreads();
    const float r = red[0];
    __syncthreads();
    return r;
}

template<bool PAIR>
__global__ __launch_bounds__(256) void add_ln_kernel(
    const float* __restrict__ xres, const float* __restrict__ v,
    const float* __restrict__ g, const float* __restrict__ be,
    float* __restrict__ out, u16* __restrict__ oh)
{
    __shared__ float red[8];
    const size_t row = blockIdx.x;
    const int c0 = threadIdx.x * 4;
    const float* vr = v + row * CDIM;

    float vals[4];
    *(float4*)vals = *(const float4*)(vr + c0);
    float s = vals[0] + vals[1] + vals[2] + vals[3];
    const float mean = block_sum256(s, red) * (1.f / CDIM);

    float d2 = 0.f;
    #pragma unroll
    for (int i = 0; i < 4; ++i) {
        const float d = vals[i] - mean;
        d2 = fmaf(d, d, d2);
    }
    const float var = block_sum256(d2, red) * (1.f / CDIM);
    const float rstd = rsqrtf(var + 1e-5f);

    float4 xr = *(const float4*)(xres + row * CDIM + c0);
    float4 gg = *(const float4*)(g + c0);
    float4 bb = *(const float4*)(be + c0);
    float4 res;
    res.x = xr.x + (vals[0] - mean) * rstd * gg.x + bb.x;
    res.y = xr.y + (vals[1] - mean) * rstd * gg.y + bb.y;
    res.z = xr.z + (vals[2] - mean) * rstd * gg.z + bb.z;
    res.w = xr.w + (vals[3] - mean) * rstd * gg.w + bb.w;
    *(float4*)(out + row * CDIM + c0) = res;
    if (PAIR) {
        u16 h0 = fp_hi(res.x), h1 = fp_hi(res.y), h2 = fp_hi(res.z), h3 = fp_hi(res.w);
        *(uint2*)(oh + row * CDIM + c0) =
            make_uint2((u32)h0 | ((u32)h1 << 16), (u32)h2 | ((u32)h3 << 16));
    }
}

// ---------------- launch ----------------
extern "C" void kernel_launch(void* const* d_in, const int* in_sizes, int n_in,
                              void* d_out, int out_size)
{
    const float* x      = (const float*)d_in[0];
    const float* w_attn = (const float*)d_in[1];
    const float* b_attn = (const float*)d_in[2];
    const float* wa1    = (const float*)d_in[3];
    const float* ba1    = (const float*)d_in[4];
    const float* wa2    = (const float*)d_in[5];
    const float* ba2    = (const float*)d_in[6];
    const float* g1     = (const float*)d_in[7];
    const float* be1    = (const float*)d_in[8];
    const float* wf1    = (const float*)d_in[9];
    const float* bf1    = (const float*)d_in[10];
    const float* wf2    = (const float*)d_in[11];
    const float* bf2    = (const float*)d_in[12];
    const float* g2     = (const float*)d_in[13];
    const float* be2    = (const float*)d_in[14];
    float* out = (float*)d_out;

    float *tbuf, *x1;
    u16 *xh, *qkvh, *yh, *x1h, *hh;
    u16 *wa, *w1, *w2, *w3, *w4;
    cudaGetSymbolAddress((void**)&tbuf, g_t);
    cudaGetSymbolAddress((void**)&x1, g_x1);
    cudaGetSymbolAddress((void**)&xh, g_xh);
    cudaGetSymbolAddress((void**)&qkvh, g_qkvh);
    cudaGetSymbolAddress((void**)&yh, g_yh);
    cudaGetSymbolAddress((void**)&x1h, g_x1h);
    cudaGetSymbolAddress((void**)&hh, g_hh);
    cudaGetSymbolAddress((void**)&wa, g_wa);
    cudaGetSymbolAddress((void**)&w1, g_w1);
    cudaGetSymbolAddress((void**)&w2, g_w2);
    cudaGetSymbolAddress((void**)&w3, g_w3);
    cudaGetSymbolAddress((void**)&w4, g_w4);

    cudaFuncSetAttribute(mma_gemm<0>, cudaFuncAttributeMaxDynamicSharedMemorySize, MG_SMEM);
    cudaFuncSetAttribute(mma_gemm<1>, cudaFuncAttributeMaxDynamicSharedMemorySize, MG_SMEM);
    cudaFuncSetAttribute(mma_gemm<2>, cudaFuncAttributeMaxDynamicSharedMemorySize, MG_SMEM);
    cudaFuncSetAttribute(attn_mma, cudaFuncAttributeMaxDynamicSharedMemorySize, ATT_SMEM);

    // fork-join side stream for prep work (graph-capture-safe pattern)
    cudaStream_t s2;
    cudaEvent_t eFork, eConv, eW;
    cudaStreamCreateWithFlags(&s2, cudaStreamNonBlocking);
    cudaEventCreateWithFlags(&eFork, cudaEventDisableTiming);
    cudaEventCreateWithFlags(&eConv, cudaEventDisableTiming);
    cudaEventCreateWithFlags(&eW, cudaEventDisableTiming);

    const dim3 tb(32, 8);

    // fork: side stream joins the capture graph
    cudaEventRecord(eFork, 0);
    cudaStreamWaitEvent(s2, eFork, 0);

    // side stream: x conversion (needed before qkv), then w1..w4 transposes
    conv_k<<<(ROWS * CDIM / 4 + 255) / 256, 256, 0, s2>>>(x, xh, ROWS * CDIM / 4);
    cudaEventRecord(eConv, s2);
    tdecomp_k<<<dim3(HID / 32, CDIM / 32), tb, 0, s2>>>(wa1, w1, CDIM, HID);
    tdecomp_k<<<dim3(CDIM / 32, HID / 32), tb, 0, s2>>>(wa2, w2, HID, CDIM);
    tdecomp_k<<<dim3(HID / 32, CDIM / 32), tb, 0, s2>>>(wf1, w3, CDIM, HID);
    tdecomp_k<<<dim3(CDIM / 32, HID / 32), tb, 0, s2>>>(wf2, w4, HID, CDIM);
    cudaEventRecord(eW, s2);

    // main stream: wa transpose runs concurrent with conv_k
    tdecomp_k<<<dim3(3 * CDIM / 32, CDIM / 32), tb>>>(w_attn, wa, CDIM, 3 * CDIM);
    cudaStreamWaitEvent(0, eConv, 0);   // need xh before qkv

    // qkv = x @ w_attn + b_attn -> fp16  (overlaps w1..w4 transposes on s2)
    mma_gemm<2><<<dim3(3 * CDIM / 128, ROWS / 128), 256, MG_SMEM>>>(
        xh, wa, b_attn, nullptr, qkvh, 3 * CDIM, CDIM);

    // causal MHA -> y  (still overlapping s2)
    attn_mma<<<dim3(SEQ / 128, NHEAD, BATCH), 256, ATT_SMEM>>>(qkvh, yh);

    cudaStreamWaitEvent(0, eW, 0);      // join: weights ready for FF chain

    // h = gelu(y @ wa1 + ba1)
    mma_gemm<1><<<dim3(HID / 128, ROWS / 128), 256, MG_SMEM>>>(
        yh, w1, ba1, nullptr, hh, HID, CDIM);

    // t = h @ wa2 + ba2 (fp32)
    mma_gemm<0><<<dim3(CDIM / 128, ROWS / 128), 256, MG_SMEM>>>(
        hh, w2, ba2, tbuf, nullptr, CDIM, HID);

    // x1 = x + LN(t)
    add_ln_kernel<true><<<ROWS, 256>>>(x, tbuf, g1, be1, x1, x1h);

    // h = gelu(x1 @ wf1 + bf1)
    mma_gemm<1><<<dim3(HID / 128, ROWS / 128), 256, MG_SMEM>>>(
        x1h, w3, bf1, nullptr, hh, HID, CDIM);

    // t = h @ wf2 + bf2 (fp32)
    mma_gemm<0><<<dim3(CDIM / 128, ROWS / 128), 256, MG_SMEM>>>(
        hh, w4, bf2, tbuf, nullptr, CDIM, HID);

    // out = x1 + LN(t)
    add_ln_kernel<false><<<ROWS, 256>>>(x1, tbuf, g2, be2, out, nullptr);

    cudaStreamDestroy(s2);
    cudaEventDestroy(eFork);
    cudaEventDestroy(eConv);
    cudaEventDestroy(eW);
}

// round 15
// speedup vs baseline: 2.7658x; 1.0090x over previous
#include <cuda_runtime.h>
#include <cuda_fp16.h>
#include <math.h>
#include <stdint.h>

// Problem constants
#define BATCH 2
#define SEQ   2048
#define CDIM  1024
#define NHEAD 16
#define HDIM  64
#define ROWS  (BATCH * SEQ)          // 4096
#define HID   (4 * CDIM)             // 4096

typedef unsigned short u16;
typedef unsigned int   u32;

// ---------------- scratch (static device globals; no allocation) ----------------
__device__ float g_t  [(size_t)ROWS * CDIM];
__device__ float g_x1 [(size_t)ROWS * CDIM];
__device__ u16 g_xh  [(size_t)ROWS * CDIM];
__device__ u16 g_qkvh[(size_t)ROWS * 3 * CDIM];
__device__ u16 g_yh  [(size_t)ROWS * CDIM];
__device__ u16 g_x1h [(size_t)ROWS * CDIM];
__device__ u16 g_hh  [(size_t)ROWS * HID];
// transposed fp16 weights, layout [N][K]
__device__ u16 g_wa[(size_t)3*CDIM*CDIM];
__device__ u16 g_w1[(size_t)HID*CDIM];
__device__ u16 g_w2[(size_t)CDIM*HID];
__device__ u16 g_w3[(size_t)HID*CDIM];
__device__ u16 g_w4[(size_t)CDIM*HID];

// ---------------- helpers ----------------
__device__ __forceinline__ uint32_t smem_u32(const void* p) {
    uint32_t a;
    asm("{ .reg .u64 t; cvta.to.shared.u64 t, %1; cvt.u32.u64 %0, t; }" : "=r"(a) : "l"(p));
    return a;
}
__device__ __forceinline__ void cp16(uint32_t dst, const void* src) {
    asm volatile("cp.async.cg.shared.global [%0], [%1], 16;" :: "r"(dst), "l"(src) : "memory");
}
#define CP_COMMIT() asm volatile("cp.async.commit_group;" ::: "memory")
#define CP_WAIT(n)  asm volatile("cp.async.wait_group %0;" :: "n"(n) : "memory")

__device__ __forceinline__ void ldsm4(u32* r, u32 addr) {
    asm volatile("ldmatrix.sync.aligned.m8n8.x4.shared.b16 {%0,%1,%2,%3}, [%4];"
        : "=r"(r[0]), "=r"(r[1]), "=r"(r[2]), "=r"(r[3]) : "r"(addr));
}
__device__ __forceinline__ void ldsm4t(u32* r, u32 addr) {
    asm volatile("ldmatrix.sync.aligned.m8n8.x4.trans.shared.b16 {%0,%1,%2,%3}, [%4];"
        : "=r"(r[0]), "=r"(r[1]), "=r"(r[2]), "=r"(r[3]) : "r"(addr));
}
__device__ __forceinline__ void mma_fp16(float* d, const u32* a, const u32* b) {
    asm volatile("mma.sync.aligned.m16n8k16.row.col.f32.f16.f16.f32 "
        "{%0,%1,%2,%3}, {%4,%5,%6,%7}, {%8,%9}, {%0,%1,%2,%3};"
        : "+f"(d[0]), "+f"(d[1]), "+f"(d[2]), "+f"(d[3])
        : "r"(a[0]), "r"(a[1]), "r"(a[2]), "r"(a[3]), "r"(b[0]), "r"(b[1]));
}
__device__ __forceinline__ uint32_t swz(uint32_t off) { return off ^ ((off >> 3) & 0x70); }

__device__ __forceinline__ u16 fp_hi(float v) { return __half_as_ushort(__float2half_rn(v)); }

// ---------------- convert activations: fp32 -> fp16 ----------------
__global__ __launch_bounds__(256) void conv_k(const float* __restrict__ x,
                                              u16* __restrict__ h, int n4) {
    int i = blockIdx.x * 256 + threadIdx.x;
    if (i >= n4) return;
    float4 v = ((const float4*)x)[i];
    u16 h0 = fp_hi(v.x), h1 = fp_hi(v.y), h2 = fp_hi(v.z), h3 = fp_hi(v.w);
    ((uint2*)h)[i] = make_uint2((u32)h0 | ((u32)h1 << 16), (u32)h2 | ((u32)h3 << 16));
}

// ---------------- transpose weights: W[K][N] fp32 -> T[N][K] fp16 ----------------
__global__ __launch_bounds__(256) void tdecomp_k(const float* __restrict__ W,
                                                 u16* __restrict__ Th, int K, int N) {
    __shared__ float t[32][33];
    const int n0 = blockIdx.x * 32, k0 = blockIdx.y * 32;
    const int tx = threadIdx.x, ty = threadIdx.y;  // 32x8
    #pragma unroll
    for (int i = 0; i < 32; i += 8)
        t[ty + i][tx] = W[(size_t)(k0 + ty + i) * N + n0 + tx];
    __syncthreads();
    #pragma unroll
    for (int i = 0; i < 32; i += 8) {
        float v = t[tx][ty + i];
        Th[(size_t)(n0 + ty + i) * K + k0 + tx] = fp_hi(v);
    }
}

// ---------------- tensor-core GEMM via mma.sync (fp16, 1-term) ----------------
// C = A @ B^T (+bias).  OUT=0: fp32 C. OUT=1: gelu -> fp16. OUT=2: fp16 (no gelu).
// BK=64, 2-stage cp.async, 64KB smem. B frags loaded in two halves to cut regs
// below the 2-CTA residency boundary (target <= ~112 regs/thread).
#define BK 64
#define STAGE_B 32768
#define MG_SMEM (2 * STAGE_B)   // 64 KB

template<int OUT>
__global__ __launch_bounds__(256, 2) void mma_gemm(
    const u16* __restrict__ A, const u16* __restrict__ B,
    const float* __restrict__ bias,
    float* __restrict__ C, u16* __restrict__ Ch,
    int N, int K)
{
    extern __shared__ char smem_raw[];
    const uint32_t sbase = smem_u32(smem_raw);

    const int tid = threadIdx.x, lane = tid & 31, wid = tid >> 5;
    const int warp_m = wid & 3, warp_n = wid >> 2;
    const int bm = blockIdx.y * 128, bn = blockIdx.x * 128;

    const u16* aP = A + (size_t)bm * K;
    const u16* bP = B + (size_t)bn * K;

    const int nk = K / BK;

    auto load_stage = [&](int t) {
        const uint32_t st = sbase + (uint32_t)(t & 1) * STAGE_B;
        const int k0 = t * BK;
        #pragma unroll
        for (int i = 0; i < 4; ++i) {
            const int idx = i * 256 + tid;          // 1024 segs per 16KB tile
            const int row = idx >> 3, seg = idx & 7;
            const uint32_t soff = swz((uint32_t)(row * 128 + seg * 16));
            const size_t goff = (size_t)row * K + k0 + seg * 8;
            cp16(st + soff,         aP + goff);
            cp16(st + 16384 + soff, bP + goff);
        }
        CP_COMMIT();
    };

    float acc[2][8][4];
    #pragma unroll
    for (int mi = 0; mi < 2; ++mi)
        #pragma unroll
        for (int ni = 0; ni < 8; ++ni)
            #pragma unroll
            for (int j = 0; j < 4; ++j) acc[mi][ni][j] = 0.f;

    load_stage(0);

    const int lrow = lane & 15;
    const int kblk = lane >> 4;

    for (int t = 0; t < nk; ++t) {
        if (t + 1 < nk) {
            load_stage(t + 1);
            CP_WAIT(1);
        } else {
            CP_WAIT(0);
        }
        __syncthreads();

        const uint32_t st = sbase + (uint32_t)(t & 1) * STAGE_B;

        #pragma unroll
        for (int s = 0; s < BK / 16; ++s) {
            const int c16 = s * 2 + kblk;
            u32 aa[2][4];
            #pragma unroll
            for (int mi = 0; mi < 2; ++mi) {
                const uint32_t off = swz((uint32_t)((warp_m * 32 + mi * 16 + lrow) * 128 + c16 * 16));
                ldsm4(aa[mi], st + off);
            }
            // B in two halves of 4 n-frags each (register lifetime cut)
            #pragma unroll
            for (int half = 0; half < 2; ++half) {
                u32 bb[4][2];
                #pragma unroll
                for (int nb = 0; nb < 2; ++nb) {
                    const int nrow = warp_n * 64 + (half * 2 + nb) * 16 + lrow;
                    const uint32_t off = swz((uint32_t)(nrow * 128 + c16 * 16));
                    u32 r[4];
                    ldsm4(r, st + 16384 + off);
                    bb[nb * 2][0] = r[0]; bb[nb * 2 + 1][0] = r[1];
                    bb[nb * 2][1] = r[2]; bb[nb * 2 + 1][1] = r[3];
                }
                #pragma unroll
                for (int mi = 0; mi < 2; ++mi)
                    #pragma unroll
                    for (int nj = 0; nj < 4; ++nj)
                        mma_fp16(acc[mi][half * 4 + nj], aa[mi], bb[nj]);
            }
        }
        __syncthreads();
    }

    #pragma unroll
    for (int ni = 0; ni < 8; ++ni) {
        const int col = bn + warp_n * 64 + ni * 8 + (lane & 3) * 2;
        const float b0 = bias[col], b1 = bias[col + 1];
        #pragma unroll
        for (int mi = 0; mi < 2; ++mi) {
            const int r0 = bm + warp_m * 32 + mi * 16 + (lane >> 2);
            #pragma unroll
            for (int half = 0; half < 2; ++half) {
                const int r = r0 + half * 8;
                float v0 = acc[mi][ni][half * 2 + 0] + b0;
                float v1 = acc[mi][ni][half * 2 + 1] + b1;
                if (OUT == 0) {
                    *(float2*)(C + (size_t)r * N + col) = make_float2(v0, v1);
                } else {
                    if (OUT == 1) {
                        v0 *= normcdff(v0);
                        v1 *= normcdff(v1);
                    }
                    u16 h0 = fp_hi(v0), h1 = fp_hi(v1);
                    *(u32*)(Ch + (size_t)r * N + col) = (u32)h0 | ((u32)h1 << 16);
                }
            }
        }
    }
}

// ---------------- tensor-core flash attention (causal, fp16 1-term), qkv split K|Q|V ----------------
// S = Q K^T ; O = P V. 256 threads, 128 queries/CTA, heavy-first.
// smem: Q(16K) | 2 x { K(8K) V(8K) }  = 48 KB
#define ATT_STAGE 16384
#define ATT_SMEM (16384 + 2 * ATT_STAGE)   // 48 KB

__global__ __launch_bounds__(256, 2) void attn_mma(
    const u16* __restrict__ qkvh, u16* __restrict__ yh)
{
    extern __shared__ char smem_raw[];
    const uint32_t sb = smem_u32(smem_raw);
    const int tid = threadIdx.x, lane = tid & 31, wid = tid >> 5;
    const int qt = gridDim.x - 1 - blockIdx.x;   // heavy tiles first
    const int h = blockIdx.y, b = blockIdx.z;
    const int q0 = qt * 128;
    const int gid = lane >> 2, qp = lane & 3;
    const size_t tokbase = (size_t)b * SEQ;
    const int rs = 3 * CDIM;

    // Q load (128 rows)
    #pragma unroll
    for (int i = 0; i < 4; ++i) {
        const int idx = i * 256 + tid;
        const int row = idx >> 3, seg = idx & 7;
        const uint32_t off = swz((uint32_t)(row * 128 + seg * 16));
        const size_t g = (tokbase + q0 + row) * rs + CDIM + h * HDIM + seg * 8;
        cp16(sb + off, qkvh + g);
    }

    auto load_stage = [&](int t) {
        const uint32_t st = sb + 16384 + (uint32_t)(t & 1) * ATT_STAGE;
        const int k0 = t * 64;
        #pragma unroll
        for (int i = 0; i < 2; ++i) {
            const int idx = i * 256 + tid;
            const int row = idx >> 3, seg = idx & 7;
            const uint32_t off = swz((uint32_t)(row * 128 + seg * 16));
            const size_t gk = (tokbase + k0 + row) * rs + h * HDIM + seg * 8;
            cp16(st + off,        qkvh + gk);            // K at ch 0
            cp16(st + 8192 + off, qkvh + gk + 2 * CDIM); // V at ch 2C
        }
        CP_COMMIT();
    };

    const int ntiles = 2 * qt + 2;
    load_stage(0);

    float m0 = -INFINITY, m1 = -INFINITY, l0 = 0.f, l1 = 0.f;
    float oacc[8][4];
    #pragma unroll
    for (int ni = 0; ni < 8; ++ni)
        #pragma unroll
        for (int j = 0; j < 4; ++j) oacc[ni][j] = 0.f;

    const int lr = lane & 15, ck = lane >> 4;
    const int wrow0 = q0 + wid * 16;

    for (int t = 0; t < ntiles; ++t) {
        if (t + 1 < ntiles) {
            load_stage(t + 1);
            CP_WAIT(1);
        } else {
            CP_WAIT(0);
        }
        __syncthreads();
        const uint32_t st = sb + 16384 + (uint32_t)(t & 1) * ATT_STAGE;
        const int k0 = t * 64;
        const bool active = (k0 <= wrow0 + 15);

        if (active) {
            float sacc[8][4];
            #pragma unroll
            for (int ni = 0; ni < 8; ++ni)
                #pragma unroll
                for (int j = 0; j < 4; ++j) sacc[ni][j] = 0.f;

            #pragma unroll
            for (int s = 0; s < 4; ++s) {
                const int c16 = s * 2 + ck;
                u32 aQ[4];
                {
                    const uint32_t off = swz((uint32_t)((wid * 16 + lr) * 128 + c16 * 16));
                    ldsm4(aQ, sb + off);
                }
                u32 bK[8][2];
                #pragma unroll
                for (int ng = 0; ng < 4; ++ng) {
                    const uint32_t off = swz((uint32_t)((ng * 16 + lr) * 128 + c16 * 16));
                    u32 r[4];
                    ldsm4(r, st + off);
                    bK[2 * ng][0] = r[0]; bK[2 * ng + 1][0] = r[1];
                    bK[2 * ng][1] = r[2]; bK[2 * ng + 1][1] = r[3];
                }
                #pragma unroll
                for (int ni = 0; ni < 8; ++ni)
                    mma_fp16(sacc[ni], aQ, bK[ni]);
            }
            #pragma unroll
            for (int ni = 0; ni < 8; ++ni)
                #pragma unroll
                for (int j = 0; j < 4; ++j) sacc[ni][j] *= 0.125f;

            if (k0 + 63 > wrow0) {
                #pragma unroll
                for (int ni = 0; ni < 8; ++ni) {
                    const int kbase = k0 + ni * 8 + qp * 2;
                    #pragma unroll
                    for (int j = 0; j < 4; ++j) {
                        if (kbase + (j & 1) > wrow0 + gid + (j >> 1) * 8) sacc[ni][j] = -INFINITY;
                    }
                }
            }

            float mt0 = -INFINITY, mt1 = -INFINITY;
            #pragma unroll
            for (int ni = 0; ni < 8; ++ni) {
                mt0 = fmaxf(mt0, fmaxf(sacc[ni][0], sacc[ni][1]));
                mt1 = fmaxf(mt1, fmaxf(sacc[ni][2], sacc[ni][3]));
            }
            mt0 = fmaxf(mt0, __shfl_xor_sync(0xffffffffu, mt0, 1));
            mt0 = fmaxf(mt0, __shfl_xor_sync(0xffffffffu, mt0, 2));
            mt1 = fmaxf(mt1, __shfl_xor_sync(0xffffffffu, mt1, 1));
            mt1 = fmaxf(mt1, __shfl_xor_sync(0xffffffffu, mt1, 2));
            const float mn0 = fmaxf(m0, mt0), mn1 = fmaxf(m1, mt1);
            const float sc0 = __expf(m0 - mn0), sc1 = __expf(m1 - mn1);
            m0 = mn0; m1 = mn1;
            float ls0 = 0.f, ls1 = 0.f;
            #pragma unroll
            for (int ni = 0; ni < 8; ++ni) {
                sacc[ni][0] = __expf(sacc[ni][0] - mn0);
                sacc[ni][1] = __expf(sacc[ni][1] - mn0);
                sacc[ni][2] = __expf(sacc[ni][2] - mn1);
                sacc[ni][3] = __expf(sacc[ni][3] - mn1);
                ls0 += sacc[ni][0] + sacc[ni][1];
                ls1 += sacc[ni][2] + sacc[ni][3];
            }
            ls0 += __shfl_xor_sync(0xffffffffu, ls0, 1);
            ls0 += __shfl_xor_sync(0xffffffffu, ls0, 2);
            ls1 += __shfl_xor_sync(0xffffffffu, ls1, 1);
            ls1 += __shfl_xor_sync(0xffffffffu, ls1, 2);
            l0 = l0 * sc0 + ls0;
            l1 = l1 * sc1 + ls1;
            #pragma unroll
            for (int ni = 0; ni < 8; ++ni) {
                oacc[ni][0] *= sc0; oacc[ni][1] *= sc0;
                oacc[ni][2] *= sc1; oacc[ni][3] *= sc1;
            }

            // pack P (fp16)
            u32 aP[4][4];
            #pragma unroll
            for (int s = 0; s < 4; ++s) {
                #pragma unroll
                for (int half = 0; half < 2; ++half) {
                    const float p0 = sacc[2 * s + half][0], p1 = sacc[2 * s + half][1];
                    const float p2 = sacc[2 * s + half][2], p3 = sacc[2 * s + half][3];
                    const u16 h0 = fp_hi(p0), h1 = fp_hi(p1), h2 = fp_hi(p2), h3 = fp_hi(p3);
                    aP[s][half * 2 + 0] = (u32)h0 | ((u32)h1 << 16);
                    aP[s][half * 2 + 1] = (u32)h2 | ((u32)h3 << 16);
                }
            }

            // O += P V
            #pragma unroll
            for (int s = 0; s < 4; ++s) {
                u32 bV[8][2];
                #pragma unroll
                for (int nd = 0; nd < 4; ++nd) {
                    const uint32_t off = swz((uint32_t)((s * 16 + lr) * 128 + nd * 32 + ck * 16));
                    u32 r[4];
                    ldsm4t(r, st + 8192 + off);
                    bV[2 * nd][0] = r[0]; bV[2 * nd][1] = r[1];
                    bV[2 * nd + 1][0] = r[2]; bV[2 * nd + 1][1] = r[3];
                }
                #pragma unroll
                for (int ni = 0; ni < 8; ++ni)
                    mma_fp16(oacc[ni], aP[s], bV[ni]);
            }
        }
        __syncthreads();
    }

    const float rl0 = 1.f / l0, rl1 = 1.f / l1;
    const int r0 = wrow0 + gid, r1 = r0 + 8;
    #pragma unroll
    for (int ni = 0; ni < 8; ++ni) {
        const int col = h * HDIM + ni * 8 + qp * 2;
        {
            const float v0 = oacc[ni][0] * rl0, v1 = oacc[ni][1] * rl0;
            const u16 h0 = fp_hi(v0), h1 = fp_hi(v1);
            *(u32*)(yh + (tokbase + r0) * CDIM + col) = (u32)h0 | ((u32)h1 << 16);
        }
        {
            const float v0 = oacc[ni][2] * rl1, v1 = oacc[ni][3] * rl1;
            const u16 h0 = fp_hi(v0), h1 = fp_hi(v1);
            *(u32*)(yh + (tokbase + r1) * CDIM + col) = (u32)h0 | ((u32)h1 << 16);
        }
    }
}

// ---------------- residual + LayerNorm ----------------
__device__ __forceinline__ float block_sum256(float v, float* red) {
    const int lane = threadIdx.x & 31;
    const int w = threadIdx.x >> 5;
    #pragma unroll
    for (int off = 16; off; off >>= 1) v += __shfl_xor_sync(0xffffffffu, v, off);
    if (lane == 0) red[w] = v;
    __syncthreads();
    float t = (threadIdx.x < 8) ? red[threadIdx.x] : 0.f;
    if (w == 0) {
        t += __shfl_xor_sync(0xffffffffu, t, 4);
        t += __shfl_xor_sync(0xffffffffu, t, 2);
        t += __shfl_xor_sync(0xffffffffu, t, 1);
        if (lane == 0) red[0] = t;
    }
    __syncthreads();
    const float r = red[0];
    __syncthreads();
    return r;
}

template<bool PAIR>
__global__ __launch_bounds__(256) void add_ln_kernel(
    const float* __restrict__ xres, const float* __restrict__ v,
    const float* __restrict__ g, const float* __restrict__ be,
    float* __restrict__ out, u16* __restrict__ oh)
{
    __shared__ float red[8];
    const size_t row = blockIdx.x;
    const int c0 = threadIdx.x * 4;
    const float* vr = v + row * CDIM;

    float vals[4];
    *(float4*)vals = *(const float4*)(vr + c0);
    float s = vals[0] + vals[1] + vals[2] + vals[3];
    const float mean = block_sum256(s, red) * (1.f / CDIM);

    float d2 = 0.f;
    #pragma unroll
    for (int i = 0; i < 4; ++i) {
        const float d = vals[i] - mean;
        d2 = fmaf(d, d, d2);
    }
    const float var = block_sum256(d2, red) * (1.f / CDIM);
    const float rstd = rsqrtf(var + 1e-5f);

    float4 xr = *(const float4*)(xres + row * CDIM + c0);
    float4 gg = *(const float4*)(g + c0);
    float4 bb = *(const float4*)(be + c0);
    float4 res;
    res.x = xr.x + (vals[0] - mean) * rstd * gg.x + bb.x;
    res.y = xr.y + (vals[1] - mean) * rstd * gg.y + bb.y;
    res.z = xr.z + (vals[2] - mean) * rstd * gg.z + bb.z;
    res.w = xr.w + (vals[3] - mean) * rstd * gg.w + bb.w;
    *(float4*)(out + row * CDIM + c0) = res;
    if (PAIR) {
        u16 h0 = fp_hi(res.x), h1 = fp_hi(res.y), h2 = fp_hi(res.z), h3 = fp_hi(res.w);
        *(uint2*)(oh + row * CDIM + c0) =
            make_uint2((u32)h0 | ((u32)h1 << 16), (u32)h2 | ((u32)h3 << 16));
    }
}

// ---------------- launch ----------------
extern "C" void kernel_launch(void* const* d_in, const int* in_sizes, int n_in,
                              void* d_out, int out_size)
{
    const float* x      = (const float*)d_in[0];
    const float* w_attn = (const float*)d_in[1];
    const float* b_attn = (const float*)d_in[2];
    const float* wa1    = (const float*)d_in[3];
    const float* ba1    = (const float*)d_in[4];
    const float* wa2    = (const float*)d_in[5];
    const float* ba2    = (const float*)d_in[6];
    const float* g1     = (const float*)d_in[7];
    const float* be1    = (const float*)d_in[8];
    const float* wf1    = (const float*)d_in[9];
    const float* bf1    = (const float*)d_in[10];
    const float* wf2    = (const float*)d_in[11];
    const float* bf2    = (const float*)d_in[12];
    const float* g2     = (const float*)d_in[13];
    const float* be2    = (const float*)d_in[14];
    float* out = (float*)d_out;

    float *tbuf, *x1;
    u16 *xh, *qkvh, *yh, *x1h, *hh;
    u16 *wa, *w1, *w2, *w3, *w4;
    cudaGetSymbolAddress((void**)&tbuf, g_t);
    cudaGetSymbolAddress((void**)&x1, g_x1);
    cudaGetSymbolAddress((void**)&xh, g_xh);
    cudaGetSymbolAddress((void**)&qkvh, g_qkvh);
    cudaGetSymbolAddress((void**)&yh, g_yh);
    cudaGetSymbolAddress((void**)&x1h, g_x1h);
    cudaGetSymbolAddress((void**)&hh, g_hh);
    cudaGetSymbolAddress((void**)&wa, g_wa);
    cudaGetSymbolAddress((void**)&w1, g_w1);
    cudaGetSymbolAddress((void**)&w2, g_w2);
    cudaGetSymbolAddress((void**)&w3, g_w3);
    cudaGetSymbolAddress((void**)&w4, g_w4);

    cudaFuncSetAttribute(mma_gemm<0>, cudaFuncAttributeMaxDynamicSharedMemorySize, MG_SMEM);
    cudaFuncSetAttribute(mma_gemm<1>, cudaFuncAttributeMaxDynamicSharedMemorySize, MG_SMEM);
    cudaFuncSetAttribute(mma_gemm<2>, cudaFuncAttributeMaxDynamicSharedMemorySize, MG_SMEM);
    cudaFuncSetAttribute(attn_mma, cudaFuncAttributeMaxDynamicSharedMemorySize, ATT_SMEM);

    // fork-join side stream for prep work (graph-capture-safe pattern)
    cudaStream_t s2;
    cudaEvent_t eFork, eConv, eW;
    cudaStreamCreateWithFlags(&s2, cudaStreamNonBlocking);
    cudaEventCreateWithFlags(&eFork, cudaEventDisableTiming);
    cudaEventCreateWithFlags(&eConv, cudaEventDisableTiming);
    cudaEventCreateWithFlags(&eW, cudaEventDisableTiming);

    const dim3 tb(32, 8);

    // fork
    cudaEventRecord(eFork, 0);
    cudaStreamWaitEvent(s2, eFork, 0);

    // side stream: x conversion, then w1..w4 transposes
    conv_k<<<(ROWS * CDIM / 4 + 255) / 256, 256, 0, s2>>>(x, xh, ROWS * CDIM / 4);
    cudaEventRecord(eConv, s2);
    tdecomp_k<<<dim3(HID / 32, CDIM / 32), tb, 0, s2>>>(wa1, w1, CDIM, HID);
    tdecomp_k<<<dim3(CDIM / 32, HID / 32), tb, 0, s2>>>(wa2, w2, HID, CDIM);
    tdecomp_k<<<dim3(HID / 32, CDIM / 32), tb, 0, s2>>>(wf1, w3, CDIM, HID);
    tdecomp_k<<<dim3(CDIM / 32, HID / 32), tb, 0, s2>>>(wf2, w4, HID, CDIM);
    cudaEventRecord(eW, s2);

    // main stream: wa transpose concurrent with conv_k
    tdecomp_k<<<dim3(3 * CDIM / 32, CDIM / 32), tb>>>(w_attn, wa, CDIM, 3 * CDIM);
    cudaStreamWaitEvent(0, eConv, 0);

    // qkv = x @ w_attn + b_attn -> fp16
    mma_gemm<2><<<dim3(3 * CDIM / 128, ROWS / 128), 256, MG_SMEM>>>(
        xh, wa, b_attn, nullptr, qkvh, 3 * CDIM, CDIM);

    // causal MHA -> y
    attn_mma<<<dim3(SEQ / 128, NHEAD, BATCH), 256, ATT_SMEM>>>(qkvh, yh);

    cudaStreamWaitEvent(0, eW, 0);

    // h = gelu(y @ wa1 + ba1)
    mma_gemm<1><<<dim3(HID / 128, ROWS / 128), 256, MG_SMEM>>>(
        yh, w1, ba1, nullptr, hh, HID, CDIM);

    // t = h @ wa2 + ba2 (fp32)
    mma_gemm<0><<<dim3(CDIM / 128, ROWS / 128), 256, MG_SMEM>>>(
        hh, w2, ba2, tbuf, nullptr, CDIM, HID);

    // x1 = x + LN(t)
    add_ln_kernel<true><<<ROWS, 256>>>(x, tbuf, g1, be1, x1, x1h);

    // h = gelu(x1 @ wf1 + bf1)
    mma_gemm<1><<<dim3(HID / 128, ROWS / 128), 256, MG_SMEM>>>(
        x1h, w3, bf1, nullptr, hh, HID, CDIM);

    // t = h @ wf2 + bf2 (fp32)
    mma_gemm<0><<<dim3(CDIM / 128, ROWS / 128), 256, MG_SMEM>>>(
        hh, w4, bf2, tbuf, nullptr, CDIM, HID);

    // out = x1 + LN(t)
    add_ln_kernel<false><<<ROWS, 256>>>(x1, tbuf, g2, be2, out, nullptr);

    cudaStreamDestroy(s2);
    cudaEventDestroy(eFork);
    cudaEventDestroy(eConv);
    cudaEventDestroy(eW);
}